// round 3
// baseline (speedup 1.0000x reference)
#include <cuda_runtime.h>
#include <math.h>

// Problem constants (fixed by the reference)
#define N_NODES  100000
#define N_EDGES  300000
#define D_IN     256
#define HID      1024
#define N_CLS    64

// ---------------------------------------------------------------------------
// Scratch (device globals: allocation-free)
// ---------------------------------------------------------------------------
__device__ float g_buf256[(size_t)N_NODES * D_IN];   // 102.4 MB
__device__ float g_bufA[(size_t)N_NODES * HID];      // 409.6 MB
__device__ float g_bufB[(size_t)N_NODES * HID];      // 409.6 MB
__device__ int   g_edges[2 * N_EDGES];               // normalized int32 indices
__device__ int   g_idx64;                            // 1 if edge_index is int64

// ---------------------------------------------------------------------------
// Edge-index dtype detection + normalization
// If the buffer is int64 (little-endian), every odd 32-bit word is the high
// half of a value < 100000 -> zero. If int32, odd words are random node ids;
// 256 consecutive zeros is impossible.
// ---------------------------------------------------------------------------
__global__ void detect_idx_kernel(const unsigned int* __restrict__ ei) {
    unsigned v = ei[2 * threadIdx.x + 1];
    int any = __syncthreads_or(v != 0u);
    if (threadIdx.x == 0) g_idx64 = any ? 0 : 1;
}

__global__ void convert_idx_kernel(const unsigned int* __restrict__ ei) {
    int i = blockIdx.x * blockDim.x + threadIdx.x;
    if (i < 2 * N_EDGES) {
        g_edges[i] = g_idx64 ? (int)ei[2 * i] : (int)ei[i];
    }
}

// ---------------------------------------------------------------------------
// float4 copy (buf init: h_agg starts as a copy of the node features)
// ---------------------------------------------------------------------------
__global__ void copy_f4_kernel(const float4* __restrict__ src,
                               float4* __restrict__ dst, long n) {
    long i = (long)blockIdx.x * blockDim.x + threadIdx.x;
    if (i < n) dst[i] = src[i];
}

// ---------------------------------------------------------------------------
// Scatter-add aggregation: buf[dst] += feat[src]   (D4 = D/4 float4 per node)
// ---------------------------------------------------------------------------
template <int D4>
__global__ void scatter_add_kernel(const float4* __restrict__ feat,
                                   float* __restrict__ buf) {
    long idx = (long)blockIdx.x * blockDim.x + threadIdx.x;
    if (idx >= (long)N_EDGES * D4) return;
    int e = (int)(idx / D4);
    int d = (int)(idx % D4);
    int s = g_edges[e];
    int t = g_edges[N_EDGES + e];
    float4 v = feat[(size_t)s * D4 + d];
    float* p = buf + ((size_t)t * D4 + d) * 4;
    atomicAdd(p + 0, v.x);
    atomicAdd(p + 1, v.y);
    atomicAdd(p + 2, v.z);
    atomicAdd(p + 3, v.w);
}

// ---------------------------------------------------------------------------
// Register-tiled SGEMM:  C[M,N] = act(A[M,K] @ B[K,N] + bias[N])
// A row-major, B row-major. N % BN == 0 and K % BK == 0 (true for all calls);
// only M needs edge guards.
// ---------------------------------------------------------------------------
template <int BM, int BN, int BK, int TM, int TN, bool RELU>
__launch_bounds__((BM / TM) * (BN / TN))
__global__ void sgemm_bias_kernel(const float* __restrict__ A,
                                  const float* __restrict__ B,
                                  const float* __restrict__ bias,
                                  float* __restrict__ C,
                                  int M, int N, int K) {
    constexpr int THREADS = (BM / TM) * (BN / TN);
    __shared__ float As[BK][BM];
    __shared__ float Bs[BK][BN];

    const int tid = threadIdx.x;
    const int tx = tid % (BN / TN);
    const int ty = tid / (BN / TN);
    const int rowBase = blockIdx.y * BM;
    const int colBase = blockIdx.x * BN;

    constexpr int A_F4 = BM * BK / 4;   // float4 tiles of A
    constexpr int AKQ  = BK / 4;        // float4 per A row
    constexpr int B_F4 = BK * BN / 4;
    constexpr int BNQ  = BN / 4;

    float acc[TM][TN];
#pragma unroll
    for (int i = 0; i < TM; i++)
#pragma unroll
        for (int j = 0; j < TN; j++) acc[i][j] = 0.0f;

    for (int k0 = 0; k0 < K; k0 += BK) {
        // Load A tile (transpose into As[k][m]); zero-fill rows >= M
#pragma unroll
        for (int i = tid; i < A_F4; i += THREADS) {
            int r  = i / AKQ;
            int kq = i % AKQ;
            int gr = rowBase + r;
            float4 v = make_float4(0.f, 0.f, 0.f, 0.f);
            if (gr < M)
                v = *reinterpret_cast<const float4*>(
                        &A[(size_t)gr * K + k0 + kq * 4]);
            As[kq * 4 + 0][r] = v.x;
            As[kq * 4 + 1][r] = v.y;
            As[kq * 4 + 2][r] = v.z;
            As[kq * 4 + 3][r] = v.w;
        }
        // Load B tile
#pragma unroll
        for (int i = tid; i < B_F4; i += THREADS) {
            int r = i / BNQ;
            int c = i % BNQ;
            float4 v = *reinterpret_cast<const float4*>(
                           &B[(size_t)(k0 + r) * N + colBase + c * 4]);
            *reinterpret_cast<float4*>(&Bs[r][c * 4]) = v;
        }
        __syncthreads();

#pragma unroll
        for (int kk = 0; kk < BK; kk++) {
            float ra[TM], rb[TN];
#pragma unroll
            for (int i = 0; i < TM; i++) ra[i] = As[kk][ty * TM + i];
#pragma unroll
            for (int j = 0; j < TN; j++) rb[j] = Bs[kk][tx * TN + j];
#pragma unroll
            for (int i = 0; i < TM; i++)
#pragma unroll
                for (int j = 0; j < TN; j++)
                    acc[i][j] = fmaf(ra[i], rb[j], acc[i][j]);
        }
        __syncthreads();
    }

    // Epilogue: bias + optional relu, vectorized stores
#pragma unroll
    for (int i = 0; i < TM; i++) {
        int gr = rowBase + ty * TM + i;
        if (gr >= M) continue;
#pragma unroll
        for (int j = 0; j < TN; j += 4) {
            int gc = colBase + tx * TN + j;
            float4 v;
            v.x = acc[i][j + 0] + bias[gc + 0];
            v.y = acc[i][j + 1] + bias[gc + 1];
            v.z = acc[i][j + 2] + bias[gc + 2];
            v.w = acc[i][j + 3] + bias[gc + 3];
            if (RELU) {
                v.x = fmaxf(v.x, 0.f);
                v.y = fmaxf(v.y, 0.f);
                v.z = fmaxf(v.z, 0.f);
                v.w = fmaxf(v.w, 0.f);
            }
            *reinterpret_cast<float4*>(&C[(size_t)gr * N + gc]) = v;
        }
    }
}

// ---------------------------------------------------------------------------
// In-place log_softmax over 64 classes, one warp per row
// ---------------------------------------------------------------------------
__global__ void log_softmax64_kernel(float* __restrict__ out, int M) {
    int warp = (blockIdx.x * blockDim.x + threadIdx.x) >> 5;
    int lane = threadIdx.x & 31;
    if (warp >= M) return;
    float* row = out + (size_t)warp * N_CLS;
    float a = row[lane];
    float b = row[lane + 32];
    float m = fmaxf(a, b);
#pragma unroll
    for (int o = 16; o > 0; o >>= 1)
        m = fmaxf(m, __shfl_xor_sync(0xFFFFFFFFu, m, o));
    float s = expf(a - m) + expf(b - m);
#pragma unroll
    for (int o = 16; o > 0; o >>= 1)
        s += __shfl_xor_sync(0xFFFFFFFFu, s, o);
    float lse = m + logf(s);
    row[lane]      = a - lse;
    row[lane + 32] = b - lse;
}

// ---------------------------------------------------------------------------
// Launch
// ---------------------------------------------------------------------------
extern "C" void kernel_launch(void* const* d_in, const int* in_sizes, int n_in,
                              void* d_out, int out_size) {
    const float*        x   = (const float*)d_in[0];
    const unsigned int* ei  = (const unsigned int*)d_in[1];
    const float* W1a = (const float*)d_in[2];
    const float* b1a = (const float*)d_in[3];
    const float* W1b = (const float*)d_in[4];
    const float* b1b = (const float*)d_in[5];
    const float* W2a = (const float*)d_in[6];
    const float* b2a = (const float*)d_in[7];
    const float* W2b = (const float*)d_in[8];
    const float* b2b = (const float*)d_in[9];
    const float* Wfc = (const float*)d_in[10];
    const float* bfc = (const float*)d_in[11];
    float* out = (float*)d_out;

    float *buf256, *bufA, *bufB;
    cudaGetSymbolAddress((void**)&buf256, g_buf256);
    cudaGetSymbolAddress((void**)&bufA, g_bufA);
    cudaGetSymbolAddress((void**)&bufB, g_bufB);

    // Edge index normalization (handles int32 or int64 storage)
    detect_idx_kernel<<<1, 256>>>(ei);
    convert_idx_kernel<<<(2 * N_EDGES + 255) / 256, 256>>>(ei);

    const int GEMM_THREADS = 256;
    dim3 gridBig(HID / 128, (N_NODES + 127) / 128);
    dim3 gridFC(N_CLS / 64, (N_NODES + 127) / 128);

    // ---- Layer 1: h = x + segsum(x[src] -> dst) ----
    {
        long n4 = (long)N_NODES * (D_IN / 4);
        copy_f4_kernel<<<(int)((n4 + 255) / 256), 256>>>(
            (const float4*)x, (float4*)buf256, n4);
        long work = (long)N_EDGES * (D_IN / 4);
        scatter_add_kernel<D_IN / 4><<<(int)((work + 255) / 256), 256>>>(
            (const float4*)x, buf256);
    }
    // bufA = relu(buf256 @ W1a + b1a)
    sgemm_bias_kernel<128, 128, 16, 8, 8, true><<<gridBig, GEMM_THREADS>>>(
        buf256, W1a, b1a, bufA, N_NODES, HID, D_IN);
    // bufB = relu(bufA @ W1b + b1b)   (fuses GIN output + outer relu) = h1
    sgemm_bias_kernel<128, 128, 16, 8, 8, true><<<gridBig, GEMM_THREADS>>>(
        bufA, W1b, b1b, bufB, N_NODES, HID, HID);

    // ---- Layer 2: bufA = h1 + segsum(h1[src] -> dst) ----
    {
        long n4 = (long)N_NODES * (HID / 4);
        copy_f4_kernel<<<(int)((n4 + 255) / 256), 256>>>(
            (const float4*)bufB, (float4*)bufA, n4);
        long work = (long)N_EDGES * (HID / 4);
        scatter_add_kernel<HID / 4><<<(int)((work + 255) / 256), 256>>>(
            (const float4*)bufB, bufA);
    }
    // bufB = relu(bufA @ W2a + b2a)
    sgemm_bias_kernel<128, 128, 16, 8, 8, true><<<gridBig, GEMM_THREADS>>>(
        bufA, W2a, b2a, bufB, N_NODES, HID, HID);
    // bufA = bufB @ W2b + b2b   (no relu) = h2
    sgemm_bias_kernel<128, 128, 16, 8, 8, false><<<gridBig, GEMM_THREADS>>>(
        bufB, W2b, b2b, bufA, N_NODES, HID, HID);

    // ---- Classifier: out = h2 @ Wfc + bfc, then in-place log_softmax ----
    sgemm_bias_kernel<128, 64, 16, 8, 4, false><<<gridFC, GEMM_THREADS>>>(
        bufA, Wfc, bfc, out, N_NODES, N_CLS, HID);
    log_softmax64_kernel<<<(N_NODES * 32 + 255) / 256, 256>>>(out, N_NODES);
}

// round 6
// speedup vs baseline: 2.4803x; 2.4803x over previous
#include <cuda_runtime.h>
#include <cuda_bf16.h>
#include <math.h>
#include <stdint.h>

// Problem constants (fixed by the reference)
#define N_NODES  100000
#define N_EDGES  300000
#define D_IN     256
#define HID      1024
#define N_CLS    64

// ---------------------------------------------------------------------------
// Scratch (device globals: allocation-free)
// ---------------------------------------------------------------------------
__device__ float g_buf256[(size_t)N_NODES * D_IN];          // 102.4 MB
__device__ float g_bufA[(size_t)N_NODES * HID];             // 409.6 MB
__device__ float g_bufB[(size_t)N_NODES * HID];             // 409.6 MB
__device__ __nv_bfloat16 g_Ah[(size_t)N_NODES * HID];       // split pair 0
__device__ __nv_bfloat16 g_Al[(size_t)N_NODES * HID];
__device__ __nv_bfloat16 g_Ch[(size_t)N_NODES * HID];       // split pair 1
__device__ __nv_bfloat16 g_Cl[(size_t)N_NODES * HID];
__device__ __nv_bfloat16 g_Wh[(size_t)HID * HID];           // weight^T split
__device__ __nv_bfloat16 g_Wl[(size_t)HID * HID];
__device__ int   g_edges[2 * N_EDGES];
__device__ int   g_idx64;

// ---------------------------------------------------------------------------
// PTX helpers (all sm_80-era: valid under compute_103, no 'a' features)
// ---------------------------------------------------------------------------
__device__ __forceinline__ uint32_t s2u(const void* p) {
    uint32_t a;
    asm("{ .reg .u64 t; cvta.to.shared.u64 t, %1; cvt.u32.u64 %0, t; }"
        : "=r"(a) : "l"(p));
    return a;
}

__device__ __forceinline__ void cp_async16(uint32_t s, const void* g, unsigned sz) {
    asm volatile("cp.async.cg.shared.global [%0], [%1], 16, %2;"
                 :: "r"(s), "l"(g), "r"(sz));
}

__device__ __forceinline__ void ldsm4(uint32_t* r, uint32_t addr) {
    asm volatile("ldmatrix.sync.aligned.m8n8.x4.shared.b16 {%0,%1,%2,%3}, [%4];"
                 : "=r"(r[0]), "=r"(r[1]), "=r"(r[2]), "=r"(r[3]) : "r"(addr));
}

__device__ __forceinline__ void mma_bf16(float* d, const uint32_t* a,
                                         const uint32_t* b) {
    asm volatile(
        "mma.sync.aligned.m16n8k16.row.col.f32.bf16.bf16.f32 "
        "{%0,%1,%2,%3},{%4,%5,%6,%7},{%8,%9},{%0,%1,%2,%3};"
        : "+f"(d[0]), "+f"(d[1]), "+f"(d[2]), "+f"(d[3])
        : "r"(a[0]), "r"(a[1]), "r"(a[2]), "r"(a[3]), "r"(b[0]), "r"(b[1]));
}

// ---------------------------------------------------------------------------
// Edge-index dtype detection + normalization
// ---------------------------------------------------------------------------
__global__ void detect_idx_kernel(const unsigned int* __restrict__ ei) {
    unsigned v = ei[2 * threadIdx.x + 1];
    int any = __syncthreads_or(v != 0u);
    if (threadIdx.x == 0) g_idx64 = any ? 0 : 1;
}

__global__ void convert_idx_kernel(const unsigned int* __restrict__ ei) {
    int i = blockIdx.x * blockDim.x + threadIdx.x;
    if (i < 2 * N_EDGES) g_edges[i] = g_idx64 ? (int)ei[2 * i] : (int)ei[i];
}

// ---------------------------------------------------------------------------
// float4 copy
// ---------------------------------------------------------------------------
__global__ void copy_f4_kernel(const float4* __restrict__ src,
                               float4* __restrict__ dst, long n) {
    long i = (long)blockIdx.x * blockDim.x + threadIdx.x;
    if (i < n) dst[i] = src[i];
}

// ---------------------------------------------------------------------------
// Scatter-add aggregation: buf[dst] += feat[src]
// ---------------------------------------------------------------------------
template <int D4>
__global__ void scatter_add_kernel(const float4* __restrict__ feat,
                                   float* __restrict__ buf) {
    long idx = (long)blockIdx.x * blockDim.x + threadIdx.x;
    if (idx >= (long)N_EDGES * D4) return;
    int e = (int)(idx / D4);
    int d = (int)(idx % D4);
    int s = g_edges[e];
    int t = g_edges[N_EDGES + e];
    float4 v = feat[(size_t)s * D4 + d];
    float* p = buf + ((size_t)t * D4 + d) * 4;
    atomicAdd(p + 0, v.x);
    atomicAdd(p + 1, v.y);
    atomicAdd(p + 2, v.z);
    atomicAdd(p + 3, v.w);
}

// ---------------------------------------------------------------------------
// fp32 -> (bf16 hi, bf16 lo) split, element-wise (activations)
// ---------------------------------------------------------------------------
__global__ void split_act_kernel(const float4* __restrict__ X,
                                 __nv_bfloat162* __restrict__ Th,
                                 __nv_bfloat162* __restrict__ Tl, long n4) {
    long i = (long)blockIdx.x * blockDim.x + threadIdx.x;
    if (i >= n4) return;
    float4 v = X[i];
    __nv_bfloat16 h0 = __float2bfloat16(v.x), h1 = __float2bfloat16(v.y);
    __nv_bfloat16 h2 = __float2bfloat16(v.z), h3 = __float2bfloat16(v.w);
    __nv_bfloat16 l0 = __float2bfloat16(v.x - __bfloat162float(h0));
    __nv_bfloat16 l1 = __float2bfloat16(v.y - __bfloat162float(h1));
    __nv_bfloat16 l2 = __float2bfloat16(v.z - __bfloat162float(h2));
    __nv_bfloat16 l3 = __float2bfloat16(v.w - __bfloat162float(h3));
    Th[2 * i]     = __nv_bfloat162(h0, h1);
    Th[2 * i + 1] = __nv_bfloat162(h2, h3);
    Tl[2 * i]     = __nv_bfloat162(l0, l1);
    Tl[2 * i + 1] = __nv_bfloat162(l2, l3);
}

// ---------------------------------------------------------------------------
// Weight W[K,N] fp32  ->  transposed split Wt[N,K] bf16 hi/lo
// ---------------------------------------------------------------------------
__global__ void split_weightT_kernel(const float* __restrict__ W,
                                     __nv_bfloat16* __restrict__ Th,
                                     __nv_bfloat16* __restrict__ Tl,
                                     int Kd, int Nd) {
    int idx = blockIdx.x * blockDim.x + threadIdx.x;
    if (idx >= Kd * Nd) return;
    int n = idx / Kd;
    int k = idx % Kd;
    float v = W[(size_t)k * Nd + n];
    __nv_bfloat16 h = __float2bfloat16(v);
    Th[idx] = h;
    Tl[idx] = __float2bfloat16(v - __bfloat162float(h));
}

// ---------------------------------------------------------------------------
// bf16x3 mma.sync GEMM:  C[M,1024] = act(A[M,K] @ W[K,1024] + bias)
// A: bf16 hi/lo [M,K].  W: transposed bf16 hi/lo [1024,K].
// BM=128, BN=128, BK=64. 256 threads = 2x4 warps (64x32 per warp).
// 3-stage cp.async pipeline; SW128-swizzled SMEM tiles; ldmatrix + HMMA.
// OUT: 0 = fp32 to C; 1 = split bf16 hi/lo to Oh/Ol.
// ---------------------------------------------------------------------------
template <int K>
__device__ __forceinline__ void load_stage(uint32_t tbase, int stage,
    const __nv_bfloat16* __restrict__ Ah, const __nv_bfloat16* __restrict__ Al,
    const __nv_bfloat16* __restrict__ Bh, const __nv_bfloat16* __restrict__ Bl,
    int chunk, int rowBase, int colBase, int M) {
    const int tid = threadIdx.x;
    const uint32_t sBase = tbase + (uint32_t)stage * 65536u;
    const long kOff = (long)chunk * 64;
#pragma unroll
    for (int i = 0; i < 4; ++i) {
        int t = i * 256 + tid;            // 0..1023 16B chunks per 16KB tile
        int r = t >> 3;
        int cc = t & 7;
        uint32_t sw = (uint32_t)(r * 128 + ((cc ^ (r & 7)) << 4));
        // A tiles (row guard -> zero fill)
        int gr = rowBase + r;
        unsigned sz = (gr < M) ? 16u : 0u;
        int ga = gr < M ? gr : (M - 1);
        size_t aoff = ((size_t)ga * K + kOff + cc * 8) * 2;  // bytes
        cp_async16(sBase + sw,          (const char*)Ah + aoff, sz);
        cp_async16(sBase + 16384u + sw, (const char*)Al + aoff, sz);
        // B tiles (always full; N=1024 divisible)
        int gn = colBase + r;
        size_t boff = ((size_t)gn * K + kOff + cc * 8) * 2;
        cp_async16(sBase + 32768u + sw, (const char*)Bh + boff, 16u);
        cp_async16(sBase + 49152u + sw, (const char*)Bl + boff, 16u);
    }
}

__device__ __forceinline__ void compute_chunk(uint32_t st, int wm, int wn,
                                              int lane, float acc[4][4][4]) {
    const uint32_t aHi = st, aLo = st + 16384u;
    const uint32_t bHi = st + 32768u, bLo = st + 49152u;
    const int midx = lane >> 3;
    const int l7 = lane & 7;
    const int a_row = ((midx & 1) << 3) + l7;   // within 16-row frag
    const int a_ck  = (midx >> 1);              // 16B-chunk offset (k)
    const int b_row = ((midx >> 1) << 3) + l7;
    const int b_ck  = (midx & 1);
#pragma unroll
    for (int k = 0; k < 4; ++k) {
        uint32_t ah[4][4], al[4][4], bh[2][4], bl[2][4];
#pragma unroll
        for (int fm = 0; fm < 4; ++fm) {
            int row = wm * 64 + fm * 16 + a_row;
            int ck  = k * 2 + a_ck;
            uint32_t off = (uint32_t)(row * 128 + ((ck ^ (row & 7)) << 4));
            ldsm4(ah[fm], aHi + off);
            ldsm4(al[fm], aLo + off);
        }
#pragma unroll
        for (int f2 = 0; f2 < 2; ++f2) {
            int row = wn * 32 + f2 * 16 + b_row;
            int ck  = k * 2 + b_ck;
            uint32_t off = (uint32_t)(row * 128 + ((ck ^ (row & 7)) << 4));
            ldsm4(bh[f2], bHi + off);
            ldsm4(bl[f2], bLo + off);
        }
#pragma unroll
        for (int fm = 0; fm < 4; ++fm)
#pragma unroll
            for (int fn = 0; fn < 4; ++fn) {
                const uint32_t* pbh = &bh[fn >> 1][(fn & 1) * 2];
                const uint32_t* pbl = &bl[fn >> 1][(fn & 1) * 2];
                mma_bf16(acc[fm][fn], ah[fm], pbh);  // Ah*Bh
                mma_bf16(acc[fm][fn], ah[fm], pbl);  // Ah*Bl
                mma_bf16(acc[fm][fn], al[fm], pbh);  // Al*Bh
            }
    }
}

template <int K, bool RELU, int OUT>
__global__ void __launch_bounds__(256)
gemm_bf16x3_mma_kernel(const __nv_bfloat16* __restrict__ Ah,
                       const __nv_bfloat16* __restrict__ Al,
                       const __nv_bfloat16* __restrict__ Bh,
                       const __nv_bfloat16* __restrict__ Bl,
                       const float* __restrict__ bias,
                       float* __restrict__ C,
                       __nv_bfloat162* __restrict__ Oh,
                       __nv_bfloat162* __restrict__ Ol, int M) {
    constexpr int NC = K / 64;
    extern __shared__ char smem[];
    const uint32_t tile_base = (s2u(smem) + 1023u) & ~1023u;

    const int tid = threadIdx.x;
    const int wid = tid >> 5;
    const int lane = tid & 31;
    const int wm = wid >> 2;          // 0..1
    const int wn = wid & 3;           // 0..3
    const int rowBase = blockIdx.y * 128;
    const int colBase = blockIdx.x * 128;

    float acc[4][4][4];
#pragma unroll
    for (int i = 0; i < 4; i++)
#pragma unroll
        for (int j = 0; j < 4; j++)
#pragma unroll
            for (int q = 0; q < 4; q++) acc[i][j][q] = 0.0f;

    // Prologue: prefetch chunks 0, 1
    load_stage<K>(tile_base, 0, Ah, Al, Bh, Bl, 0, rowBase, colBase, M);
    asm volatile("cp.async.commit_group;" ::: "memory");
    load_stage<K>(tile_base, 1, Ah, Al, Bh, Bl, 1, rowBase, colBase, M);
    asm volatile("cp.async.commit_group;" ::: "memory");

    for (int c = 0; c < NC; ++c) {
        if (c + 1 < NC) asm volatile("cp.async.wait_group 1;" ::: "memory");
        else            asm volatile("cp.async.wait_group 0;" ::: "memory");
        __syncthreads();
        if (c + 2 < NC) {
            load_stage<K>(tile_base, (c + 2) % 3, Ah, Al, Bh, Bl,
                          c + 2, rowBase, colBase, M);
            asm volatile("cp.async.commit_group;" ::: "memory");
        }
        compute_chunk(tile_base + (uint32_t)(c % 3) * 65536u, wm, wn, lane, acc);
    }

    // Epilogue: bias (+relu), fp32 or split-bf16 output
    const int rowb = rowBase + wm * 64 + (lane >> 2);
    const int colb = colBase + wn * 32;
#pragma unroll
    for (int fm = 0; fm < 4; ++fm) {
        int r0 = rowb + fm * 16;
        int r1 = r0 + 8;
#pragma unroll
        for (int fn = 0; fn < 4; ++fn) {
            int col = colb + fn * 8 + (lane & 3) * 2;
            float2 bp = *reinterpret_cast<const float2*>(&bias[col]);
            float v0 = acc[fm][fn][0] + bp.x;
            float v1 = acc[fm][fn][1] + bp.y;
            float v2 = acc[fm][fn][2] + bp.x;
            float v3 = acc[fm][fn][3] + bp.y;
            if (RELU) {
                v0 = fmaxf(v0, 0.f); v1 = fmaxf(v1, 0.f);
                v2 = fmaxf(v2, 0.f); v3 = fmaxf(v3, 0.f);
            }
            if (OUT == 0) {
                if (r0 < M)
                    *reinterpret_cast<float2*>(&C[(size_t)r0 * HID + col]) =
                        make_float2(v0, v1);
                if (r1 < M)
                    *reinterpret_cast<float2*>(&C[(size_t)r1 * HID + col]) =
                        make_float2(v2, v3);
            } else {
                if (r0 < M) {
                    size_t h = ((size_t)r0 * HID + col) >> 1;
                    __nv_bfloat16 h0 = __float2bfloat16(v0);
                    __nv_bfloat16 h1 = __float2bfloat16(v1);
                    Oh[h] = __nv_bfloat162(h0, h1);
                    Ol[h] = __nv_bfloat162(
                        __float2bfloat16(v0 - __bfloat162float(h0)),
                        __float2bfloat16(v1 - __bfloat162float(h1)));
                }
                if (r1 < M) {
                    size_t h = ((size_t)r1 * HID + col) >> 1;
                    __nv_bfloat16 h2 = __float2bfloat16(v2);
                    __nv_bfloat16 h3 = __float2bfloat16(v3);
                    Oh[h] = __nv_bfloat162(h2, h3);
                    Ol[h] = __nv_bfloat162(
                        __float2bfloat16(v2 - __bfloat162float(h2)),
                        __float2bfloat16(v3 - __bfloat162float(h3)));
                }
            }
        }
    }
}

// ---------------------------------------------------------------------------
// fp32 register-tiled SGEMM (kept only for the small classifier GEMM)
// ---------------------------------------------------------------------------
template <int BM, int BN, int BK, int TM, int TN, bool RELU>
__launch_bounds__((BM / TM) * (BN / TN))
__global__ void sgemm_bias_kernel(const float* __restrict__ A,
                                  const float* __restrict__ B,
                                  const float* __restrict__ bias,
                                  float* __restrict__ C,
                                  int M, int N, int K) {
    constexpr int THREADS = (BM / TM) * (BN / TN);
    __shared__ float As[BK][BM];
    __shared__ float Bs[BK][BN];
    const int tid = threadIdx.x;
    const int tx = tid % (BN / TN);
    const int ty = tid / (BN / TN);
    const int rowBase = blockIdx.y * BM;
    const int colBase = blockIdx.x * BN;
    constexpr int A_F4 = BM * BK / 4;
    constexpr int AKQ  = BK / 4;
    constexpr int B_F4 = BK * BN / 4;
    constexpr int BNQ  = BN / 4;

    float acc[TM][TN];
#pragma unroll
    for (int i = 0; i < TM; i++)
#pragma unroll
        for (int j = 0; j < TN; j++) acc[i][j] = 0.0f;

    for (int k0 = 0; k0 < K; k0 += BK) {
#pragma unroll
        for (int i = tid; i < A_F4; i += THREADS) {
            int r = i / AKQ, kq = i % AKQ;
            int gr = rowBase + r;
            float4 v = make_float4(0.f, 0.f, 0.f, 0.f);
            if (gr < M)
                v = *reinterpret_cast<const float4*>(&A[(size_t)gr * K + k0 + kq * 4]);
            As[kq * 4 + 0][r] = v.x; As[kq * 4 + 1][r] = v.y;
            As[kq * 4 + 2][r] = v.z; As[kq * 4 + 3][r] = v.w;
        }
#pragma unroll
        for (int i = tid; i < B_F4; i += THREADS) {
            int r = i / BNQ, c = i % BNQ;
            *reinterpret_cast<float4*>(&Bs[r][c * 4]) =
                *reinterpret_cast<const float4*>(&B[(size_t)(k0 + r) * N + colBase + c * 4]);
        }
        __syncthreads();
#pragma unroll
        for (int kk = 0; kk < BK; kk++) {
            float ra[TM], rb[TN];
#pragma unroll
            for (int i = 0; i < TM; i++) ra[i] = As[kk][ty * TM + i];
#pragma unroll
            for (int j = 0; j < TN; j++) rb[j] = Bs[kk][tx * TN + j];
#pragma unroll
            for (int i = 0; i < TM; i++)
#pragma unroll
                for (int j = 0; j < TN; j++)
                    acc[i][j] = fmaf(ra[i], rb[j], acc[i][j]);
        }
        __syncthreads();
    }
#pragma unroll
    for (int i = 0; i < TM; i++) {
        int gr = rowBase + ty * TM + i;
        if (gr >= M) continue;
#pragma unroll
        for (int j = 0; j < TN; j += 4) {
            int gc = colBase + tx * TN + j;
            float4 v;
            v.x = acc[i][j + 0] + bias[gc + 0];
            v.y = acc[i][j + 1] + bias[gc + 1];
            v.z = acc[i][j + 2] + bias[gc + 2];
            v.w = acc[i][j + 3] + bias[gc + 3];
            if (RELU) {
                v.x = fmaxf(v.x, 0.f); v.y = fmaxf(v.y, 0.f);
                v.z = fmaxf(v.z, 0.f); v.w = fmaxf(v.w, 0.f);
            }
            *reinterpret_cast<float4*>(&C[(size_t)gr * N + gc]) = v;
        }
    }
}

// ---------------------------------------------------------------------------
// In-place log_softmax over 64 classes, one warp per row
// ---------------------------------------------------------------------------
__global__ void log_softmax64_kernel(float* __restrict__ out, int M) {
    int warp = (blockIdx.x * blockDim.x + threadIdx.x) >> 5;
    int lane = threadIdx.x & 31;
    if (warp >= M) return;
    float* row = out + (size_t)warp * N_CLS;
    float a = row[lane];
    float b = row[lane + 32];
    float m = fmaxf(a, b);
#pragma unroll
    for (int o = 16; o > 0; o >>= 1)
        m = fmaxf(m, __shfl_xor_sync(0xFFFFFFFFu, m, o));
    float s = expf(a - m) + expf(b - m);
#pragma unroll
    for (int o = 16; o > 0; o >>= 1)
        s += __shfl_xor_sync(0xFFFFFFFFu, s, o);
    float lse = m + logf(s);
    row[lane]      = a - lse;
    row[lane + 32] = b - lse;
}

// ---------------------------------------------------------------------------
// Launch
// ---------------------------------------------------------------------------
extern "C" void kernel_launch(void* const* d_in, const int* in_sizes, int n_in,
                              void* d_out, int out_size) {
    const float*        x   = (const float*)d_in[0];
    const unsigned int* ei  = (const unsigned int*)d_in[1];
    const float* W1a = (const float*)d_in[2];
    const float* b1a = (const float*)d_in[3];
    const float* W1b = (const float*)d_in[4];
    const float* b1b = (const float*)d_in[5];
    const float* W2a = (const float*)d_in[6];
    const float* b2a = (const float*)d_in[7];
    const float* W2b = (const float*)d_in[8];
    const float* b2b = (const float*)d_in[9];
    const float* Wfc = (const float*)d_in[10];
    const float* bfc = (const float*)d_in[11];
    float* out = (float*)d_out;

    float *buf256, *bufA, *bufB;
    __nv_bfloat16 *Ah, *Al, *Ch, *Cl, *Wh, *Wl;
    cudaGetSymbolAddress((void**)&buf256, g_buf256);
    cudaGetSymbolAddress((void**)&bufA, g_bufA);
    cudaGetSymbolAddress((void**)&bufB, g_bufB);
    cudaGetSymbolAddress((void**)&Ah, g_Ah);
    cudaGetSymbolAddress((void**)&Al, g_Al);
    cudaGetSymbolAddress((void**)&Ch, g_Ch);
    cudaGetSymbolAddress((void**)&Cl, g_Cl);
    cudaGetSymbolAddress((void**)&Wh, g_Wh);
    cudaGetSymbolAddress((void**)&Wl, g_Wl);

    const int GEMM_SMEM = 3 * 65536 + 1024;  // 197632 B (3-stage + align slack)
    cudaFuncSetAttribute(gemm_bf16x3_mma_kernel<256, true, 1>,
                         cudaFuncAttributeMaxDynamicSharedMemorySize, GEMM_SMEM);
    cudaFuncSetAttribute(gemm_bf16x3_mma_kernel<1024, true, 0>,
                         cudaFuncAttributeMaxDynamicSharedMemorySize, GEMM_SMEM);
    cudaFuncSetAttribute(gemm_bf16x3_mma_kernel<1024, true, 1>,
                         cudaFuncAttributeMaxDynamicSharedMemorySize, GEMM_SMEM);
    cudaFuncSetAttribute(gemm_bf16x3_mma_kernel<1024, false, 0>,
                         cudaFuncAttributeMaxDynamicSharedMemorySize, GEMM_SMEM);

    // Edge index normalization
    detect_idx_kernel<<<1, 256>>>(ei);
    convert_idx_kernel<<<(2 * N_EDGES + 255) / 256, 256>>>(ei);

    dim3 gridGemm(HID / 128, (N_NODES + 127) / 128);   // (8, 782)
    dim3 gridFC(1, (N_NODES + 127) / 128);

    // ---- Layer 1 aggregation: buf256 = x + segsum(x[src] -> dst) ----
    {
        long n4 = (long)N_NODES * (D_IN / 4);
        copy_f4_kernel<<<(int)((n4 + 255) / 256), 256>>>(
            (const float4*)x, (float4*)buf256, n4);
        long work = (long)N_EDGES * (D_IN / 4);
        scatter_add_kernel<D_IN / 4><<<(int)((work + 255) / 256), 256>>>(
            (const float4*)x, buf256);
    }
    // GEMM1a: Ch/Cl = split(relu(buf256 @ W1a + b1a))
    {
        long n4 = (long)N_NODES * (D_IN / 4);
        split_act_kernel<<<(int)((n4 + 255) / 256), 256>>>(
            (const float4*)buf256, (__nv_bfloat162*)Ah, (__nv_bfloat162*)Al, n4);
        split_weightT_kernel<<<(D_IN * HID + 255) / 256, 256>>>(W1a, Wh, Wl, D_IN, HID);
        gemm_bf16x3_mma_kernel<256, true, 1><<<gridGemm, 256, GEMM_SMEM>>>(
            Ah, Al, Wh, Wl, b1a, nullptr,
            (__nv_bfloat162*)Ch, (__nv_bfloat162*)Cl, N_NODES);
    }
    // GEMM1b: bufB = relu(Ch/Cl @ W1b + b1b) = h1   (outer relu fused)
    {
        split_weightT_kernel<<<(HID * HID + 255) / 256, 256>>>(W1b, Wh, Wl, HID, HID);
        gemm_bf16x3_mma_kernel<1024, true, 0><<<gridGemm, 256, GEMM_SMEM>>>(
            Ch, Cl, Wh, Wl, b1b, bufB, nullptr, nullptr, N_NODES);
    }
    // ---- Layer 2 aggregation: bufA = h1 + segsum(h1[src] -> dst) ----
    {
        long n4 = (long)N_NODES * (HID / 4);
        copy_f4_kernel<<<(int)((n4 + 255) / 256), 256>>>(
            (const float4*)bufB, (float4*)bufA, n4);
        long work = (long)N_EDGES * (HID / 4);
        scatter_add_kernel<HID / 4><<<(int)((work + 255) / 256), 256>>>(
            (const float4*)bufB, bufA);
    }
    // GEMM2a: Ch/Cl = split(relu(bufA @ W2a + b2a))
    {
        long n4 = (long)N_NODES * (HID / 4);
        split_act_kernel<<<(int)((n4 + 255) / 256), 256>>>(
            (const float4*)bufA, (__nv_bfloat162*)Ah, (__nv_bfloat162*)Al, n4);
        split_weightT_kernel<<<(HID * HID + 255) / 256, 256>>>(W2a, Wh, Wl, HID, HID);
        gemm_bf16x3_mma_kernel<1024, true, 1><<<gridGemm, 256, GEMM_SMEM>>>(
            Ah, Al, Wh, Wl, b2a, nullptr,
            (__nv_bfloat162*)Ch, (__nv_bfloat162*)Cl, N_NODES);
    }
    // GEMM2b: bufA = Ch/Cl @ W2b + b2b   (no relu) = h2
    {
        split_weightT_kernel<<<(HID * HID + 255) / 256, 256>>>(W2b, Wh, Wl, HID, HID);
        gemm_bf16x3_mma_kernel<1024, false, 0><<<gridGemm, 256, GEMM_SMEM>>>(
            Ch, Cl, Wh, Wl, b2b, bufA, nullptr, nullptr, N_NODES);
    }
    // ---- Classifier (fp32) + log_softmax ----
    sgemm_bias_kernel<128, 64, 16, 8, 4, false><<<gridFC, 256>>>(
        bufA, Wfc, bfc, out, N_NODES, N_CLS, HID);
    log_softmax64_kernel<<<(N_NODES * 32 + 255) / 256, 256>>>(out, N_NODES);
}

// round 8
// speedup vs baseline: 2.5401x; 1.0241x over previous
#include <cuda_runtime.h>
#include <cuda_bf16.h>
#include <math.h>
#include <stdint.h>

// Problem constants (fixed by the reference)
#define N_NODES  100000
#define N_EDGES  300000
#define D_IN     256
#define HID      1024
#define N_CLS    64

// ---------------------------------------------------------------------------
// Scratch (device globals: allocation-free)
// ---------------------------------------------------------------------------
__device__ float g_buf256[(size_t)N_NODES * D_IN];          // 102.4 MB
__device__ float g_bufA[(size_t)N_NODES * HID];             // 409.6 MB
__device__ float g_bufB[(size_t)N_NODES * HID];             // 409.6 MB
__device__ __nv_bfloat16 g_Ah[(size_t)N_NODES * HID];       // split pair 0
__device__ __nv_bfloat16 g_Al[(size_t)N_NODES * HID];
__device__ __nv_bfloat16 g_Ch[(size_t)N_NODES * HID];       // split pair 1
__device__ __nv_bfloat16 g_Cl[(size_t)N_NODES * HID];
__device__ __nv_bfloat16 g_Wh[(size_t)HID * HID];           // weight^T split
__device__ __nv_bfloat16 g_Wl[(size_t)HID * HID];
__device__ float g_bfcPad[128];                             // padded classifier bias
__device__ int   g_edges[2 * N_EDGES];
__device__ int   g_idx64;

// ---------------------------------------------------------------------------
// PTX helpers (all sm_80-era: valid under compute_103, no 'a' features)
// ---------------------------------------------------------------------------
__device__ __forceinline__ uint32_t s2u(const void* p) {
    uint32_t a;
    asm("{ .reg .u64 t; cvta.to.shared.u64 t, %1; cvt.u32.u64 %0, t; }"
        : "=r"(a) : "l"(p));
    return a;
}

__device__ __forceinline__ void cp_async16(uint32_t s, const void* g, unsigned sz) {
    asm volatile("cp.async.cg.shared.global [%0], [%1], 16, %2;"
                 :: "r"(s), "l"(g), "r"(sz));
}

__device__ __forceinline__ void ldsm4(uint32_t* r, uint32_t addr) {
    asm volatile("ldmatrix.sync.aligned.m8n8.x4.shared.b16 {%0,%1,%2,%3}, [%4];"
                 : "=r"(r[0]), "=r"(r[1]), "=r"(r[2]), "=r"(r[3]) : "r"(addr));
}

__device__ __forceinline__ void mma_bf16(float* d, const uint32_t* a,
                                         const uint32_t* b) {
    asm volatile(
        "mma.sync.aligned.m16n8k16.row.col.f32.bf16.bf16.f32 "
        "{%0,%1,%2,%3},{%4,%5,%6,%7},{%8,%9},{%0,%1,%2,%3};"
        : "+f"(d[0]), "+f"(d[1]), "+f"(d[2]), "+f"(d[3])
        : "r"(a[0]), "r"(a[1]), "r"(a[2]), "r"(a[3]), "r"(b[0]), "r"(b[1]));
}

// ---------------------------------------------------------------------------
// Edge-index dtype detection + normalization
// ---------------------------------------------------------------------------
__global__ void detect_idx_kernel(const unsigned int* __restrict__ ei) {
    unsigned v = ei[2 * threadIdx.x + 1];
    int any = __syncthreads_or(v != 0u);
    if (threadIdx.x == 0) g_idx64 = any ? 0 : 1;
}

__global__ void convert_idx_kernel(const unsigned int* __restrict__ ei) {
    int i = blockIdx.x * blockDim.x + threadIdx.x;
    if (i < 2 * N_EDGES) g_edges[i] = g_idx64 ? (int)ei[2 * i] : (int)ei[i];
}

// ---------------------------------------------------------------------------
// float4 copy
// ---------------------------------------------------------------------------
__global__ void copy_f4_kernel(const float4* __restrict__ src,
                               float4* __restrict__ dst, long n) {
    long i = (long)blockIdx.x * blockDim.x + threadIdx.x;
    if (i < n) dst[i] = src[i];
}

// ---------------------------------------------------------------------------
// Scatter-add aggregation: buf[dst] += feat[src]
// ---------------------------------------------------------------------------
template <int D4>
__global__ void scatter_add_kernel(const float4* __restrict__ feat,
                                   float* __restrict__ buf) {
    long idx = (long)blockIdx.x * blockDim.x + threadIdx.x;
    if (idx >= (long)N_EDGES * D4) return;
    int e = (int)(idx / D4);
    int d = (int)(idx % D4);
    int s = g_edges[e];
    int t = g_edges[N_EDGES + e];
    float4 v = feat[(size_t)s * D4 + d];
    float* p = buf + ((size_t)t * D4 + d) * 4;
    atomicAdd(p + 0, v.x);
    atomicAdd(p + 1, v.y);
    atomicAdd(p + 2, v.z);
    atomicAdd(p + 3, v.w);
}

// ---------------------------------------------------------------------------
// fp32 -> (bf16 hi, bf16 lo) split, element-wise (activations)
// ---------------------------------------------------------------------------
__global__ void split_act_kernel(const float4* __restrict__ X,
                                 __nv_bfloat162* __restrict__ Th,
                                 __nv_bfloat162* __restrict__ Tl, long n4) {
    long i = (long)blockIdx.x * blockDim.x + threadIdx.x;
    if (i >= n4) return;
    float4 v = X[i];
    __nv_bfloat16 h0 = __float2bfloat16(v.x), h1 = __float2bfloat16(v.y);
    __nv_bfloat16 h2 = __float2bfloat16(v.z), h3 = __float2bfloat16(v.w);
    __nv_bfloat16 l0 = __float2bfloat16(v.x - __bfloat162float(h0));
    __nv_bfloat16 l1 = __float2bfloat16(v.y - __bfloat162float(h1));
    __nv_bfloat16 l2 = __float2bfloat16(v.z - __bfloat162float(h2));
    __nv_bfloat16 l3 = __float2bfloat16(v.w - __bfloat162float(h3));
    Th[2 * i]     = __nv_bfloat162(h0, h1);
    Th[2 * i + 1] = __nv_bfloat162(h2, h3);
    Tl[2 * i]     = __nv_bfloat162(l0, l1);
    Tl[2 * i + 1] = __nv_bfloat162(l2, l3);
}

// ---------------------------------------------------------------------------
// Weight W[K,N] fp32 -> transposed split Wt[Npad,K] bf16 hi/lo (zero-pad rows)
// ---------------------------------------------------------------------------
__global__ void split_weightT_kernel(const float* __restrict__ W,
                                     __nv_bfloat16* __restrict__ Th,
                                     __nv_bfloat16* __restrict__ Tl,
                                     int Kd, int Nd, int Npad) {
    int idx = blockIdx.x * blockDim.x + threadIdx.x;
    if (idx >= Kd * Npad) return;
    int n = idx / Kd;
    int k = idx % Kd;
    float v = (n < Nd) ? W[(size_t)k * Nd + n] : 0.0f;
    __nv_bfloat16 h = __float2bfloat16(v);
    Th[idx] = h;
    Tl[idx] = __float2bfloat16(v - __bfloat162float(h));
}

__global__ void pad_bias_kernel(const float* __restrict__ b, int n) {
    int i = threadIdx.x;
    if (i < 128) g_bfcPad[i] = (i < n) ? b[i] : 0.0f;
}

// ---------------------------------------------------------------------------
// bf16x3 mma.sync GEMM:  C[M, ncols] = act(A[M,K] @ W[K,ncols] + bias)
// A: bf16 hi/lo [M,K].  W: transposed bf16 hi/lo [128-col-padded N, K].
// BM=128, BN=128, BK=64. 256 threads = 2x4 warps (64x32 per warp).
// 3-stage cp.async pipeline; SW128-swizzled SMEM; double-buffered ldsm frags.
// OUT: 0 = fp32 to C (stride ostride, guard col<ncols); 1 = split bf16 Oh/Ol.
// ---------------------------------------------------------------------------
template <int K>
__device__ __forceinline__ void load_stage(uint32_t tbase, int stage,
    const __nv_bfloat16* __restrict__ Ah, const __nv_bfloat16* __restrict__ Al,
    const __nv_bfloat16* __restrict__ Bh, const __nv_bfloat16* __restrict__ Bl,
    int chunk, int rowBase, int colBase, int M) {
    const int tid = threadIdx.x;
    const uint32_t sBase = tbase + (uint32_t)stage * 65536u;
    const long kOff = (long)chunk * 64;
#pragma unroll
    for (int i = 0; i < 4; ++i) {
        int t = i * 256 + tid;            // 0..1023 16B chunks per 16KB tile
        int r = t >> 3;
        int cc = t & 7;
        uint32_t sw = (uint32_t)(r * 128 + ((cc ^ (r & 7)) << 4));
        int gr = rowBase + r;
        unsigned sz = (gr < M) ? 16u : 0u;
        int ga = gr < M ? gr : (M - 1);
        size_t aoff = ((size_t)ga * K + kOff + cc * 8) * 2;  // bytes
        cp_async16(sBase + sw,          (const char*)Ah + aoff, sz);
        cp_async16(sBase + 16384u + sw, (const char*)Al + aoff, sz);
        int gn = colBase + r;
        size_t boff = ((size_t)gn * K + kOff + cc * 8) * 2;
        cp_async16(sBase + 32768u + sw, (const char*)Bh + boff, 16u);
        cp_async16(sBase + 49152u + sw, (const char*)Bl + boff, 16u);
    }
}

struct Frags {
    uint32_t ah[4][4];
    uint32_t al[4][4];
    uint32_t bh[2][4];
    uint32_t bl[2][4];
};

__device__ __forceinline__ void load_frags(uint32_t st, int k,
                                           const int* arow, const int* brow,
                                           int a_ck, int b_ck, Frags& f) {
    const uint32_t aHi = st, aLo = st + 16384u;
    const uint32_t bHi = st + 32768u, bLo = st + 49152u;
#pragma unroll
    for (int fm = 0; fm < 4; ++fm) {
        int row = arow[fm];
        int ck = k * 2 + a_ck;
        uint32_t off = (uint32_t)(row * 128 + ((ck ^ (row & 7)) << 4));
        ldsm4(f.ah[fm], aHi + off);
        ldsm4(f.al[fm], aLo + off);
    }
#pragma unroll
    for (int f2 = 0; f2 < 2; ++f2) {
        int row = brow[f2];
        int ck = k * 2 + b_ck;
        uint32_t off = (uint32_t)(row * 128 + ((ck ^ (row & 7)) << 4));
        ldsm4(f.bh[f2], bHi + off);
        ldsm4(f.bl[f2], bLo + off);
    }
}

__device__ __forceinline__ void mma_frags(const Frags& f, float acc[4][4][4]) {
#pragma unroll
    for (int fm = 0; fm < 4; ++fm)
#pragma unroll
        for (int fn = 0; fn < 4; ++fn) {
            const uint32_t* pbh = &f.bh[fn >> 1][(fn & 1) * 2];
            const uint32_t* pbl = &f.bl[fn >> 1][(fn & 1) * 2];
            mma_bf16(acc[fm][fn], f.ah[fm], pbh);  // Ah*Bh
            mma_bf16(acc[fm][fn], f.ah[fm], pbl);  // Ah*Bl
            mma_bf16(acc[fm][fn], f.al[fm], pbh);  // Al*Bh
        }
}

template <int K, bool RELU, int OUT>
__global__ void __launch_bounds__(256)
gemm_bf16x3_mma_kernel(const __nv_bfloat16* __restrict__ Ah,
                       const __nv_bfloat16* __restrict__ Al,
                       const __nv_bfloat16* __restrict__ Bh,
                       const __nv_bfloat16* __restrict__ Bl,
                       const float* __restrict__ bias,
                       float* __restrict__ C,
                       __nv_bfloat162* __restrict__ Oh,
                       __nv_bfloat162* __restrict__ Ol,
                       int M, int ostride, int ncols) {
    constexpr int NC = K / 64;
    extern __shared__ char smem[];
    const uint32_t tile_base = (s2u(smem) + 1023u) & ~1023u;

    const int tid = threadIdx.x;
    const int wid = tid >> 5;
    const int lane = tid & 31;
    const int wm = wid >> 2;          // 0..1
    const int wn = wid & 3;           // 0..3
    const int rowBase = blockIdx.y * 128;
    const int colBase = blockIdx.x * 128;

    // ldmatrix source row/chunk mapping (same math as R6, hoisted)
    const int midx = lane >> 3;
    const int l7 = lane & 7;
    const int a_ck = (midx >> 1);
    const int b_ck = (midx & 1);
    int arow[4], brow[2];
#pragma unroll
    for (int fm = 0; fm < 4; ++fm)
        arow[fm] = wm * 64 + fm * 16 + ((midx & 1) << 3) + l7;
#pragma unroll
    for (int f2 = 0; f2 < 2; ++f2)
        brow[f2] = wn * 32 + f2 * 16 + ((midx >> 1) << 3) + l7;

    float acc[4][4][4];
#pragma unroll
    for (int i = 0; i < 4; i++)
#pragma unroll
        for (int j = 0; j < 4; j++)
#pragma unroll
            for (int q = 0; q < 4; q++) acc[i][j][q] = 0.0f;

    // Prologue: prefetch chunks 0, 1
    load_stage<K>(tile_base, 0, Ah, Al, Bh, Bl, 0, rowBase, colBase, M);
    asm volatile("cp.async.commit_group;" ::: "memory");
    load_stage<K>(tile_base, 1, Ah, Al, Bh, Bl, 1, rowBase, colBase, M);
    asm volatile("cp.async.commit_group;" ::: "memory");

    Frags fr[2];
    for (int c = 0; c < NC; ++c) {
        if (c + 1 < NC) asm volatile("cp.async.wait_group 1;" ::: "memory");
        else            asm volatile("cp.async.wait_group 0;" ::: "memory");
        __syncthreads();
        const uint32_t st = tile_base + (uint32_t)(c % 3) * 65536u;
        // Preload k=0 fragments, then issue next stage's cp.async
        load_frags(st, 0, arow, brow, a_ck, b_ck, fr[0]);
        if (c + 2 < NC) {
            load_stage<K>(tile_base, (c + 2) % 3, Ah, Al, Bh, Bl,
                          c + 2, rowBase, colBase, M);
            asm volatile("cp.async.commit_group;" ::: "memory");
        }
        // Software-pipelined k loop: prefetch k+1 while computing k
#pragma unroll
        for (int k = 0; k < 4; ++k) {
            if (k < 3) load_frags(st, k + 1, arow, brow, a_ck, b_ck, fr[(k + 1) & 1]);
            mma_frags(fr[k & 1], acc);
        }
    }

    // Epilogue: bias (+relu), fp32 (strided, col-guarded) or split-bf16 output
    const int rowb = rowBase + wm * 64 + (lane >> 2);
    const int colb = colBase + wn * 32;
#pragma unroll
    for (int fm = 0; fm < 4; ++fm) {
        int r0 = rowb + fm * 16;
        int r1 = r0 + 8;
#pragma unroll
        for (int fn = 0; fn < 4; ++fn) {
            int col = colb + fn * 8 + (lane & 3) * 2;
            float2 bp = *reinterpret_cast<const float2*>(&bias[col]);
            float v0 = acc[fm][fn][0] + bp.x;
            float v1 = acc[fm][fn][1] + bp.y;
            float v2 = acc[fm][fn][2] + bp.x;
            float v3 = acc[fm][fn][3] + bp.y;
            if (RELU) {
                v0 = fmaxf(v0, 0.f); v1 = fmaxf(v1, 0.f);
                v2 = fmaxf(v2, 0.f); v3 = fmaxf(v3, 0.f);
            }
            if (OUT == 0) {
                if (col < ncols) {
                    if (r0 < M)
                        *reinterpret_cast<float2*>(&C[(size_t)r0 * ostride + col]) =
                            make_float2(v0, v1);
                    if (r1 < M)
                        *reinterpret_cast<float2*>(&C[(size_t)r1 * ostride + col]) =
                            make_float2(v2, v3);
                }
            } else {
                if (r0 < M) {
                    size_t h = ((size_t)r0 * ostride + col) >> 1;
                    __nv_bfloat16 h0 = __float2bfloat16(v0);
                    __nv_bfloat16 h1 = __float2bfloat16(v1);
                    Oh[h] = __nv_bfloat162(h0, h1);
                    Ol[h] = __nv_bfloat162(
                        __float2bfloat16(v0 - __bfloat162float(h0)),
                        __float2bfloat16(v1 - __bfloat162float(h1)));
                }
                if (r1 < M) {
                    size_t h = ((size_t)r1 * ostride + col) >> 1;
                    __nv_bfloat16 h2 = __float2bfloat16(v2);
                    __nv_bfloat16 h3 = __float2bfloat16(v3);
                    Oh[h] = __nv_bfloat162(h2, h3);
                    Ol[h] = __nv_bfloat162(
                        __float2bfloat16(v2 - __bfloat162float(h2)),
                        __float2bfloat16(v3 - __bfloat162float(h3)));
                }
            }
        }
    }
}

// ---------------------------------------------------------------------------
// In-place log_softmax over 64 classes, one warp per row
// ---------------------------------------------------------------------------
__global__ void log_softmax64_kernel(float* __restrict__ out, int M) {
    int warp = (blockIdx.x * blockDim.x + threadIdx.x) >> 5;
    int lane = threadIdx.x & 31;
    if (warp >= M) return;
    float* row = out + (size_t)warp * N_CLS;
    float a = row[lane];
    float b = row[lane + 32];
    float m = fmaxf(a, b);
#pragma unroll
    for (int o = 16; o > 0; o >>= 1)
        m = fmaxf(m, __shfl_xor_sync(0xFFFFFFFFu, m, o));
    float s = expf(a - m) + expf(b - m);
#pragma unroll
    for (int o = 16; o > 0; o >>= 1)
        s += __shfl_xor_sync(0xFFFFFFFFu, s, o);
    float lse = m + logf(s);
    row[lane]      = a - lse;
    row[lane + 32] = b - lse;
}

// ---------------------------------------------------------------------------
// Launch
// ---------------------------------------------------------------------------
extern "C" void kernel_launch(void* const* d_in, const int* in_sizes, int n_in,
                              void* d_out, int out_size) {
    const float*        x   = (const float*)d_in[0];
    const unsigned int* ei  = (const unsigned int*)d_in[1];
    const float* W1a = (const float*)d_in[2];
    const float* b1a = (const float*)d_in[3];
    const float* W1b = (const float*)d_in[4];
    const float* b1b = (const float*)d_in[5];
    const float* W2a = (const float*)d_in[6];
    const float* b2a = (const float*)d_in[7];
    const float* W2b = (const float*)d_in[8];
    const float* b2b = (const float*)d_in[9];
    const float* Wfc = (const float*)d_in[10];
    const float* bfc = (const float*)d_in[11];
    float* out = (float*)d_out;

    float *buf256, *bufA, *bufB, *bfcPad;
    __nv_bfloat16 *Ah, *Al, *Ch, *Cl, *Wh, *Wl;
    cudaGetSymbolAddress((void**)&buf256, g_buf256);
    cudaGetSymbolAddress((void**)&bufA, g_bufA);
    cudaGetSymbolAddress((void**)&bufB, g_bufB);
    cudaGetSymbolAddress((void**)&Ah, g_Ah);
    cudaGetSymbolAddress((void**)&Al, g_Al);
    cudaGetSymbolAddress((void**)&Ch, g_Ch);
    cudaGetSymbolAddress((void**)&Cl, g_Cl);
    cudaGetSymbolAddress((void**)&Wh, g_Wh);
    cudaGetSymbolAddress((void**)&Wl, g_Wl);
    cudaGetSymbolAddress((void**)&bfcPad, g_bfcPad);

    const int GEMM_SMEM = 3 * 65536 + 1024;  // 197632 B (3-stage + align slack)
    cudaFuncSetAttribute(gemm_bf16x3_mma_kernel<256, true, 1>,
                         cudaFuncAttributeMaxDynamicSharedMemorySize, GEMM_SMEM);
    cudaFuncSetAttribute(gemm_bf16x3_mma_kernel<1024, true, 0>,
                         cudaFuncAttributeMaxDynamicSharedMemorySize, GEMM_SMEM);
    cudaFuncSetAttribute(gemm_bf16x3_mma_kernel<1024, true, 1>,
                         cudaFuncAttributeMaxDynamicSharedMemorySize, GEMM_SMEM);
    cudaFuncSetAttribute(gemm_bf16x3_mma_kernel<1024, false, 0>,
                         cudaFuncAttributeMaxDynamicSharedMemorySize, GEMM_SMEM);
    cudaFuncSetAttribute(gemm_bf16x3_mma_kernel<1024, false, 1>,
                         cudaFuncAttributeMaxDynamicSharedMemorySize, GEMM_SMEM);

    // Edge index normalization
    detect_idx_kernel<<<1, 256>>>(ei);
    convert_idx_kernel<<<(2 * N_EDGES + 255) / 256, 256>>>(ei);

    dim3 gridGemm(HID / 128, (N_NODES + 127) / 128);   // (8, 782)
    dim3 gridFC(1, (N_NODES + 127) / 128);

    // ---- Layer 1 aggregation: buf256 = x + segsum(x[src] -> dst) ----
    {
        long n4 = (long)N_NODES * (D_IN / 4);
        copy_f4_kernel<<<(int)((n4 + 255) / 256), 256>>>(
            (const float4*)x, (float4*)buf256, n4);
        long work = (long)N_EDGES * (D_IN / 4);
        scatter_add_kernel<D_IN / 4><<<(int)((work + 255) / 256), 256>>>(
            (const float4*)x, buf256);
    }
    // GEMM1a: Ch/Cl = split(relu(buf256 @ W1a + b1a))
    {
        long n4 = (long)N_NODES * (D_IN / 4);
        split_act_kernel<<<(int)((n4 + 255) / 256), 256>>>(
            (const float4*)buf256, (__nv_bfloat162*)Ah, (__nv_bfloat162*)Al, n4);
        split_weightT_kernel<<<(D_IN * HID + 255) / 256, 256>>>(
            W1a, Wh, Wl, D_IN, HID, HID);
        gemm_bf16x3_mma_kernel<256, true, 1><<<gridGemm, 256, GEMM_SMEM>>>(
            Ah, Al, Wh, Wl, b1a, nullptr,
            (__nv_bfloat162*)Ch, (__nv_bfloat162*)Cl, N_NODES, HID, HID);
    }
    // GEMM1b: bufB = relu(Ch/Cl @ W1b + b1b) = h1   (outer relu fused)
    {
        split_weightT_kernel<<<(HID * HID + 255) / 256, 256>>>(
            W1b, Wh, Wl, HID, HID, HID);
        gemm_bf16x3_mma_kernel<1024, true, 0><<<gridGemm, 256, GEMM_SMEM>>>(
            Ch, Cl, Wh, Wl, b1b, bufB, nullptr, nullptr, N_NODES, HID, HID);
    }
    // ---- Layer 2 aggregation: bufA = h1 + segsum(h1[src] -> dst) ----
    {
        long n4 = (long)N_NODES * (HID / 4);
        copy_f4_kernel<<<(int)((n4 + 255) / 256), 256>>>(
            (const float4*)bufB, (float4*)bufA, n4);
        long work = (long)N_EDGES * (HID / 4);
        scatter_add_kernel<HID / 4><<<(int)((work + 255) / 256), 256>>>(
            (const float4*)bufB, bufA);
    }
    // GEMM2a: Ch/Cl = split(relu(bufA @ W2a + b2a))
    {
        long n4 = (long)N_NODES * (HID / 4);
        split_act_kernel<<<(int)((n4 + 255) / 256), 256>>>(
            (const float4*)bufA, (__nv_bfloat162*)Ah, (__nv_bfloat162*)Al, n4);
        split_weightT_kernel<<<(HID * HID + 255) / 256, 256>>>(
            W2a, Wh, Wl, HID, HID, HID);
        gemm_bf16x3_mma_kernel<1024, true, 1><<<gridGemm, 256, GEMM_SMEM>>>(
            Ah, Al, Wh, Wl, b2a, nullptr,
            (__nv_bfloat162*)Ch, (__nv_bfloat162*)Cl, N_NODES, HID, HID);
    }
    // GEMM2b: Ah/Al = split(Ch/Cl @ W2b + b2b)   (no relu) = h2, split form
    {
        split_weightT_kernel<<<(HID * HID + 255) / 256, 256>>>(
            W2b, Wh, Wl, HID, HID, HID);
        gemm_bf16x3_mma_kernel<1024, false, 1><<<gridGemm, 256, GEMM_SMEM>>>(
            Ch, Cl, Wh, Wl, b2b, nullptr,
            (__nv_bfloat162*)Ah, (__nv_bfloat162*)Al, N_NODES, HID, HID);
    }
    // ---- Classifier on tensor cores (N padded 64->128) + log_softmax ----
    {
        pad_bias_kernel<<<1, 128>>>(bfc, N_CLS);
        split_weightT_kernel<<<(HID * 128 + 255) / 256, 256>>>(
            Wfc, Wh, Wl, HID, N_CLS, 128);
        gemm_bf16x3_mma_kernel<1024, false, 0><<<gridFC, 256, GEMM_SMEM>>>(
            Ah, Al, Wh, Wl, bfcPad, out, nullptr, nullptr, N_NODES, N_CLS, N_CLS);
    }
    log_softmax64_kernel<<<(N_NODES * 32 + 255) / 256, 256>>>(out, N_NODES);
}

// round 9
// speedup vs baseline: 3.2467x; 1.2782x over previous
#include <cuda_runtime.h>
#include <cuda_bf16.h>
#include <math.h>
#include <stdint.h>

// Problem constants (fixed by the reference)
#define N_NODES  100000
#define N_EDGES  300000
#define D_IN     256
#define HID      1024
#define N_CLS    64

// ---------------------------------------------------------------------------
// Scratch (device globals: allocation-free)
// ---------------------------------------------------------------------------
__device__ float g_buf256[(size_t)N_NODES * D_IN];          // 102.4 MB
__device__ float g_bufA[(size_t)N_NODES * HID];             // 409.6 MB
__device__ float g_bufB[(size_t)N_NODES * HID];             // 409.6 MB
__device__ __nv_bfloat16 g_Ah[(size_t)N_NODES * HID];       // act bf16 hi
__device__ __nv_bfloat16 g_Al[(size_t)N_NODES * HID];       // act bf16 lo (h2 only)
__device__ __nv_bfloat16 g_Ch[(size_t)N_NODES * HID];       // act bf16 hi (pair 1)
__device__ __nv_bfloat16 g_Wh[(size_t)HID * HID];           // weight^T split hi
__device__ __nv_bfloat16 g_Wl[(size_t)HID * HID];           // weight^T split lo
__device__ float g_bfcPad[128];                             // padded classifier bias
__device__ int   g_edges[2 * N_EDGES];
__device__ int   g_idx64;

// ---------------------------------------------------------------------------
// PTX helpers (all sm_80-era: valid under compute_103, no 'a' features)
// ---------------------------------------------------------------------------
__device__ __forceinline__ uint32_t s2u(const void* p) {
    uint32_t a;
    asm("{ .reg .u64 t; cvta.to.shared.u64 t, %1; cvt.u32.u64 %0, t; }"
        : "=r"(a) : "l"(p));
    return a;
}

__device__ __forceinline__ void cp_async16(uint32_t s, const void* g, unsigned sz) {
    asm volatile("cp.async.cg.shared.global [%0], [%1], 16, %2;"
                 :: "r"(s), "l"(g), "r"(sz));
}

__device__ __forceinline__ void ldsm4(uint32_t* r, uint32_t addr) {
    asm volatile("ldmatrix.sync.aligned.m8n8.x4.shared.b16 {%0,%1,%2,%3}, [%4];"
                 : "=r"(r[0]), "=r"(r[1]), "=r"(r[2]), "=r"(r[3]) : "r"(addr));
}

__device__ __forceinline__ void mma_bf16(float* d, const uint32_t* a,
                                         const uint32_t* b) {
    asm volatile(
        "mma.sync.aligned.m16n8k16.row.col.f32.bf16.bf16.f32 "
        "{%0,%1,%2,%3},{%4,%5,%6,%7},{%8,%9},{%0,%1,%2,%3};"
        : "+f"(d[0]), "+f"(d[1]), "+f"(d[2]), "+f"(d[3])
        : "r"(a[0]), "r"(a[1]), "r"(a[2]), "r"(a[3]), "r"(b[0]), "r"(b[1]));
}

// ---------------------------------------------------------------------------
// Edge-index dtype detection + normalization
// ---------------------------------------------------------------------------
__global__ void detect_idx_kernel(const unsigned int* __restrict__ ei) {
    unsigned v = ei[2 * threadIdx.x + 1];
    int any = __syncthreads_or(v != 0u);
    if (threadIdx.x == 0) g_idx64 = any ? 0 : 1;
}

__global__ void convert_idx_kernel(const unsigned int* __restrict__ ei) {
    int i = blockIdx.x * blockDim.x + threadIdx.x;
    if (i < 2 * N_EDGES) g_edges[i] = g_idx64 ? (int)ei[2 * i] : (int)ei[i];
}

// ---------------------------------------------------------------------------
// float4 copy
// ---------------------------------------------------------------------------
__global__ void copy_f4_kernel(const float4* __restrict__ src,
                               float4* __restrict__ dst, long n) {
    long i = (long)blockIdx.x * blockDim.x + threadIdx.x;
    if (i < n) dst[i] = src[i];
}

// ---------------------------------------------------------------------------
// Scatter-add aggregation: buf[dst] += feat[src]
// ---------------------------------------------------------------------------
template <int D4>
__global__ void scatter_add_kernel(const float4* __restrict__ feat,
                                   float* __restrict__ buf) {
    long idx = (long)blockIdx.x * blockDim.x + threadIdx.x;
    if (idx >= (long)N_EDGES * D4) return;
    int e = (int)(idx / D4);
    int d = (int)(idx % D4);
    int s = g_edges[e];
    int t = g_edges[N_EDGES + e];
    float4 v = feat[(size_t)s * D4 + d];
    float* p = buf + ((size_t)t * D4 + d) * 4;
    atomicAdd(p + 0, v.x);
    atomicAdd(p + 1, v.y);
    atomicAdd(p + 2, v.z);
    atomicAdd(p + 3, v.w);
}

// ---------------------------------------------------------------------------
// fp32 -> bf16 convert (activations; hi part only)
// ---------------------------------------------------------------------------
__global__ void convert_act_kernel(const float4* __restrict__ X,
                                   __nv_bfloat162* __restrict__ Th, long n4) {
    long i = (long)blockIdx.x * blockDim.x + threadIdx.x;
    if (i >= n4) return;
    float4 v = X[i];
    Th[2 * i]     = __nv_bfloat162(__float2bfloat16(v.x), __float2bfloat16(v.y));
    Th[2 * i + 1] = __nv_bfloat162(__float2bfloat16(v.z), __float2bfloat16(v.w));
}

// ---------------------------------------------------------------------------
// Weight W[K,N] fp32 -> transposed split Wt[Npad,K] bf16 hi/lo (zero-pad rows)
// ---------------------------------------------------------------------------
__global__ void split_weightT_kernel(const float* __restrict__ W,
                                     __nv_bfloat16* __restrict__ Th,
                                     __nv_bfloat16* __restrict__ Tl,
                                     int Kd, int Nd, int Npad) {
    int idx = blockIdx.x * blockDim.x + threadIdx.x;
    if (idx >= Kd * Npad) return;
    int n = idx / Kd;
    int k = idx % Kd;
    float v = (n < Nd) ? W[(size_t)k * Nd + n] : 0.0f;
    __nv_bfloat16 h = __float2bfloat16(v);
    Th[idx] = h;
    Tl[idx] = __float2bfloat16(v - __bfloat162float(h));
}

__global__ void pad_bias_kernel(const float* __restrict__ b, int n) {
    int i = threadIdx.x;
    if (i < 128) g_bfcPad[i] = (i < n) ? b[i] : 0.0f;
}

// ---------------------------------------------------------------------------
// bf16 split-compensated mma.sync GEMM:
//   C[M, ncols] = act(A[M,K] @ W[K,ncols] + bias)
// TERMS=2: A bf16 (Ah only); products AhBh + AhBl (W split to ~2^-16).
// TERMS=3: A split too; adds AlBh.
// BM=128, BN=128, BK=64. 256 threads = 2x4 warps (64x32 per warp).
// 3-stage cp.async pipeline; SW128-swizzled SMEM; double-buffered ldsm frags.
// OUT: 0 = fp32 to C (stride ostride, col guard); 1 = bf16 hi+lo; 2 = bf16 hi.
// ---------------------------------------------------------------------------
template <int K, int TERMS>
__device__ __forceinline__ void load_stage(uint32_t tbase, int stage,
    const __nv_bfloat16* __restrict__ Ah, const __nv_bfloat16* __restrict__ Al,
    const __nv_bfloat16* __restrict__ Bh, const __nv_bfloat16* __restrict__ Bl,
    int chunk, int rowBase, int colBase, int M) {
    const int tid = threadIdx.x;
    const uint32_t sBase = tbase + (uint32_t)stage * 65536u;
    const long kOff = (long)chunk * 64;
#pragma unroll
    for (int i = 0; i < 4; ++i) {
        int t = i * 256 + tid;            // 0..1023 16B chunks per 16KB tile
        int r = t >> 3;
        int cc = t & 7;
        uint32_t sw = (uint32_t)(r * 128 + ((cc ^ (r & 7)) << 4));
        int gr = rowBase + r;
        unsigned sz = (gr < M) ? 16u : 0u;
        int ga = gr < M ? gr : (M - 1);
        size_t aoff = ((size_t)ga * K + kOff + cc * 8) * 2;  // bytes
        cp_async16(sBase + sw, (const char*)Ah + aoff, sz);
        if (TERMS == 3)
            cp_async16(sBase + 16384u + sw, (const char*)Al + aoff, sz);
        int gn = colBase + r;
        size_t boff = ((size_t)gn * K + kOff + cc * 8) * 2;
        cp_async16(sBase + 32768u + sw, (const char*)Bh + boff, 16u);
        cp_async16(sBase + 49152u + sw, (const char*)Bl + boff, 16u);
    }
}

struct Frags {
    uint32_t ah[4][4];
    uint32_t al[4][4];
    uint32_t bh[2][4];
    uint32_t bl[2][4];
};

template <int TERMS>
__device__ __forceinline__ void load_frags(uint32_t st, int k,
                                           const int* arow, const int* brow,
                                           int a_ck, int b_ck, Frags& f) {
    const uint32_t aHi = st, aLo = st + 16384u;
    const uint32_t bHi = st + 32768u, bLo = st + 49152u;
#pragma unroll
    for (int fm = 0; fm < 4; ++fm) {
        int row = arow[fm];
        int ck = k * 2 + a_ck;
        uint32_t off = (uint32_t)(row * 128 + ((ck ^ (row & 7)) << 4));
        ldsm4(f.ah[fm], aHi + off);
        if (TERMS == 3) ldsm4(f.al[fm], aLo + off);
    }
#pragma unroll
    for (int f2 = 0; f2 < 2; ++f2) {
        int row = brow[f2];
        int ck = k * 2 + b_ck;
        uint32_t off = (uint32_t)(row * 128 + ((ck ^ (row & 7)) << 4));
        ldsm4(f.bh[f2], bHi + off);
        ldsm4(f.bl[f2], bLo + off);
    }
}

template <int TERMS>
__device__ __forceinline__ void mma_frags(const Frags& f, float acc[4][4][4]) {
#pragma unroll
    for (int fm = 0; fm < 4; ++fm)
#pragma unroll
        for (int fn = 0; fn < 4; ++fn) {
            const uint32_t* pbh = &f.bh[fn >> 1][(fn & 1) * 2];
            const uint32_t* pbl = &f.bl[fn >> 1][(fn & 1) * 2];
            mma_bf16(acc[fm][fn], f.ah[fm], pbh);              // Ah*Bh
            mma_bf16(acc[fm][fn], f.ah[fm], pbl);              // Ah*Bl
            if (TERMS == 3) mma_bf16(acc[fm][fn], f.al[fm], pbh);  // Al*Bh
        }
}

template <int K, bool RELU, int OUT, int TERMS>
__global__ void __launch_bounds__(256)
gemm_bf16s_mma_kernel(const __nv_bfloat16* __restrict__ Ah,
                      const __nv_bfloat16* __restrict__ Al,
                      const __nv_bfloat16* __restrict__ Bh,
                      const __nv_bfloat16* __restrict__ Bl,
                      const float* __restrict__ bias,
                      float* __restrict__ C,
                      __nv_bfloat162* __restrict__ Oh,
                      __nv_bfloat162* __restrict__ Ol,
                      int M, int ostride, int ncols) {
    constexpr int NC = K / 64;
    extern __shared__ char smem[];
    const uint32_t tile_base = (s2u(smem) + 1023u) & ~1023u;

    const int tid = threadIdx.x;
    const int wid = tid >> 5;
    const int lane = tid & 31;
    const int wm = wid >> 2;          // 0..1
    const int wn = wid & 3;           // 0..3
    const int rowBase = blockIdx.y * 128;
    const int colBase = blockIdx.x * 128;

    const int midx = lane >> 3;
    const int l7 = lane & 7;
    const int a_ck = (midx >> 1);
    const int b_ck = (midx & 1);
    int arow[4], brow[2];
#pragma unroll
    for (int fm = 0; fm < 4; ++fm)
        arow[fm] = wm * 64 + fm * 16 + ((midx & 1) << 3) + l7;
#pragma unroll
    for (int f2 = 0; f2 < 2; ++f2)
        brow[f2] = wn * 32 + f2 * 16 + ((midx >> 1) << 3) + l7;

    float acc[4][4][4];
#pragma unroll
    for (int i = 0; i < 4; i++)
#pragma unroll
        for (int j = 0; j < 4; j++)
#pragma unroll
            for (int q = 0; q < 4; q++) acc[i][j][q] = 0.0f;

    // Prologue: prefetch chunks 0, 1
    load_stage<K, TERMS>(tile_base, 0, Ah, Al, Bh, Bl, 0, rowBase, colBase, M);
    asm volatile("cp.async.commit_group;" ::: "memory");
    load_stage<K, TERMS>(tile_base, 1, Ah, Al, Bh, Bl, 1, rowBase, colBase, M);
    asm volatile("cp.async.commit_group;" ::: "memory");

    Frags fr[2];
    for (int c = 0; c < NC; ++c) {
        if (c + 1 < NC) asm volatile("cp.async.wait_group 1;" ::: "memory");
        else            asm volatile("cp.async.wait_group 0;" ::: "memory");
        __syncthreads();
        const uint32_t st = tile_base + (uint32_t)(c % 3) * 65536u;
        load_frags<TERMS>(st, 0, arow, brow, a_ck, b_ck, fr[0]);
        if (c + 2 < NC) {
            load_stage<K, TERMS>(tile_base, (c + 2) % 3, Ah, Al, Bh, Bl,
                                 c + 2, rowBase, colBase, M);
            asm volatile("cp.async.commit_group;" ::: "memory");
        }
#pragma unroll
        for (int k = 0; k < 4; ++k) {
            if (k < 3)
                load_frags<TERMS>(st, k + 1, arow, brow, a_ck, b_ck, fr[(k + 1) & 1]);
            mma_frags<TERMS>(fr[k & 1], acc);
        }
    }

    // Epilogue: bias (+relu); fp32 strided / bf16 hi+lo / bf16 hi
    const int rowb = rowBase + wm * 64 + (lane >> 2);
    const int colb = colBase + wn * 32;
#pragma unroll
    for (int fm = 0; fm < 4; ++fm) {
        int r0 = rowb + fm * 16;
        int r1 = r0 + 8;
#pragma unroll
        for (int fn = 0; fn < 4; ++fn) {
            int col = colb + fn * 8 + (lane & 3) * 2;
            float2 bp = *reinterpret_cast<const float2*>(&bias[col]);
            float v0 = acc[fm][fn][0] + bp.x;
            float v1 = acc[fm][fn][1] + bp.y;
            float v2 = acc[fm][fn][2] + bp.x;
            float v3 = acc[fm][fn][3] + bp.y;
            if (RELU) {
                v0 = fmaxf(v0, 0.f); v1 = fmaxf(v1, 0.f);
                v2 = fmaxf(v2, 0.f); v3 = fmaxf(v3, 0.f);
            }
            if (OUT == 0) {
                if (col < ncols) {
                    if (r0 < M)
                        *reinterpret_cast<float2*>(&C[(size_t)r0 * ostride + col]) =
                            make_float2(v0, v1);
                    if (r1 < M)
                        *reinterpret_cast<float2*>(&C[(size_t)r1 * ostride + col]) =
                            make_float2(v2, v3);
                }
            } else {
                if (r0 < M) {
                    size_t h = ((size_t)r0 * ostride + col) >> 1;
                    __nv_bfloat16 h0 = __float2bfloat16(v0);
                    __nv_bfloat16 h1 = __float2bfloat16(v1);
                    Oh[h] = __nv_bfloat162(h0, h1);
                    if (OUT == 1)
                        Ol[h] = __nv_bfloat162(
                            __float2bfloat16(v0 - __bfloat162float(h0)),
                            __float2bfloat16(v1 - __bfloat162float(h1)));
                }
                if (r1 < M) {
                    size_t h = ((size_t)r1 * ostride + col) >> 1;
                    __nv_bfloat16 h2 = __float2bfloat16(v2);
                    __nv_bfloat16 h3 = __float2bfloat16(v3);
                    Oh[h] = __nv_bfloat162(h2, h3);
                    if (OUT == 1)
                        Ol[h] = __nv_bfloat162(
                            __float2bfloat16(v2 - __bfloat162float(h2)),
                            __float2bfloat16(v3 - __bfloat162float(h3)));
                }
            }
        }
    }
}

// ---------------------------------------------------------------------------
// In-place log_softmax over 64 classes, one warp per row
// ---------------------------------------------------------------------------
__global__ void log_softmax64_kernel(float* __restrict__ out, int M) {
    int warp = (blockIdx.x * blockDim.x + threadIdx.x) >> 5;
    int lane = threadIdx.x & 31;
    if (warp >= M) return;
    float* row = out + (size_t)warp * N_CLS;
    float a = row[lane];
    float b = row[lane + 32];
    float m = fmaxf(a, b);
#pragma unroll
    for (int o = 16; o > 0; o >>= 1)
        m = fmaxf(m, __shfl_xor_sync(0xFFFFFFFFu, m, o));
    float s = expf(a - m) + expf(b - m);
#pragma unroll
    for (int o = 16; o > 0; o >>= 1)
        s += __shfl_xor_sync(0xFFFFFFFFu, s, o);
    float lse = m + logf(s);
    row[lane]      = a - lse;
    row[lane + 32] = b - lse;
}

// ---------------------------------------------------------------------------
// Launch
// ---------------------------------------------------------------------------
extern "C" void kernel_launch(void* const* d_in, const int* in_sizes, int n_in,
                              void* d_out, int out_size) {
    const float*        x   = (const float*)d_in[0];
    const unsigned int* ei  = (const unsigned int*)d_in[1];
    const float* W1a = (const float*)d_in[2];
    const float* b1a = (const float*)d_in[3];
    const float* W1b = (const float*)d_in[4];
    const float* b1b = (const float*)d_in[5];
    const float* W2a = (const float*)d_in[6];
    const float* b2a = (const float*)d_in[7];
    const float* W2b = (const float*)d_in[8];
    const float* b2b = (const float*)d_in[9];
    const float* Wfc = (const float*)d_in[10];
    const float* bfc = (const float*)d_in[11];
    float* out = (float*)d_out;

    float *buf256, *bufA, *bufB, *bfcPad;
    __nv_bfloat16 *Ah, *Al, *Ch, *Wh, *Wl;
    cudaGetSymbolAddress((void**)&buf256, g_buf256);
    cudaGetSymbolAddress((void**)&bufA, g_bufA);
    cudaGetSymbolAddress((void**)&bufB, g_bufB);
    cudaGetSymbolAddress((void**)&Ah, g_Ah);
    cudaGetSymbolAddress((void**)&Al, g_Al);
    cudaGetSymbolAddress((void**)&Ch, g_Ch);
    cudaGetSymbolAddress((void**)&Wh, g_Wh);
    cudaGetSymbolAddress((void**)&Wl, g_Wl);
    cudaGetSymbolAddress((void**)&bfcPad, g_bfcPad);

    const int GEMM_SMEM = 3 * 65536 + 1024;  // 197632 B (3-stage + align slack)
    cudaFuncSetAttribute(gemm_bf16s_mma_kernel<256, true, 2, 2>,
                         cudaFuncAttributeMaxDynamicSharedMemorySize, GEMM_SMEM);
    cudaFuncSetAttribute(gemm_bf16s_mma_kernel<1024, true, 0, 2>,
                         cudaFuncAttributeMaxDynamicSharedMemorySize, GEMM_SMEM);
    cudaFuncSetAttribute(gemm_bf16s_mma_kernel<1024, true, 2, 2>,
                         cudaFuncAttributeMaxDynamicSharedMemorySize, GEMM_SMEM);
    cudaFuncSetAttribute(gemm_bf16s_mma_kernel<1024, false, 1, 2>,
                         cudaFuncAttributeMaxDynamicSharedMemorySize, GEMM_SMEM);
    cudaFuncSetAttribute(gemm_bf16s_mma_kernel<1024, false, 0, 3>,
                         cudaFuncAttributeMaxDynamicSharedMemorySize, GEMM_SMEM);

    // Edge index normalization
    detect_idx_kernel<<<1, 256>>>(ei);
    convert_idx_kernel<<<(2 * N_EDGES + 255) / 256, 256>>>(ei);

    dim3 gridGemm(HID / 128, (N_NODES + 127) / 128);   // (8, 782)
    dim3 gridFC(1, (N_NODES + 127) / 128);

    // ---- Layer 1 aggregation: buf256 = x + segsum(x[src] -> dst) ----
    {
        long n4 = (long)N_NODES * (D_IN / 4);
        copy_f4_kernel<<<(int)((n4 + 255) / 256), 256>>>(
            (const float4*)x, (float4*)buf256, n4);
        long work = (long)N_EDGES * (D_IN / 4);
        scatter_add_kernel<D_IN / 4><<<(int)((work + 255) / 256), 256>>>(
            (const float4*)x, buf256);
    }
    // GEMM1a: Ch = bf16(relu(buf256 @ W1a + b1a))
    {
        long n4 = (long)N_NODES * (D_IN / 4);
        convert_act_kernel<<<(int)((n4 + 255) / 256), 256>>>(
            (const float4*)buf256, (__nv_bfloat162*)Ah, n4);
        split_weightT_kernel<<<(D_IN * HID + 255) / 256, 256>>>(
            W1a, Wh, Wl, D_IN, HID, HID);
        gemm_bf16s_mma_kernel<256, true, 2, 2><<<gridGemm, 256, GEMM_SMEM>>>(
            Ah, nullptr, Wh, Wl, b1a, nullptr,
            (__nv_bfloat162*)Ch, nullptr, N_NODES, HID, HID);
    }
    // GEMM1b: bufB = relu(Ch @ W1b + b1b) = h1   (outer relu fused)
    {
        split_weightT_kernel<<<(HID * HID + 255) / 256, 256>>>(
            W1b, Wh, Wl, HID, HID, HID);
        gemm_bf16s_mma_kernel<1024, true, 0, 2><<<gridGemm, 256, GEMM_SMEM>>>(
            Ch, nullptr, Wh, Wl, b1b, bufB, nullptr, nullptr, N_NODES, HID, HID);
    }
    // ---- Layer 2 aggregation: bufA = h1 + segsum(h1[src] -> dst) ----
    {
        long n4 = (long)N_NODES * (HID / 4);
        copy_f4_kernel<<<(int)((n4 + 255) / 256), 256>>>(
            (const float4*)bufB, (float4*)bufA, n4);
        long work = (long)N_EDGES * (HID / 4);
        scatter_add_kernel<HID / 4><<<(int)((work + 255) / 256), 256>>>(
            (const float4*)bufB, bufA);
    }
    // GEMM2a: Ch = bf16(relu(bufA @ W2a + b2a))
    {
        long n4 = (long)N_NODES * (HID / 4);
        convert_act_kernel<<<(int)((n4 + 255) / 256), 256>>>(
            (const float4*)bufA, (__nv_bfloat162*)Ah, n4);
        split_weightT_kernel<<<(HID * HID + 255) / 256, 256>>>(
            W2a, Wh, Wl, HID, HID, HID);
        gemm_bf16s_mma_kernel<1024, true, 2, 2><<<gridGemm, 256, GEMM_SMEM>>>(
            Ah, nullptr, Wh, Wl, b2a, nullptr,
            (__nv_bfloat162*)Ch, nullptr, N_NODES, HID, HID);
    }
    // GEMM2b: Ah/Al = split(Ch @ W2b + b2b) = h2 (split: feeds 3-term classifier)
    {
        split_weightT_kernel<<<(HID * HID + 255) / 256, 256>>>(
            W2b, Wh, Wl, HID, HID, HID);
        gemm_bf16s_mma_kernel<1024, false, 1, 2><<<gridGemm, 256, GEMM_SMEM>>>(
            Ch, nullptr, Wh, Wl, b2b, nullptr,
            (__nv_bfloat162*)Ah, (__nv_bfloat162*)Al, N_NODES, HID, HID);
    }
    // ---- Classifier (3-term, N padded 64->128) + log_softmax ----
    {
        pad_bias_kernel<<<1, 128>>>(bfc, N_CLS);
        split_weightT_kernel<<<(HID * 128 + 255) / 256, 256>>>(
            Wfc, Wh, Wl, HID, N_CLS, 128);
        gemm_bf16s_mma_kernel<1024, false, 0, 3><<<gridFC, 256, GEMM_SMEM>>>(
            Ah, Al, Wh, Wl, bfcPad, out, nullptr, nullptr, N_NODES, N_CLS, N_CLS);
    }
    log_softmax64_kernel<<<(N_NODES * 32 + 255) / 256, 256>>>(out, N_NODES);
}

// round 11
// speedup vs baseline: 4.1246x; 1.2704x over previous
#include <cuda_runtime.h>
#include <cuda_bf16.h>
#include <math.h>
#include <stdint.h>

// Problem constants (fixed by the reference)
#define N_NODES  100000
#define N_EDGES  300000
#define D_IN     256
#define HID      1024
#define N_CLS    64

// ---------------------------------------------------------------------------
// Scratch (device globals: allocation-free)
// ---------------------------------------------------------------------------
__device__ __nv_bfloat16 g_Ah[(size_t)N_NODES * HID];       // act bf16 ping
__device__ __nv_bfloat16 g_Ch[(size_t)N_NODES * HID];       // act bf16 pong
__device__ __nv_bfloat16 g_Al[(size_t)N_NODES * HID];       // h2 lo residual
__device__ __nv_bfloat16 g_Wh[(size_t)HID * HID];           // weight^T split hi
__device__ __nv_bfloat16 g_Wl[(size_t)HID * HID];           // weight^T split lo
__device__ float g_bfcPad[128];                             // padded classifier bias
__device__ int   g_edges[2 * N_EDGES];
__device__ int   g_idx64;
// CSR scratch
__device__ int g_deg[N_NODES];
__device__ int g_incl[N_NODES];
__device__ int g_ptr[N_NODES];
__device__ int g_cursor[N_NODES];
__device__ int g_blockSums[128];
__device__ int g_csr_idx[N_EDGES];

// ---------------------------------------------------------------------------
// PTX helpers (all sm_80-era: valid under compute_103, no 'a' features)
// ---------------------------------------------------------------------------
__device__ __forceinline__ uint32_t s2u(const void* p) {
    uint32_t a;
    asm("{ .reg .u64 t; cvta.to.shared.u64 t, %1; cvt.u32.u64 %0, t; }"
        : "=r"(a) : "l"(p));
    return a;
}

__device__ __forceinline__ void cp_async16(uint32_t s, const void* g, unsigned sz) {
    asm volatile("cp.async.cg.shared.global [%0], [%1], 16, %2;"
                 :: "r"(s), "l"(g), "r"(sz));
}

__device__ __forceinline__ void ldsm4(uint32_t* r, uint32_t addr) {
    asm volatile("ldmatrix.sync.aligned.m8n8.x4.shared.b16 {%0,%1,%2,%3}, [%4];"
                 : "=r"(r[0]), "=r"(r[1]), "=r"(r[2]), "=r"(r[3]) : "r"(addr));
}

__device__ __forceinline__ void mma_bf16(float* d, const uint32_t* a,
                                         const uint32_t* b) {
    asm volatile(
        "mma.sync.aligned.m16n8k16.row.col.f32.bf16.bf16.f32 "
        "{%0,%1,%2,%3},{%4,%5,%6,%7},{%8,%9},{%0,%1,%2,%3};"
        : "+f"(d[0]), "+f"(d[1]), "+f"(d[2]), "+f"(d[3])
        : "r"(a[0]), "r"(a[1]), "r"(a[2]), "r"(a[3]), "r"(b[0]), "r"(b[1]));
}

// ---------------------------------------------------------------------------
// Edge-index dtype detection + normalization
// ---------------------------------------------------------------------------
__global__ void detect_idx_kernel(const unsigned int* __restrict__ ei) {
    unsigned v = ei[2 * threadIdx.x + 1];
    int any = __syncthreads_or(v != 0u);
    if (threadIdx.x == 0) g_idx64 = any ? 0 : 1;
}

__global__ void convert_idx_kernel(const unsigned int* __restrict__ ei) {
    int i = blockIdx.x * blockDim.x + threadIdx.x;
    if (i < 2 * N_EDGES) g_edges[i] = g_idx64 ? (int)ei[2 * i] : (int)ei[i];
}

// ---------------------------------------------------------------------------
// CSR build: degree count -> block scan -> ptr -> atomic-slot fill
// ---------------------------------------------------------------------------
__global__ void zero_csr_kernel() {
    int i = blockIdx.x * blockDim.x + threadIdx.x;
    if (i < N_NODES) { g_deg[i] = 0; g_cursor[i] = 0; }
}

__global__ void count_deg_kernel() {
    int e = blockIdx.x * blockDim.x + threadIdx.x;
    if (e < N_EDGES) atomicAdd(&g_deg[g_edges[N_EDGES + e]], 1);
}

__global__ void scan_block_kernel() {
    __shared__ int s[1024];
    int g = blockIdx.x * 1024 + threadIdx.x;
    int v = (g < N_NODES) ? g_deg[g] : 0;
    s[threadIdx.x] = v;
    __syncthreads();
#pragma unroll
    for (int off = 1; off < 1024; off <<= 1) {
        int t = (threadIdx.x >= off) ? s[threadIdx.x - off] : 0;
        __syncthreads();
        s[threadIdx.x] += t;
        __syncthreads();
    }
    if (g < N_NODES) g_incl[g] = s[threadIdx.x];
    if (threadIdx.x == 1023) g_blockSums[blockIdx.x] = s[1023];
}

__global__ void scan_sums_kernel(int nb) {
    if (threadIdx.x == 0) {
        int run = 0;
        for (int i = 0; i < nb; i++) { int t = g_blockSums[i]; g_blockSums[i] = run; run += t; }
    }
}

__global__ void finalize_ptr_kernel() {
    int g = blockIdx.x * blockDim.x + threadIdx.x;
    if (g < N_NODES) g_ptr[g] = g_incl[g] - g_deg[g] + g_blockSums[g >> 10];
}

__global__ void fill_csr_kernel() {
    int e = blockIdx.x * blockDim.x + threadIdx.x;
    if (e < N_EDGES) {
        int s = g_edges[e];
        int d = g_edges[N_EDGES + e];
        int slot = atomicAdd(&g_cursor[d], 1);
        g_csr_idx[g_ptr[d] + slot] = s;
    }
}

// ---------------------------------------------------------------------------
// Gather aggregation, layer 1: O[i] = bf16(x[i] + sum_j x[j]), D=256 fp32 in
// One block (128 threads) per node; thread t owns features 2t, 2t+1.
// ---------------------------------------------------------------------------
__global__ void __launch_bounds__(128)
gather_x_kernel(const float2* __restrict__ X, __nv_bfloat162* __restrict__ O) {
    int node = blockIdx.x;
    int t = threadIdx.x;
    float2 a = X[(size_t)node * 128 + t];
    int st = g_ptr[node];
    int de = g_deg[node];
    for (int q = 0; q < de; q++) {
        int j = g_csr_idx[st + q];
        float2 v = X[(size_t)j * 128 + t];
        a.x += v.x;
        a.y += v.y;
    }
    O[(size_t)node * 128 + t] = __nv_bfloat162(__float2bfloat16(a.x),
                                               __float2bfloat16(a.y));
}

// ---------------------------------------------------------------------------
// Gather aggregation, layer 2: O[i] = bf16(H[i] + sum_j H[j]), D=1024 bf16 in
// One block (128 threads) per node; thread t owns 8 bf16 (one uint4).
// ---------------------------------------------------------------------------
__global__ void __launch_bounds__(128)
gather_h_kernel(const uint4* __restrict__ H, uint4* __restrict__ O) {
    int node = blockIdx.x;
    int t = threadIdx.x;
    uint4 sv = H[(size_t)node * 128 + t];
    float acc[8];
    {
        float2 p0 = __bfloat1622float2(*(__nv_bfloat162*)&sv.x);
        float2 p1 = __bfloat1622float2(*(__nv_bfloat162*)&sv.y);
        float2 p2 = __bfloat1622float2(*(__nv_bfloat162*)&sv.z);
        float2 p3 = __bfloat1622float2(*(__nv_bfloat162*)&sv.w);
        acc[0] = p0.x; acc[1] = p0.y; acc[2] = p1.x; acc[3] = p1.y;
        acc[4] = p2.x; acc[5] = p2.y; acc[6] = p3.x; acc[7] = p3.y;
    }
    int st = g_ptr[node];
    int de = g_deg[node];
    for (int q = 0; q < de; q++) {
        int j = g_csr_idx[st + q];
        uint4 v = H[(size_t)j * 128 + t];
        float2 p0 = __bfloat1622float2(*(__nv_bfloat162*)&v.x);
        float2 p1 = __bfloat1622float2(*(__nv_bfloat162*)&v.y);
        float2 p2 = __bfloat1622float2(*(__nv_bfloat162*)&v.z);
        float2 p3 = __bfloat1622float2(*(__nv_bfloat162*)&v.w);
        acc[0] += p0.x; acc[1] += p0.y; acc[2] += p1.x; acc[3] += p1.y;
        acc[4] += p2.x; acc[5] += p2.y; acc[6] += p3.x; acc[7] += p3.y;
    }
    uint4 o;
    *(__nv_bfloat162*)&o.x = __nv_bfloat162(__float2bfloat16(acc[0]), __float2bfloat16(acc[1]));
    *(__nv_bfloat162*)&o.y = __nv_bfloat162(__float2bfloat16(acc[2]), __float2bfloat16(acc[3]));
    *(__nv_bfloat162*)&o.z = __nv_bfloat162(__float2bfloat16(acc[4]), __float2bfloat16(acc[5]));
    *(__nv_bfloat162*)&o.w = __nv_bfloat162(__float2bfloat16(acc[6]), __float2bfloat16(acc[7]));
    O[(size_t)node * 128 + t] = o;
}

// ---------------------------------------------------------------------------
// Weight W[K,N] fp32 -> transposed split Wt[Npad,K] bf16 hi/lo (zero-pad rows)
// ---------------------------------------------------------------------------
__global__ void split_weightT_kernel(const float* __restrict__ W,
                                     __nv_bfloat16* __restrict__ Th,
                                     __nv_bfloat16* __restrict__ Tl,
                                     int Kd, int Nd, int Npad) {
    int idx = blockIdx.x * blockDim.x + threadIdx.x;
    if (idx >= Kd * Npad) return;
    int n = idx / Kd;
    int k = idx % Kd;
    float v = (n < Nd) ? W[(size_t)k * Nd + n] : 0.0f;
    __nv_bfloat16 h = __float2bfloat16(v);
    Th[idx] = h;
    Tl[idx] = __float2bfloat16(v - __bfloat162float(h));
}

__global__ void pad_bias_kernel(const float* __restrict__ b, int n) {
    int i = threadIdx.x;
    if (i < 128) g_bfcPad[i] = (i < n) ? b[i] : 0.0f;
}

// ---------------------------------------------------------------------------
// bf16 split-compensated mma.sync GEMM:
//   C[M, ncols] = act(A[M,K] @ W[K,ncols] + bias)
// TERMS=2: A bf16 (Ah only); products AhBh + AhBl (W split to ~2^-16).
// TERMS=3: A split too; adds AlBh.
// BM=128, BN=128, BK=64. 256 threads = 2x4 warps (64x32 per warp).
// 3-stage cp.async pipeline; SW128-swizzled SMEM; double-buffered ldsm frags.
// OUT: 0 = fp32 to C (stride ostride, col guard); 1 = bf16 hi+lo; 2 = bf16 hi.
// ---------------------------------------------------------------------------
template <int K, int TERMS>
__device__ __forceinline__ void load_stage(uint32_t tbase, int stage,
    const __nv_bfloat16* __restrict__ Ah, const __nv_bfloat16* __restrict__ Al,
    const __nv_bfloat16* __restrict__ Bh, const __nv_bfloat16* __restrict__ Bl,
    int chunk, int rowBase, int colBase, int M) {
    const int tid = threadIdx.x;
    const uint32_t sBase = tbase + (uint32_t)stage * 65536u;
    const long kOff = (long)chunk * 64;
#pragma unroll
    for (int i = 0; i < 4; ++i) {
        int t = i * 256 + tid;            // 0..1023 16B chunks per 16KB tile
        int r = t >> 3;
        int cc = t & 7;
        uint32_t sw = (uint32_t)(r * 128 + ((cc ^ (r & 7)) << 4));
        int gr = rowBase + r;
        unsigned sz = (gr < M) ? 16u : 0u;
        int ga = gr < M ? gr : (M - 1);
        size_t aoff = ((size_t)ga * K + kOff + cc * 8) * 2;  // bytes
        cp_async16(sBase + sw, (const char*)Ah + aoff, sz);
        if (TERMS == 3)
            cp_async16(sBase + 16384u + sw, (const char*)Al + aoff, sz);
        int gn = colBase + r;
        size_t boff = ((size_t)gn * K + kOff + cc * 8) * 2;
        cp_async16(sBase + 32768u + sw, (const char*)Bh + boff, 16u);
        cp_async16(sBase + 49152u + sw, (const char*)Bl + boff, 16u);
    }
}

struct Frags {
    uint32_t ah[4][4];
    uint32_t al[4][4];
    uint32_t bh[2][4];
    uint32_t bl[2][4];
};

template <int TERMS>
__device__ __forceinline__ void load_frags(uint32_t st, int k,
                                           const int* arow, const int* brow,
                                           int a_ck, int b_ck, Frags& f) {
    const uint32_t aHi = st, aLo = st + 16384u;
    const uint32_t bHi = st + 32768u, bLo = st + 49152u;
#pragma unroll
    for (int fm = 0; fm < 4; ++fm) {
        int row = arow[fm];
        int ck = k * 2 + a_ck;
        uint32_t off = (uint32_t)(row * 128 + ((ck ^ (row & 7)) << 4));
        ldsm4(f.ah[fm], aHi + off);
        if (TERMS == 3) ldsm4(f.al[fm], aLo + off);
    }
#pragma unroll
    for (int f2 = 0; f2 < 2; ++f2) {
        int row = brow[f2];
        int ck = k * 2 + b_ck;
        uint32_t off = (uint32_t)(row * 128 + ((ck ^ (row & 7)) << 4));
        ldsm4(f.bh[f2], bHi + off);
        ldsm4(f.bl[f2], bLo + off);
    }
}

template <int TERMS>
__device__ __forceinline__ void mma_frags(const Frags& f, float acc[4][4][4]) {
#pragma unroll
    for (int fm = 0; fm < 4; ++fm)
#pragma unroll
        for (int fn = 0; fn < 4; ++fn) {
            const uint32_t* pbh = &f.bh[fn >> 1][(fn & 1) * 2];
            const uint32_t* pbl = &f.bl[fn >> 1][(fn & 1) * 2];
            mma_bf16(acc[fm][fn], f.ah[fm], pbh);              // Ah*Bh
            mma_bf16(acc[fm][fn], f.ah[fm], pbl);              // Ah*Bl
            if (TERMS == 3) mma_bf16(acc[fm][fn], f.al[fm], pbh);  // Al*Bh
        }
}

template <int K, bool RELU, int OUT, int TERMS>
__global__ void __launch_bounds__(256)
gemm_bf16s_mma_kernel(const __nv_bfloat16* __restrict__ Ah,
                      const __nv_bfloat16* __restrict__ Al,
                      const __nv_bfloat16* __restrict__ Bh,
                      const __nv_bfloat16* __restrict__ Bl,
                      const float* __restrict__ bias,
                      float* __restrict__ C,
                      __nv_bfloat162* __restrict__ Oh,
                      __nv_bfloat162* __restrict__ Ol,
                      int M, int ostride, int ncols) {
    constexpr int NC = K / 64;
    extern __shared__ char smem[];
    const uint32_t tile_base = (s2u(smem) + 1023u) & ~1023u;

    const int tid = threadIdx.x;
    const int wid = tid >> 5;
    const int lane = tid & 31;
    const int wm = wid >> 2;          // 0..1
    const int wn = wid & 3;           // 0..3
    const int rowBase = blockIdx.y * 128;
    const int colBase = blockIdx.x * 128;

    const int midx = lane >> 3;
    const int l7 = lane & 7;
    const int a_ck = (midx >> 1);
    const int b_ck = (midx & 1);
    int arow[4], brow[2];
#pragma unroll
    for (int fm = 0; fm < 4; ++fm)
        arow[fm] = wm * 64 + fm * 16 + ((midx & 1) << 3) + l7;
#pragma unroll
    for (int f2 = 0; f2 < 2; ++f2)
        brow[f2] = wn * 32 + f2 * 16 + ((midx >> 1) << 3) + l7;

    float acc[4][4][4];
#pragma unroll
    for (int i = 0; i < 4; i++)
#pragma unroll
        for (int j = 0; j < 4; j++)
#pragma unroll
            for (int q = 0; q < 4; q++) acc[i][j][q] = 0.0f;

    // Prologue: prefetch chunks 0, 1
    load_stage<K, TERMS>(tile_base, 0, Ah, Al, Bh, Bl, 0, rowBase, colBase, M);
    asm volatile("cp.async.commit_group;" ::: "memory");
    load_stage<K, TERMS>(tile_base, 1, Ah, Al, Bh, Bl, 1, rowBase, colBase, M);
    asm volatile("cp.async.commit_group;" ::: "memory");

    Frags fr[2];
    for (int c = 0; c < NC; ++c) {
        if (c + 1 < NC) asm volatile("cp.async.wait_group 1;" ::: "memory");
        else            asm volatile("cp.async.wait_group 0;" ::: "memory");
        __syncthreads();
        const uint32_t st = tile_base + (uint32_t)(c % 3) * 65536u;
        load_frags<TERMS>(st, 0, arow, brow, a_ck, b_ck, fr[0]);
        if (c + 2 < NC) {
            load_stage<K, TERMS>(tile_base, (c + 2) % 3, Ah, Al, Bh, Bl,
                                 c + 2, rowBase, colBase, M);
            asm volatile("cp.async.commit_group;" ::: "memory");
        }
#pragma unroll
        for (int k = 0; k < 4; ++k) {
            if (k < 3)
                load_frags<TERMS>(st, k + 1, arow, brow, a_ck, b_ck, fr[(k + 1) & 1]);
            mma_frags<TERMS>(fr[k & 1], acc);
        }
    }

    // Epilogue: bias (+relu); fp32 strided / bf16 hi+lo / bf16 hi
    const int rowb = rowBase + wm * 64 + (lane >> 2);
    const int colb = colBase + wn * 32;
#pragma unroll
    for (int fm = 0; fm < 4; ++fm) {
        int r0 = rowb + fm * 16;
        int r1 = r0 + 8;
#pragma unroll
        for (int fn = 0; fn < 4; ++fn) {
            int col = colb + fn * 8 + (lane & 3) * 2;
            float2 bp = *reinterpret_cast<const float2*>(&bias[col]);
            float v0 = acc[fm][fn][0] + bp.x;
            float v1 = acc[fm][fn][1] + bp.y;
            float v2 = acc[fm][fn][2] + bp.x;
            float v3 = acc[fm][fn][3] + bp.y;
            if (RELU) {
                v0 = fmaxf(v0, 0.f); v1 = fmaxf(v1, 0.f);
                v2 = fmaxf(v2, 0.f); v3 = fmaxf(v3, 0.f);
            }
            if (OUT == 0) {
                if (col < ncols) {
                    if (r0 < M)
                        *reinterpret_cast<float2*>(&C[(size_t)r0 * ostride + col]) =
                            make_float2(v0, v1);
                    if (r1 < M)
                        *reinterpret_cast<float2*>(&C[(size_t)r1 * ostride + col]) =
                            make_float2(v2, v3);
                }
            } else {
                if (r0 < M) {
                    size_t h = ((size_t)r0 * ostride + col) >> 1;
                    __nv_bfloat16 h0 = __float2bfloat16(v0);
                    __nv_bfloat16 h1 = __float2bfloat16(v1);
                    Oh[h] = __nv_bfloat162(h0, h1);
                    if (OUT == 1)
                        Ol[h] = __nv_bfloat162(
                            __float2bfloat16(v0 - __bfloat162float(h0)),
                            __float2bfloat16(v1 - __bfloat162float(h1)));
                }
                if (r1 < M) {
                    size_t h = ((size_t)r1 * ostride + col) >> 1;
                    __nv_bfloat16 h2 = __float2bfloat16(v2);
                    __nv_bfloat16 h3 = __float2bfloat16(v3);
                    Oh[h] = __nv_bfloat162(h2, h3);
                    if (OUT == 1)
                        Ol[h] = __nv_bfloat162(
                            __float2bfloat16(v2 - __bfloat162float(h2)),
                            __float2bfloat16(v3 - __bfloat162float(h3)));
                }
            }
        }
    }
}

// ---------------------------------------------------------------------------
// In-place log_softmax over 64 classes, one warp per row
// ---------------------------------------------------------------------------
__global__ void log_softmax64_kernel(float* __restrict__ out, int M) {
    int warp = (blockIdx.x * blockDim.x + threadIdx.x) >> 5;
    int lane = threadIdx.x & 31;
    if (warp >= M) return;
    float* row = out + (size_t)warp * N_CLS;
    float a = row[lane];
    float b = row[lane + 32];
    float m = fmaxf(a, b);
#pragma unroll
    for (int o = 16; o > 0; o >>= 1)
        m = fmaxf(m, __shfl_xor_sync(0xFFFFFFFFu, m, o));
    float s = expf(a - m) + expf(b - m);
#pragma unroll
    for (int o = 16; o > 0; o >>= 1)
        s += __shfl_xor_sync(0xFFFFFFFFu, s, o);
    float lse = m + logf(s);
    row[lane]      = a - lse;
    row[lane + 32] = b - lse;
}

// ---------------------------------------------------------------------------
// Launch
// ---------------------------------------------------------------------------
extern "C" void kernel_launch(void* const* d_in, const int* in_sizes, int n_in,
                              void* d_out, int out_size) {
    const float*        x   = (const float*)d_in[0];
    const unsigned int* ei  = (const unsigned int*)d_in[1];
    const float* W1a = (const float*)d_in[2];
    const float* b1a = (const float*)d_in[3];
    const float* W1b = (const float*)d_in[4];
    const float* b1b = (const float*)d_in[5];
    const float* W2a = (const float*)d_in[6];
    const float* b2a = (const float*)d_in[7];
    const float* W2b = (const float*)d_in[8];
    const float* b2b = (const float*)d_in[9];
    const float* Wfc = (const float*)d_in[10];
    const float* bfc = (const float*)d_in[11];
    float* out = (float*)d_out;

    float *bfcPad;
    __nv_bfloat16 *Ah, *Al, *Ch, *Wh, *Wl;
    cudaGetSymbolAddress((void**)&Ah, g_Ah);
    cudaGetSymbolAddress((void**)&Al, g_Al);
    cudaGetSymbolAddress((void**)&Ch, g_Ch);
    cudaGetSymbolAddress((void**)&Wh, g_Wh);
    cudaGetSymbolAddress((void**)&Wl, g_Wl);
    cudaGetSymbolAddress((void**)&bfcPad, g_bfcPad);

    const int GEMM_SMEM = 3 * 65536 + 1024;  // 197632 B (3-stage + align slack)
    cudaFuncSetAttribute(gemm_bf16s_mma_kernel<256, true, 2, 2>,
                         cudaFuncAttributeMaxDynamicSharedMemorySize, GEMM_SMEM);
    cudaFuncSetAttribute(gemm_bf16s_mma_kernel<1024, true, 2, 2>,
                         cudaFuncAttributeMaxDynamicSharedMemorySize, GEMM_SMEM);
    cudaFuncSetAttribute(gemm_bf16s_mma_kernel<1024, false, 1, 2>,
                         cudaFuncAttributeMaxDynamicSharedMemorySize, GEMM_SMEM);
    cudaFuncSetAttribute(gemm_bf16s_mma_kernel<1024, false, 0, 3>,
                         cudaFuncAttributeMaxDynamicSharedMemorySize, GEMM_SMEM);

    // ---- Edge normalization + CSR build ----
    detect_idx_kernel<<<1, 256>>>(ei);
    convert_idx_kernel<<<(2 * N_EDGES + 255) / 256, 256>>>(ei);
    zero_csr_kernel<<<(N_NODES + 255) / 256, 256>>>();
    count_deg_kernel<<<(N_EDGES + 255) / 256, 256>>>();
    const int NB = (N_NODES + 1023) / 1024;   // 98
    scan_block_kernel<<<NB, 1024>>>();
    scan_sums_kernel<<<1, 32>>>(NB);
    finalize_ptr_kernel<<<(N_NODES + 255) / 256, 256>>>();
    fill_csr_kernel<<<(N_EDGES + 255) / 256, 256>>>();

    dim3 gridGemm(HID / 128, (N_NODES + 127) / 128);   // (8, 782)
    dim3 gridFC(1, (N_NODES + 127) / 128);

    // ---- Layer 1: Ah = bf16(x + gather(x)) ----
    gather_x_kernel<<<N_NODES, 128>>>((const float2*)x, (__nv_bfloat162*)Ah);
    // GEMM1a: Ch = bf16(relu(Ah @ W1a + b1a))
    split_weightT_kernel<<<(D_IN * HID + 255) / 256, 256>>>(
        W1a, Wh, Wl, D_IN, HID, HID);
    gemm_bf16s_mma_kernel<256, true, 2, 2><<<gridGemm, 256, GEMM_SMEM>>>(
        Ah, nullptr, Wh, Wl, b1a, nullptr,
        (__nv_bfloat162*)Ch, nullptr, N_NODES, HID, HID);
    // GEMM1b: Ah = bf16(relu(Ch @ W1b + b1b)) = h1   (outer relu fused)
    split_weightT_kernel<<<(HID * HID + 255) / 256, 256>>>(
        W1b, Wh, Wl, HID, HID, HID);
    gemm_bf16s_mma_kernel<1024, true, 2, 2><<<gridGemm, 256, GEMM_SMEM>>>(
        Ch, nullptr, Wh, Wl, b1b, nullptr,
        (__nv_bfloat162*)Ah, nullptr, N_NODES, HID, HID);

    // ---- Layer 2: Ch = bf16(h1 + gather(h1)) ----
    gather_h_kernel<<<N_NODES, 128>>>((const uint4*)Ah, (uint4*)Ch);
    // GEMM2a: Ah = bf16(relu(Ch @ W2a + b2a))
    split_weightT_kernel<<<(HID * HID + 255) / 256, 256>>>(
        W2a, Wh, Wl, HID, HID, HID);
    gemm_bf16s_mma_kernel<1024, true, 2, 2><<<gridGemm, 256, GEMM_SMEM>>>(
        Ch, nullptr, Wh, Wl, b2a, nullptr,
        (__nv_bfloat162*)Ah, nullptr, N_NODES, HID, HID);
    // GEMM2b: (Ch, Al) = split(Ah @ W2b + b2b) = h2 hi/lo (no relu)
    split_weightT_kernel<<<(HID * HID + 255) / 256, 256>>>(
        W2b, Wh, Wl, HID, HID, HID);
    gemm_bf16s_mma_kernel<1024, false, 1, 2><<<gridGemm, 256, GEMM_SMEM>>>(
        Ah, nullptr, Wh, Wl, b2b, nullptr,
        (__nv_bfloat162*)Ch, (__nv_bfloat162*)Al, N_NODES, HID, HID);

    // ---- Classifier (3-term, N padded 64->128) + log_softmax ----
    pad_bias_kernel<<<1, 128>>>(bfc, N_CLS);
    split_weightT_kernel<<<(HID * 128 + 255) / 256, 256>>>(
        Wfc, Wh, Wl, HID, N_CLS, 128);
    gemm_bf16s_mma_kernel<1024, false, 0, 3><<<gridFC, 256, GEMM_SMEM>>>(
        Ch, Al, Wh, Wl, bfcPad, out, nullptr, nullptr, N_NODES, N_CLS, N_CLS);
    log_softmax64_kernel<<<(N_NODES * 32 + 255) / 256, 256>>>(out, N_NODES);
}

// round 12
// speedup vs baseline: 6.1027x; 1.4796x over previous
#include <cuda_runtime.h>
#include <cuda_bf16.h>
#include <math.h>
#include <stdint.h>

// Problem constants (fixed by the reference)
#define N_NODES  100000
#define N_EDGES  300000
#define D_IN     256
#define HID      1024
#define N_CLS    64

// ---------------------------------------------------------------------------
// Scratch (device globals: allocation-free)
// ---------------------------------------------------------------------------
__device__ __nv_bfloat16 g_Ah[(size_t)N_NODES * HID];       // act bf16 ping
__device__ __nv_bfloat16 g_Ch[(size_t)N_NODES * HID];       // act bf16 pong
__device__ __nv_bfloat16 g_Al[(size_t)N_NODES * HID];       // h2 lo residual
__device__ __nv_bfloat16 g_Wh[(size_t)HID * HID];           // weight^T hi
__device__ __nv_bfloat16 g_Wl[(size_t)HID * HID];           // weight^T lo (cls only)
__device__ float g_bfcPad[128];                             // padded classifier bias
__device__ int   g_edges[2 * N_EDGES];
__device__ int   g_idx64;
// CSR scratch
__device__ int g_deg[N_NODES];
__device__ int g_incl[N_NODES];
__device__ int g_ptr[N_NODES];
__device__ int g_cursor[N_NODES];
__device__ int g_blockSums[128];
__device__ int g_csr_idx[N_EDGES];

// ---------------------------------------------------------------------------
// PTX helpers (all sm_80-era: valid under compute_103, no 'a' features)
// ---------------------------------------------------------------------------
__device__ __forceinline__ uint32_t s2u(const void* p) {
    uint32_t a;
    asm("{ .reg .u64 t; cvta.to.shared.u64 t, %1; cvt.u32.u64 %0, t; }"
        : "=r"(a) : "l"(p));
    return a;
}

__device__ __forceinline__ void cp_async16(uint32_t s, const void* g, unsigned sz) {
    asm volatile("cp.async.cg.shared.global [%0], [%1], 16, %2;"
                 :: "r"(s), "l"(g), "r"(sz));
}

__device__ __forceinline__ void ldsm4(uint32_t* r, uint32_t addr) {
    asm volatile("ldmatrix.sync.aligned.m8n8.x4.shared.b16 {%0,%1,%2,%3}, [%4];"
                 : "=r"(r[0]), "=r"(r[1]), "=r"(r[2]), "=r"(r[3]) : "r"(addr));
}

__device__ __forceinline__ void mma_bf16(float* d, const uint32_t* a,
                                         const uint32_t* b) {
    asm volatile(
        "mma.sync.aligned.m16n8k16.row.col.f32.bf16.bf16.f32 "
        "{%0,%1,%2,%3},{%4,%5,%6,%7},{%8,%9},{%0,%1,%2,%3};"
        : "+f"(d[0]), "+f"(d[1]), "+f"(d[2]), "+f"(d[3])
        : "r"(a[0]), "r"(a[1]), "r"(a[2]), "r"(a[3]), "r"(b[0]), "r"(b[1]));
}

// ---------------------------------------------------------------------------
// Edge-index dtype detection + normalization
// ---------------------------------------------------------------------------
__global__ void detect_idx_kernel(const unsigned int* __restrict__ ei) {
    unsigned v = ei[2 * threadIdx.x + 1];
    int any = __syncthreads_or(v != 0u);
    if (threadIdx.x == 0) g_idx64 = any ? 0 : 1;
}

__global__ void convert_idx_kernel(const unsigned int* __restrict__ ei) {
    int i = blockIdx.x * blockDim.x + threadIdx.x;
    if (i < 2 * N_EDGES) g_edges[i] = g_idx64 ? (int)ei[2 * i] : (int)ei[i];
}

// ---------------------------------------------------------------------------
// CSR build: degree count -> block scan -> ptr -> atomic-slot fill
// ---------------------------------------------------------------------------
__global__ void zero_csr_kernel() {
    int i = blockIdx.x * blockDim.x + threadIdx.x;
    if (i < N_NODES) { g_deg[i] = 0; g_cursor[i] = 0; }
}

__global__ void count_deg_kernel() {
    int e = blockIdx.x * blockDim.x + threadIdx.x;
    if (e < N_EDGES) atomicAdd(&g_deg[g_edges[N_EDGES + e]], 1);
}

__global__ void scan_block_kernel() {
    __shared__ int s[1024];
    int g = blockIdx.x * 1024 + threadIdx.x;
    int v = (g < N_NODES) ? g_deg[g] : 0;
    s[threadIdx.x] = v;
    __syncthreads();
#pragma unroll
    for (int off = 1; off < 1024; off <<= 1) {
        int t = (threadIdx.x >= off) ? s[threadIdx.x - off] : 0;
        __syncthreads();
        s[threadIdx.x] += t;
        __syncthreads();
    }
    if (g < N_NODES) g_incl[g] = s[threadIdx.x];
    if (threadIdx.x == 1023) g_blockSums[blockIdx.x] = s[1023];
}

__global__ void scan_sums_kernel(int nb) {
    if (threadIdx.x == 0) {
        int run = 0;
        for (int i = 0; i < nb; i++) { int t = g_blockSums[i]; g_blockSums[i] = run; run += t; }
    }
}

__global__ void finalize_ptr_kernel() {
    int g = blockIdx.x * blockDim.x + threadIdx.x;
    if (g < N_NODES) g_ptr[g] = g_incl[g] - g_deg[g] + g_blockSums[g >> 10];
}

__global__ void fill_csr_kernel() {
    int e = blockIdx.x * blockDim.x + threadIdx.x;
    if (e < N_EDGES) {
        int s = g_edges[e];
        int d = g_edges[N_EDGES + e];
        int slot = atomicAdd(&g_cursor[d], 1);
        g_csr_idx[g_ptr[d] + slot] = s;
    }
}

// ---------------------------------------------------------------------------
// Gather aggregation, layer 1: O[i] = bf16(x[i] + sum_j x[j]), D=256 fp32 in
// ---------------------------------------------------------------------------
__global__ void __launch_bounds__(128)
gather_x_kernel(const float2* __restrict__ X, __nv_bfloat162* __restrict__ O) {
    int node = blockIdx.x;
    int t = threadIdx.x;
    float2 a = X[(size_t)node * 128 + t];
    int st = g_ptr[node];
    int de = g_deg[node];
    for (int q = 0; q < de; q++) {
        int j = g_csr_idx[st + q];
        float2 v = X[(size_t)j * 128 + t];
        a.x += v.x;
        a.y += v.y;
    }
    O[(size_t)node * 128 + t] = __nv_bfloat162(__float2bfloat16(a.x),
                                               __float2bfloat16(a.y));
}

// ---------------------------------------------------------------------------
// Gather aggregation, layer 2: O[i] = bf16(H[i] + sum_j H[j]), D=1024 bf16 in
// ---------------------------------------------------------------------------
__global__ void __launch_bounds__(128)
gather_h_kernel(const uint4* __restrict__ H, uint4* __restrict__ O) {
    int node = blockIdx.x;
    int t = threadIdx.x;
    uint4 sv = H[(size_t)node * 128 + t];
    float acc[8];
    {
        float2 p0 = __bfloat1622float2(*(__nv_bfloat162*)&sv.x);
        float2 p1 = __bfloat1622float2(*(__nv_bfloat162*)&sv.y);
        float2 p2 = __bfloat1622float2(*(__nv_bfloat162*)&sv.z);
        float2 p3 = __bfloat1622float2(*(__nv_bfloat162*)&sv.w);
        acc[0] = p0.x; acc[1] = p0.y; acc[2] = p1.x; acc[3] = p1.y;
        acc[4] = p2.x; acc[5] = p2.y; acc[6] = p3.x; acc[7] = p3.y;
    }
    int st = g_ptr[node];
    int de = g_deg[node];
    for (int q = 0; q < de; q++) {
        int j = g_csr_idx[st + q];
        uint4 v = H[(size_t)j * 128 + t];
        float2 p0 = __bfloat1622float2(*(__nv_bfloat162*)&v.x);
        float2 p1 = __bfloat1622float2(*(__nv_bfloat162*)&v.y);
        float2 p2 = __bfloat1622float2(*(__nv_bfloat162*)&v.z);
        float2 p3 = __bfloat1622float2(*(__nv_bfloat162*)&v.w);
        acc[0] += p0.x; acc[1] += p0.y; acc[2] += p1.x; acc[3] += p1.y;
        acc[4] += p2.x; acc[5] += p2.y; acc[6] += p3.x; acc[7] += p3.y;
    }
    uint4 o;
    *(__nv_bfloat162*)&o.x = __nv_bfloat162(__float2bfloat16(acc[0]), __float2bfloat16(acc[1]));
    *(__nv_bfloat162*)&o.y = __nv_bfloat162(__float2bfloat16(acc[2]), __float2bfloat16(acc[3]));
    *(__nv_bfloat162*)&o.z = __nv_bfloat162(__float2bfloat16(acc[4]), __float2bfloat16(acc[5]));
    *(__nv_bfloat162*)&o.w = __nv_bfloat162(__float2bfloat16(acc[6]), __float2bfloat16(acc[7]));
    O[(size_t)node * 128 + t] = o;
}

// ---------------------------------------------------------------------------
// Weight W[K,N] fp32 -> transposed Wt[Npad,K] bf16 hi (+ optional lo)
// ---------------------------------------------------------------------------
__global__ void split_weightT_kernel(const float* __restrict__ W,
                                     __nv_bfloat16* __restrict__ Th,
                                     __nv_bfloat16* __restrict__ Tl,
                                     int Kd, int Nd, int Npad) {
    int idx = blockIdx.x * blockDim.x + threadIdx.x;
    if (idx >= Kd * Npad) return;
    int n = idx / Kd;
    int k = idx % Kd;
    float v = (n < Nd) ? W[(size_t)k * Nd + n] : 0.0f;
    __nv_bfloat16 h = __float2bfloat16(v);
    Th[idx] = h;
    if (Tl) Tl[idx] = __float2bfloat16(v - __bfloat162float(h));
}

__global__ void pad_bias_kernel(const float* __restrict__ b, int n) {
    int i = threadIdx.x;
    if (i < 128) g_bfcPad[i] = (i < n) ? b[i] : 0.0f;
}

// ---------------------------------------------------------------------------
// bf16 split-compensated mma.sync GEMM:
//   C[M, ncols] = act(A[M,K] @ W[K,ncols] + bias)
// TERMS=1: pure bf16 (AhBh only).
// TERMS=2: W split; AhBh + AhBl.
// TERMS=3: A split too; adds AlBh.
// BM=128, BN=128, BK=64. 256 threads = 2x4 warps (64x32 per warp).
// 3-stage cp.async pipeline; SW128-swizzled SMEM; double-buffered ldsm frags.
// OUT: 0 = fp32 to C (stride ostride, col guard); 1 = bf16 hi+lo; 2 = bf16 hi.
// ---------------------------------------------------------------------------
template <int K, int TERMS>
__device__ __forceinline__ void load_stage(uint32_t tbase, int stage,
    const __nv_bfloat16* __restrict__ Ah, const __nv_bfloat16* __restrict__ Al,
    const __nv_bfloat16* __restrict__ Bh, const __nv_bfloat16* __restrict__ Bl,
    int chunk, int rowBase, int colBase, int M) {
    const int tid = threadIdx.x;
    const uint32_t sBase = tbase + (uint32_t)stage * 65536u;
    const long kOff = (long)chunk * 64;
#pragma unroll
    for (int i = 0; i < 4; ++i) {
        int t = i * 256 + tid;            // 0..1023 16B chunks per 16KB tile
        int r = t >> 3;
        int cc = t & 7;
        uint32_t sw = (uint32_t)(r * 128 + ((cc ^ (r & 7)) << 4));
        int gr = rowBase + r;
        unsigned sz = (gr < M) ? 16u : 0u;
        int ga = gr < M ? gr : (M - 1);
        size_t aoff = ((size_t)ga * K + kOff + cc * 8) * 2;  // bytes
        cp_async16(sBase + sw, (const char*)Ah + aoff, sz);
        if (TERMS == 3)
            cp_async16(sBase + 16384u + sw, (const char*)Al + aoff, sz);
        int gn = colBase + r;
        size_t boff = ((size_t)gn * K + kOff + cc * 8) * 2;
        cp_async16(sBase + 32768u + sw, (const char*)Bh + boff, 16u);
        if (TERMS >= 2)
            cp_async16(sBase + 49152u + sw, (const char*)Bl + boff, 16u);
    }
}

struct Frags {
    uint32_t ah[4][4];
    uint32_t al[4][4];
    uint32_t bh[2][4];
    uint32_t bl[2][4];
};

template <int TERMS>
__device__ __forceinline__ void load_frags(uint32_t st, int k,
                                           const int* arow, const int* brow,
                                           int a_ck, int b_ck, Frags& f) {
    const uint32_t aHi = st, aLo = st + 16384u;
    const uint32_t bHi = st + 32768u, bLo = st + 49152u;
#pragma unroll
    for (int fm = 0; fm < 4; ++fm) {
        int row = arow[fm];
        int ck = k * 2 + a_ck;
        uint32_t off = (uint32_t)(row * 128 + ((ck ^ (row & 7)) << 4));
        ldsm4(f.ah[fm], aHi + off);
        if (TERMS == 3) ldsm4(f.al[fm], aLo + off);
    }
#pragma unroll
    for (int f2 = 0; f2 < 2; ++f2) {
        int row = brow[f2];
        int ck = k * 2 + b_ck;
        uint32_t off = (uint32_t)(row * 128 + ((ck ^ (row & 7)) << 4));
        ldsm4(f.bh[f2], bHi + off);
        if (TERMS >= 2) ldsm4(f.bl[f2], bLo + off);
    }
}

template <int TERMS>
__device__ __forceinline__ void mma_frags(const Frags& f, float acc[4][4][4]) {
#pragma unroll
    for (int fm = 0; fm < 4; ++fm)
#pragma unroll
        for (int fn = 0; fn < 4; ++fn) {
            const uint32_t* pbh = &f.bh[fn >> 1][(fn & 1) * 2];
            const uint32_t* pbl = &f.bl[fn >> 1][(fn & 1) * 2];
            mma_bf16(acc[fm][fn], f.ah[fm], pbh);                  // Ah*Bh
            if (TERMS >= 2) mma_bf16(acc[fm][fn], f.ah[fm], pbl);  // Ah*Bl
            if (TERMS == 3) mma_bf16(acc[fm][fn], f.al[fm], pbh);  // Al*Bh
        }
}

template <int K, bool RELU, int OUT, int TERMS>
__global__ void __launch_bounds__(256)
gemm_bf16s_mma_kernel(const __nv_bfloat16* __restrict__ Ah,
                      const __nv_bfloat16* __restrict__ Al,
                      const __nv_bfloat16* __restrict__ Bh,
                      const __nv_bfloat16* __restrict__ Bl,
                      const float* __restrict__ bias,
                      float* __restrict__ C,
                      __nv_bfloat162* __restrict__ Oh,
                      __nv_bfloat162* __restrict__ Ol,
                      int M, int ostride, int ncols) {
    constexpr int NC = K / 64;
    extern __shared__ char smem[];
    const uint32_t tile_base = (s2u(smem) + 1023u) & ~1023u;

    const int tid = threadIdx.x;
    const int wid = tid >> 5;
    const int lane = tid & 31;
    const int wm = wid >> 2;          // 0..1
    const int wn = wid & 3;           // 0..3
    const int rowBase = blockIdx.y * 128;
    const int colBase = blockIdx.x * 128;

    const int midx = lane >> 3;
    const int l7 = lane & 7;
    const int a_ck = (midx >> 1);
    const int b_ck = (midx & 1);
    int arow[4], brow[2];
#pragma unroll
    for (int fm = 0; fm < 4; ++fm)
        arow[fm] = wm * 64 + fm * 16 + ((midx & 1) << 3) + l7;
#pragma unroll
    for (int f2 = 0; f2 < 2; ++f2)
        brow[f2] = wn * 32 + f2 * 16 + ((midx >> 1) << 3) + l7;

    float acc[4][4][4];
#pragma unroll
    for (int i = 0; i < 4; i++)
#pragma unroll
        for (int j = 0; j < 4; j++)
#pragma unroll
            for (int q = 0; q < 4; q++) acc[i][j][q] = 0.0f;

    // Prologue: prefetch chunks 0, 1
    load_stage<K, TERMS>(tile_base, 0, Ah, Al, Bh, Bl, 0, rowBase, colBase, M);
    asm volatile("cp.async.commit_group;" ::: "memory");
    load_stage<K, TERMS>(tile_base, 1, Ah, Al, Bh, Bl, 1, rowBase, colBase, M);
    asm volatile("cp.async.commit_group;" ::: "memory");

    Frags fr[2];
    for (int c = 0; c < NC; ++c) {
        if (c + 1 < NC) asm volatile("cp.async.wait_group 1;" ::: "memory");
        else            asm volatile("cp.async.wait_group 0;" ::: "memory");
        __syncthreads();
        const uint32_t st = tile_base + (uint32_t)(c % 3) * 65536u;
        load_frags<TERMS>(st, 0, arow, brow, a_ck, b_ck, fr[0]);
        if (c + 2 < NC) {
            load_stage<K, TERMS>(tile_base, (c + 2) % 3, Ah, Al, Bh, Bl,
                                 c + 2, rowBase, colBase, M);
            asm volatile("cp.async.commit_group;" ::: "memory");
        }
#pragma unroll
        for (int k = 0; k < 4; ++k) {
            if (k < 3)
                load_frags<TERMS>(st, k + 1, arow, brow, a_ck, b_ck, fr[(k + 1) & 1]);
            mma_frags<TERMS>(fr[k & 1], acc);
        }
    }

    // Epilogue: bias (+relu); fp32 strided / bf16 hi+lo / bf16 hi
    const int rowb = rowBase + wm * 64 + (lane >> 2);
    const int colb = colBase + wn * 32;
#pragma unroll
    for (int fm = 0; fm < 4; ++fm) {
        int r0 = rowb + fm * 16;
        int r1 = r0 + 8;
#pragma unroll
        for (int fn = 0; fn < 4; ++fn) {
            int col = colb + fn * 8 + (lane & 3) * 2;
            float2 bp = *reinterpret_cast<const float2*>(&bias[col]);
            float v0 = acc[fm][fn][0] + bp.x;
            float v1 = acc[fm][fn][1] + bp.y;
            float v2 = acc[fm][fn][2] + bp.x;
            float v3 = acc[fm][fn][3] + bp.y;
            if (RELU) {
                v0 = fmaxf(v0, 0.f); v1 = fmaxf(v1, 0.f);
                v2 = fmaxf(v2, 0.f); v3 = fmaxf(v3, 0.f);
            }
            if (OUT == 0) {
                if (col < ncols) {
                    if (r0 < M)
                        *reinterpret_cast<float2*>(&C[(size_t)r0 * ostride + col]) =
                            make_float2(v0, v1);
                    if (r1 < M)
                        *reinterpret_cast<float2*>(&C[(size_t)r1 * ostride + col]) =
                            make_float2(v2, v3);
                }
            } else {
                if (r0 < M) {
                    size_t h = ((size_t)r0 * ostride + col) >> 1;
                    __nv_bfloat16 h0 = __float2bfloat16(v0);
                    __nv_bfloat16 h1 = __float2bfloat16(v1);
                    Oh[h] = __nv_bfloat162(h0, h1);
                    if (OUT == 1)
                        Ol[h] = __nv_bfloat162(
                            __float2bfloat16(v0 - __bfloat162float(h0)),
                            __float2bfloat16(v1 - __bfloat162float(h1)));
                }
                if (r1 < M) {
                    size_t h = ((size_t)r1 * ostride + col) >> 1;
                    __nv_bfloat16 h2 = __float2bfloat16(v2);
                    __nv_bfloat16 h3 = __float2bfloat16(v3);
                    Oh[h] = __nv_bfloat162(h2, h3);
                    if (OUT == 1)
                        Ol[h] = __nv_bfloat162(
                            __float2bfloat16(v2 - __bfloat162float(h2)),
                            __float2bfloat16(v3 - __bfloat162float(h3)));
                }
            }
        }
    }
}

// ---------------------------------------------------------------------------
// In-place log_softmax over 64 classes, one warp per row
// ---------------------------------------------------------------------------
__global__ void log_softmax64_kernel(float* __restrict__ out, int M) {
    int warp = (blockIdx.x * blockDim.x + threadIdx.x) >> 5;
    int lane = threadIdx.x & 31;
    if (warp >= M) return;
    float* row = out + (size_t)warp * N_CLS;
    float a = row[lane];
    float b = row[lane + 32];
    float m = fmaxf(a, b);
#pragma unroll
    for (int o = 16; o > 0; o >>= 1)
        m = fmaxf(m, __shfl_xor_sync(0xFFFFFFFFu, m, o));
    float s = expf(a - m) + expf(b - m);
#pragma unroll
    for (int o = 16; o > 0; o >>= 1)
        s += __shfl_xor_sync(0xFFFFFFFFu, s, o);
    float lse = m + logf(s);
    row[lane]      = a - lse;
    row[lane + 32] = b - lse;
}

// ---------------------------------------------------------------------------
// Launch
// ---------------------------------------------------------------------------
extern "C" void kernel_launch(void* const* d_in, const int* in_sizes, int n_in,
                              void* d_out, int out_size) {
    const float*        x   = (const float*)d_in[0];
    const unsigned int* ei  = (const unsigned int*)d_in[1];
    const float* W1a = (const float*)d_in[2];
    const float* b1a = (const float*)d_in[3];
    const float* W1b = (const float*)d_in[4];
    const float* b1b = (const float*)d_in[5];
    const float* W2a = (const float*)d_in[6];
    const float* b2a = (const float*)d_in[7];
    const float* W2b = (const float*)d_in[8];
    const float* b2b = (const float*)d_in[9];
    const float* Wfc = (const float*)d_in[10];
    const float* bfc = (const float*)d_in[11];
    float* out = (float*)d_out;

    float *bfcPad;
    __nv_bfloat16 *Ah, *Al, *Ch, *Wh, *Wl;
    cudaGetSymbolAddress((void**)&Ah, g_Ah);
    cudaGetSymbolAddress((void**)&Al, g_Al);
    cudaGetSymbolAddress((void**)&Ch, g_Ch);
    cudaGetSymbolAddress((void**)&Wh, g_Wh);
    cudaGetSymbolAddress((void**)&Wl, g_Wl);
    cudaGetSymbolAddress((void**)&bfcPad, g_bfcPad);

    const int GEMM_SMEM = 3 * 65536 + 1024;  // 197632 B (3-stage + align slack)
    cudaFuncSetAttribute(gemm_bf16s_mma_kernel<256, true, 2, 1>,
                         cudaFuncAttributeMaxDynamicSharedMemorySize, GEMM_SMEM);
    cudaFuncSetAttribute(gemm_bf16s_mma_kernel<1024, true, 2, 1>,
                         cudaFuncAttributeMaxDynamicSharedMemorySize, GEMM_SMEM);
    cudaFuncSetAttribute(gemm_bf16s_mma_kernel<1024, false, 1, 1>,
                         cudaFuncAttributeMaxDynamicSharedMemorySize, GEMM_SMEM);
    cudaFuncSetAttribute(gemm_bf16s_mma_kernel<1024, false, 0, 3>,
                         cudaFuncAttributeMaxDynamicSharedMemorySize, GEMM_SMEM);

    // ---- Edge normalization + CSR build ----
    detect_idx_kernel<<<1, 256>>>(ei);
    convert_idx_kernel<<<(2 * N_EDGES + 255) / 256, 256>>>(ei);
    zero_csr_kernel<<<(N_NODES + 255) / 256, 256>>>();
    count_deg_kernel<<<(N_EDGES + 255) / 256, 256>>>();
    const int NB = (N_NODES + 1023) / 1024;   // 98
    scan_block_kernel<<<NB, 1024>>>();
    scan_sums_kernel<<<1, 32>>>(NB);
    finalize_ptr_kernel<<<(N_NODES + 255) / 256, 256>>>();
    fill_csr_kernel<<<(N_EDGES + 255) / 256, 256>>>();

    dim3 gridGemm(HID / 128, (N_NODES + 127) / 128);   // (8, 782)
    dim3 gridFC(1, (N_NODES + 127) / 128);

    // ---- Layer 1: Ah = bf16(x + gather(x)) ----
    gather_x_kernel<<<N_NODES, 128>>>((const float2*)x, (__nv_bfloat162*)Ah);
    // GEMM1a: Ch = bf16(relu(Ah @ W1a + b1a))   [1-term]
    split_weightT_kernel<<<(D_IN * HID + 255) / 256, 256>>>(
        W1a, Wh, nullptr, D_IN, HID, HID);
    gemm_bf16s_mma_kernel<256, true, 2, 1><<<gridGemm, 256, GEMM_SMEM>>>(
        Ah, nullptr, Wh, nullptr, b1a, nullptr,
        (__nv_bfloat162*)Ch, nullptr, N_NODES, HID, HID);
    // GEMM1b: Ah = bf16(relu(Ch @ W1b + b1b)) = h1   [1-term]
    split_weightT_kernel<<<(HID * HID + 255) / 256, 256>>>(
        W1b, Wh, nullptr, HID, HID, HID);
    gemm_bf16s_mma_kernel<1024, true, 2, 1><<<gridGemm, 256, GEMM_SMEM>>>(
        Ch, nullptr, Wh, nullptr, b1b, nullptr,
        (__nv_bfloat162*)Ah, nullptr, N_NODES, HID, HID);

    // ---- Layer 2: Ch = bf16(h1 + gather(h1)) ----
    gather_h_kernel<<<N_NODES, 128>>>((const uint4*)Ah, (uint4*)Ch);
    // GEMM2a: Ah = bf16(relu(Ch @ W2a + b2a))   [1-term]
    split_weightT_kernel<<<(HID * HID + 255) / 256, 256>>>(
        W2a, Wh, nullptr, HID, HID, HID);
    gemm_bf16s_mma_kernel<1024, true, 2, 1><<<gridGemm, 256, GEMM_SMEM>>>(
        Ch, nullptr, Wh, nullptr, b2a, nullptr,
        (__nv_bfloat162*)Ah, nullptr, N_NODES, HID, HID);
    // GEMM2b: (Ch, Al) = split(Ah @ W2b + b2b) = h2 hi/lo   [1-term, split out]
    split_weightT_kernel<<<(HID * HID + 255) / 256, 256>>>(
        W2b, Wh, nullptr, HID, HID, HID);
    gemm_bf16s_mma_kernel<1024, false, 1, 1><<<gridGemm, 256, GEMM_SMEM>>>(
        Ah, nullptr, Wh, nullptr, b2b, nullptr,
        (__nv_bfloat162*)Ch, (__nv_bfloat162*)Al, N_NODES, HID, HID);

    // ---- Classifier (3-term, N padded 64->128) + log_softmax ----
    pad_bias_kernel<<<1, 128>>>(bfc, N_CLS);
    split_weightT_kernel<<<(HID * 128 + 255) / 256, 256>>>(
        Wfc, Wh, Wl, HID, N_CLS, 128);
    gemm_bf16s_mma_kernel<1024, false, 0, 3><<<gridFC, 256, GEMM_SMEM>>>(
        Ch, Al, Wh, Wl, bfcPad, out, nullptr, nullptr, N_NODES, N_CLS, N_CLS);
    log_softmax64_kernel<<<(N_NODES * 32 + 255) / 256, 256>>>(out, N_NODES);
}

// round 13
// speedup vs baseline: 7.6639x; 1.2558x over previous
#include <cuda_runtime.h>
#include <cuda_bf16.h>
#include <math.h>
#include <stdint.h>

// Problem constants (fixed by the reference)
#define N_NODES  100000
#define N_EDGES  300000
#define D_IN     256
#define HID      1024
#define N_CLS    64

// ---------------------------------------------------------------------------
// Scratch (device globals: allocation-free)
// ---------------------------------------------------------------------------
__device__ __nv_bfloat16 g_Ah[(size_t)N_NODES * HID];       // act bf16 ping
__device__ __nv_bfloat16 g_Ch[(size_t)N_NODES * HID];       // act bf16 pong
__device__ __nv_bfloat16 g_Al[(size_t)N_NODES * HID];       // h2 lo residual
__device__ __nv_bfloat16 g_Wh[(size_t)HID * HID];           // weight^T hi
__device__ __nv_bfloat16 g_Wl[(size_t)HID * HID];           // weight^T lo (cls only)
__device__ float g_bfcPad[128];                             // padded classifier bias
__device__ int   g_edges[2 * N_EDGES];
__device__ int   g_idx64;
// CSR scratch
__device__ int g_deg[N_NODES];
__device__ int g_incl[N_NODES];
__device__ int g_ptr[N_NODES];
__device__ int g_cursor[N_NODES];
__device__ int g_blockSums[128];
__device__ int g_csr_idx[N_EDGES];

// ---------------------------------------------------------------------------
// PTX helpers (all sm_80-era: valid under compute_103, no 'a' features)
// ---------------------------------------------------------------------------
__device__ __forceinline__ uint32_t s2u(const void* p) {
    uint32_t a;
    asm("{ .reg .u64 t; cvta.to.shared.u64 t, %1; cvt.u32.u64 %0, t; }"
        : "=r"(a) : "l"(p));
    return a;
}

__device__ __forceinline__ void cp_async16(uint32_t s, const void* g, unsigned sz) {
    asm volatile("cp.async.cg.shared.global [%0], [%1], 16, %2;"
                 :: "r"(s), "l"(g), "r"(sz));
}

__device__ __forceinline__ void ldsm4(uint32_t* r, uint32_t addr) {
    asm volatile("ldmatrix.sync.aligned.m8n8.x4.shared.b16 {%0,%1,%2,%3}, [%4];"
                 : "=r"(r[0]), "=r"(r[1]), "=r"(r[2]), "=r"(r[3]) : "r"(addr));
}

__device__ __forceinline__ void mma_bf16(float* d, const uint32_t* a,
                                         const uint32_t* b) {
    asm volatile(
        "mma.sync.aligned.m16n8k16.row.col.f32.bf16.bf16.f32 "
        "{%0,%1,%2,%3},{%4,%5,%6,%7},{%8,%9},{%0,%1,%2,%3};"
        : "+f"(d[0]), "+f"(d[1]), "+f"(d[2]), "+f"(d[3])
        : "r"(a[0]), "r"(a[1]), "r"(a[2]), "r"(a[3]), "r"(b[0]), "r"(b[1]));
}

// ---------------------------------------------------------------------------
// Edge-index dtype detection + normalization
// ---------------------------------------------------------------------------
__global__ void detect_idx_kernel(const unsigned int* __restrict__ ei) {
    unsigned v = ei[2 * threadIdx.x + 1];
    int any = __syncthreads_or(v != 0u);
    if (threadIdx.x == 0) g_idx64 = any ? 0 : 1;
}

__global__ void convert_idx_kernel(const unsigned int* __restrict__ ei) {
    int i = blockIdx.x * blockDim.x + threadIdx.x;
    if (i < 2 * N_EDGES) g_edges[i] = g_idx64 ? (int)ei[2 * i] : (int)ei[i];
}

// ---------------------------------------------------------------------------
// CSR build: degree count -> block scan -> ptr -> atomic-slot fill
// ---------------------------------------------------------------------------
__global__ void zero_csr_kernel() {
    int i = blockIdx.x * blockDim.x + threadIdx.x;
    if (i < N_NODES) { g_deg[i] = 0; g_cursor[i] = 0; }
}

__global__ void count_deg_kernel() {
    int e = blockIdx.x * blockDim.x + threadIdx.x;
    if (e < N_EDGES) atomicAdd(&g_deg[g_edges[N_EDGES + e]], 1);
}

__global__ void scan_block_kernel() {
    __shared__ int s[1024];
    int g = blockIdx.x * 1024 + threadIdx.x;
    int v = (g < N_NODES) ? g_deg[g] : 0;
    s[threadIdx.x] = v;
    __syncthreads();
#pragma unroll
    for (int off = 1; off < 1024; off <<= 1) {
        int t = (threadIdx.x >= off) ? s[threadIdx.x - off] : 0;
        __syncthreads();
        s[threadIdx.x] += t;
        __syncthreads();
    }
    if (g < N_NODES) g_incl[g] = s[threadIdx.x];
    if (threadIdx.x == 1023) g_blockSums[blockIdx.x] = s[1023];
}

__global__ void scan_sums_kernel(int nb) {
    if (threadIdx.x == 0) {
        int run = 0;
        for (int i = 0; i < nb; i++) { int t = g_blockSums[i]; g_blockSums[i] = run; run += t; }
    }
}

__global__ void finalize_ptr_kernel() {
    int g = blockIdx.x * blockDim.x + threadIdx.x;
    if (g < N_NODES) g_ptr[g] = g_incl[g] - g_deg[g] + g_blockSums[g >> 10];
}

__global__ void fill_csr_kernel() {
    int e = blockIdx.x * blockDim.x + threadIdx.x;
    if (e < N_EDGES) {
        int s = g_edges[e];
        int d = g_edges[N_EDGES + e];
        int slot = atomicAdd(&g_cursor[d], 1);
        g_csr_idx[g_ptr[d] + slot] = s;
    }
}

// ---------------------------------------------------------------------------
// Gather aggregation, layer 1: O[i] = bf16(x[i] + sum_j x[j]), D=256 fp32 in
// ---------------------------------------------------------------------------
__global__ void __launch_bounds__(128)
gather_x_kernel(const float2* __restrict__ X, __nv_bfloat162* __restrict__ O) {
    int node = blockIdx.x;
    int t = threadIdx.x;
    float2 a = X[(size_t)node * 128 + t];
    int st = g_ptr[node];
    int de = g_deg[node];
    for (int q = 0; q < de; q++) {
        int j = g_csr_idx[st + q];
        float2 v = X[(size_t)j * 128 + t];
        a.x += v.x;
        a.y += v.y;
    }
    O[(size_t)node * 128 + t] = __nv_bfloat162(__float2bfloat16(a.x),
                                               __float2bfloat16(a.y));
}

// ---------------------------------------------------------------------------
// Gather aggregation, layer 2: O[i] = bf16(H[i] + sum_j H[j]), D=1024 bf16 in
// ---------------------------------------------------------------------------
__global__ void __launch_bounds__(128)
gather_h_kernel(const uint4* __restrict__ H, uint4* __restrict__ O) {
    int node = blockIdx.x;
    int t = threadIdx.x;
    uint4 sv = H[(size_t)node * 128 + t];
    float acc[8];
    {
        float2 p0 = __bfloat1622float2(*(__nv_bfloat162*)&sv.x);
        float2 p1 = __bfloat1622float2(*(__nv_bfloat162*)&sv.y);
        float2 p2 = __bfloat1622float2(*(__nv_bfloat162*)&sv.z);
        float2 p3 = __bfloat1622float2(*(__nv_bfloat162*)&sv.w);
        acc[0] = p0.x; acc[1] = p0.y; acc[2] = p1.x; acc[3] = p1.y;
        acc[4] = p2.x; acc[5] = p2.y; acc[6] = p3.x; acc[7] = p3.y;
    }
    int st = g_ptr[node];
    int de = g_deg[node];
    for (int q = 0; q < de; q++) {
        int j = g_csr_idx[st + q];
        uint4 v = H[(size_t)j * 128 + t];
        float2 p0 = __bfloat1622float2(*(__nv_bfloat162*)&v.x);
        float2 p1 = __bfloat1622float2(*(__nv_bfloat162*)&v.y);
        float2 p2 = __bfloat1622float2(*(__nv_bfloat162*)&v.z);
        float2 p3 = __bfloat1622float2(*(__nv_bfloat162*)&v.w);
        acc[0] += p0.x; acc[1] += p0.y; acc[2] += p1.x; acc[3] += p1.y;
        acc[4] += p2.x; acc[5] += p2.y; acc[6] += p3.x; acc[7] += p3.y;
    }
    uint4 o;
    *(__nv_bfloat162*)&o.x = __nv_bfloat162(__float2bfloat16(acc[0]), __float2bfloat16(acc[1]));
    *(__nv_bfloat162*)&o.y = __nv_bfloat162(__float2bfloat16(acc[2]), __float2bfloat16(acc[3]));
    *(__nv_bfloat162*)&o.z = __nv_bfloat162(__float2bfloat16(acc[4]), __float2bfloat16(acc[5]));
    *(__nv_bfloat162*)&o.w = __nv_bfloat162(__float2bfloat16(acc[6]), __float2bfloat16(acc[7]));
    O[(size_t)node * 128 + t] = o;
}

// ---------------------------------------------------------------------------
// Weight W[K,N] fp32 -> transposed Wt[Npad,K] bf16 hi (+ optional lo)
// ---------------------------------------------------------------------------
__global__ void split_weightT_kernel(const float* __restrict__ W,
                                     __nv_bfloat16* __restrict__ Th,
                                     __nv_bfloat16* __restrict__ Tl,
                                     int Kd, int Nd, int Npad) {
    int idx = blockIdx.x * blockDim.x + threadIdx.x;
    if (idx >= Kd * Npad) return;
    int n = idx / Kd;
    int k = idx % Kd;
    float v = (n < Nd) ? W[(size_t)k * Nd + n] : 0.0f;
    __nv_bfloat16 h = __float2bfloat16(v);
    Th[idx] = h;
    if (Tl) Tl[idx] = __float2bfloat16(v - __bfloat162float(h));
}

__global__ void pad_bias_kernel(const float* __restrict__ b, int n) {
    int i = threadIdx.x;
    if (i < 128) g_bfcPad[i] = (i < n) ? b[i] : 0.0f;
}

// ---------------------------------------------------------------------------
// bf16 split-compensated mma.sync GEMM:
//   C[M, ncols] = act(A[M,K] @ W[K,ncols] + bias)
// TERMS=1: pure bf16 (AhBh only), compact 32KB stages -> 2 CTAs/SM.
// TERMS=3: A and W split (classifier), 64KB stages, 1 CTA/SM.
// BM=128, BN=128, BK=64. 256 threads = 2x4 warps (64x32 per warp).
// 3-stage cp.async pipeline; SW128-swizzled SMEM; single-buffered ldsm frags
// (latency hidden by 16 warps/SM at occupancy 2).
// OUT: 0 = fp32 to C (stride ostride, col guard); 1 = bf16 hi+lo; 2 = bf16 hi.
// ---------------------------------------------------------------------------
template <int TERMS> struct SmemLayout {
    static constexpr uint32_t OFF_AL = 16384u;
    static constexpr uint32_t OFF_BH = (TERMS == 3) ? 32768u : 16384u;
    static constexpr uint32_t OFF_BL = (TERMS == 3) ? 49152u : 32768u;
    static constexpr uint32_t STAGE  = (TERMS == 3) ? 65536u
                                     : (TERMS == 2) ? 49152u : 32768u;
};

template <int K, int TERMS>
__device__ __forceinline__ void load_stage(uint32_t tbase, int stage,
    const __nv_bfloat16* __restrict__ Ah, const __nv_bfloat16* __restrict__ Al,
    const __nv_bfloat16* __restrict__ Bh, const __nv_bfloat16* __restrict__ Bl,
    int chunk, int rowBase, int colBase, int M) {
    using L = SmemLayout<TERMS>;
    const int tid = threadIdx.x;
    const uint32_t sBase = tbase + (uint32_t)stage * L::STAGE;
    const long kOff = (long)chunk * 64;
#pragma unroll
    for (int i = 0; i < 4; ++i) {
        int t = i * 256 + tid;            // 0..1023 16B chunks per 16KB tile
        int r = t >> 3;
        int cc = t & 7;
        uint32_t sw = (uint32_t)(r * 128 + ((cc ^ (r & 7)) << 4));
        int gr = rowBase + r;
        unsigned sz = (gr < M) ? 16u : 0u;
        int ga = gr < M ? gr : (M - 1);
        size_t aoff = ((size_t)ga * K + kOff + cc * 8) * 2;  // bytes
        cp_async16(sBase + sw, (const char*)Ah + aoff, sz);
        if (TERMS == 3)
            cp_async16(sBase + L::OFF_AL + sw, (const char*)Al + aoff, sz);
        int gn = colBase + r;
        size_t boff = ((size_t)gn * K + kOff + cc * 8) * 2;
        cp_async16(sBase + L::OFF_BH + sw, (const char*)Bh + boff, 16u);
        if (TERMS >= 2)
            cp_async16(sBase + L::OFF_BL + sw, (const char*)Bl + boff, 16u);
    }
}

struct Frags {
    uint32_t ah[4][4];
    uint32_t al[4][4];
    uint32_t bh[2][4];
    uint32_t bl[2][4];
};

template <int TERMS>
__device__ __forceinline__ void load_frags(uint32_t st, int k,
                                           const int* arow, const int* brow,
                                           int a_ck, int b_ck, Frags& f) {
    using L = SmemLayout<TERMS>;
    const uint32_t aHi = st, aLo = st + L::OFF_AL;
    const uint32_t bHi = st + L::OFF_BH, bLo = st + L::OFF_BL;
#pragma unroll
    for (int fm = 0; fm < 4; ++fm) {
        int row = arow[fm];
        int ck = k * 2 + a_ck;
        uint32_t off = (uint32_t)(row * 128 + ((ck ^ (row & 7)) << 4));
        ldsm4(f.ah[fm], aHi + off);
        if (TERMS == 3) ldsm4(f.al[fm], aLo + off);
    }
#pragma unroll
    for (int f2 = 0; f2 < 2; ++f2) {
        int row = brow[f2];
        int ck = k * 2 + b_ck;
        uint32_t off = (uint32_t)(row * 128 + ((ck ^ (row & 7)) << 4));
        ldsm4(f.bh[f2], bHi + off);
        if (TERMS >= 2) ldsm4(f.bl[f2], bLo + off);
    }
}

template <int TERMS>
__device__ __forceinline__ void mma_frags(const Frags& f, float acc[4][4][4]) {
#pragma unroll
    for (int fm = 0; fm < 4; ++fm)
#pragma unroll
        for (int fn = 0; fn < 4; ++fn) {
            const uint32_t* pbh = &f.bh[fn >> 1][(fn & 1) * 2];
            const uint32_t* pbl = &f.bl[fn >> 1][(fn & 1) * 2];
            mma_bf16(acc[fm][fn], f.ah[fm], pbh);                  // Ah*Bh
            if (TERMS >= 2) mma_bf16(acc[fm][fn], f.ah[fm], pbl);  // Ah*Bl
            if (TERMS == 3) mma_bf16(acc[fm][fn], f.al[fm], pbh);  // Al*Bh
        }
}

template <int K, bool RELU, int OUT, int TERMS>
__global__ void __launch_bounds__(256, TERMS == 1 ? 2 : 1)
gemm_bf16s_mma_kernel(const __nv_bfloat16* __restrict__ Ah,
                      const __nv_bfloat16* __restrict__ Al,
                      const __nv_bfloat16* __restrict__ Bh,
                      const __nv_bfloat16* __restrict__ Bl,
                      const float* __restrict__ bias,
                      float* __restrict__ C,
                      __nv_bfloat162* __restrict__ Oh,
                      __nv_bfloat162* __restrict__ Ol,
                      int M, int ostride, int ncols) {
    constexpr int NC = K / 64;
    using L = SmemLayout<TERMS>;
    extern __shared__ char smem[];
    const uint32_t tile_base = (s2u(smem) + 1023u) & ~1023u;

    const int tid = threadIdx.x;
    const int wid = tid >> 5;
    const int lane = tid & 31;
    const int wm = wid >> 2;          // 0..1
    const int wn = wid & 3;           // 0..3
    const int rowBase = blockIdx.y * 128;
    const int colBase = blockIdx.x * 128;

    const int midx = lane >> 3;
    const int l7 = lane & 7;
    const int a_ck = (midx >> 1);
    const int b_ck = (midx & 1);
    int arow[4], brow[2];
#pragma unroll
    for (int fm = 0; fm < 4; ++fm)
        arow[fm] = wm * 64 + fm * 16 + ((midx & 1) << 3) + l7;
#pragma unroll
    for (int f2 = 0; f2 < 2; ++f2)
        brow[f2] = wn * 32 + f2 * 16 + ((midx >> 1) << 3) + l7;

    float acc[4][4][4];
#pragma unroll
    for (int i = 0; i < 4; i++)
#pragma unroll
        for (int j = 0; j < 4; j++)
#pragma unroll
            for (int q = 0; q < 4; q++) acc[i][j][q] = 0.0f;

    // Prologue: prefetch chunks 0, 1
    load_stage<K, TERMS>(tile_base, 0, Ah, Al, Bh, Bl, 0, rowBase, colBase, M);
    asm volatile("cp.async.commit_group;" ::: "memory");
    load_stage<K, TERMS>(tile_base, 1, Ah, Al, Bh, Bl, 1, rowBase, colBase, M);
    asm volatile("cp.async.commit_group;" ::: "memory");

    Frags fr;
    for (int c = 0; c < NC; ++c) {
        if (c + 1 < NC) asm volatile("cp.async.wait_group 1;" ::: "memory");
        else            asm volatile("cp.async.wait_group 0;" ::: "memory");
        __syncthreads();
        const uint32_t st = tile_base + (uint32_t)(c % 3) * L::STAGE;
        if (c + 2 < NC) {
            load_stage<K, TERMS>(tile_base, (c + 2) % 3, Ah, Al, Bh, Bl,
                                 c + 2, rowBase, colBase, M);
            asm volatile("cp.async.commit_group;" ::: "memory");
        }
#pragma unroll
        for (int k = 0; k < 4; ++k) {
            load_frags<TERMS>(st, k, arow, brow, a_ck, b_ck, fr);
            mma_frags<TERMS>(fr, acc);
        }
    }

    // Epilogue: bias (+relu); fp32 strided / bf16 hi+lo / bf16 hi
    const int rowb = rowBase + wm * 64 + (lane >> 2);
    const int colb = colBase + wn * 32;
#pragma unroll
    for (int fm = 0; fm < 4; ++fm) {
        int r0 = rowb + fm * 16;
        int r1 = r0 + 8;
#pragma unroll
        for (int fn = 0; fn < 4; ++fn) {
            int col = colb + fn * 8 + (lane & 3) * 2;
            float2 bp = *reinterpret_cast<const float2*>(&bias[col]);
            float v0 = acc[fm][fn][0] + bp.x;
            float v1 = acc[fm][fn][1] + bp.y;
            float v2 = acc[fm][fn][2] + bp.x;
            float v3 = acc[fm][fn][3] + bp.y;
            if (RELU) {
                v0 = fmaxf(v0, 0.f); v1 = fmaxf(v1, 0.f);
                v2 = fmaxf(v2, 0.f); v3 = fmaxf(v3, 0.f);
            }
            if (OUT == 0) {
                if (col < ncols) {
                    if (r0 < M)
                        *reinterpret_cast<float2*>(&C[(size_t)r0 * ostride + col]) =
                            make_float2(v0, v1);
                    if (r1 < M)
                        *reinterpret_cast<float2*>(&C[(size_t)r1 * ostride + col]) =
                            make_float2(v2, v3);
                }
            } else {
                if (r0 < M) {
                    size_t h = ((size_t)r0 * ostride + col) >> 1;
                    __nv_bfloat16 h0 = __float2bfloat16(v0);
                    __nv_bfloat16 h1 = __float2bfloat16(v1);
                    Oh[h] = __nv_bfloat162(h0, h1);
                    if (OUT == 1)
                        Ol[h] = __nv_bfloat162(
                            __float2bfloat16(v0 - __bfloat162float(h0)),
                            __float2bfloat16(v1 - __bfloat162float(h1)));
                }
                if (r1 < M) {
                    size_t h = ((size_t)r1 * ostride + col) >> 1;
                    __nv_bfloat16 h2 = __float2bfloat16(v2);
                    __nv_bfloat16 h3 = __float2bfloat16(v3);
                    Oh[h] = __nv_bfloat162(h2, h3);
                    if (OUT == 1)
                        Ol[h] = __nv_bfloat162(
                            __float2bfloat16(v2 - __bfloat162float(h2)),
                            __float2bfloat16(v3 - __bfloat162float(h3)));
                }
            }
        }
    }
}

// ---------------------------------------------------------------------------
// In-place log_softmax over 64 classes, one warp per row
// ---------------------------------------------------------------------------
__global__ void log_softmax64_kernel(float* __restrict__ out, int M) {
    int warp = (blockIdx.x * blockDim.x + threadIdx.x) >> 5;
    int lane = threadIdx.x & 31;
    if (warp >= M) return;
    float* row = out + (size_t)warp * N_CLS;
    float a = row[lane];
    float b = row[lane + 32];
    float m = fmaxf(a, b);
#pragma unroll
    for (int o = 16; o > 0; o >>= 1)
        m = fmaxf(m, __shfl_xor_sync(0xFFFFFFFFu, m, o));
    float s = expf(a - m) + expf(b - m);
#pragma unroll
    for (int o = 16; o > 0; o >>= 1)
        s += __shfl_xor_sync(0xFFFFFFFFu, s, o);
    float lse = m + logf(s);
    row[lane]      = a - lse;
    row[lane + 32] = b - lse;
}

// ---------------------------------------------------------------------------
// Launch
// ---------------------------------------------------------------------------
extern "C" void kernel_launch(void* const* d_in, const int* in_sizes, int n_in,
                              void* d_out, int out_size) {
    const float*        x   = (const float*)d_in[0];
    const unsigned int* ei  = (const unsigned int*)d_in[1];
    const float* W1a = (const float*)d_in[2];
    const float* b1a = (const float*)d_in[3];
    const float* W1b = (const float*)d_in[4];
    const float* b1b = (const float*)d_in[5];
    const float* W2a = (const float*)d_in[6];
    const float* b2a = (const float*)d_in[7];
    const float* W2b = (const float*)d_in[8];
    const float* b2b = (const float*)d_in[9];
    const float* Wfc = (const float*)d_in[10];
    const float* bfc = (const float*)d_in[11];
    float* out = (float*)d_out;

    float *bfcPad;
    __nv_bfloat16 *Ah, *Al, *Ch, *Wh, *Wl;
    cudaGetSymbolAddress((void**)&Ah, g_Ah);
    cudaGetSymbolAddress((void**)&Al, g_Al);
    cudaGetSymbolAddress((void**)&Ch, g_Ch);
    cudaGetSymbolAddress((void**)&Wh, g_Wh);
    cudaGetSymbolAddress((void**)&Wl, g_Wl);
    cudaGetSymbolAddress((void**)&bfcPad, g_bfcPad);

    // TERMS=1: 3 x 32KB stages + align slack -> 2 CTAs/SM
    const int GEMM_SMEM1 = 3 * 32768 + 1024;   // 99328 B
    // TERMS=3: 3 x 64KB stages + align slack -> 1 CTA/SM
    const int GEMM_SMEM3 = 3 * 65536 + 1024;   // 197632 B
    cudaFuncSetAttribute(gemm_bf16s_mma_kernel<256, true, 2, 1>,
                         cudaFuncAttributeMaxDynamicSharedMemorySize, GEMM_SMEM1);
    cudaFuncSetAttribute(gemm_bf16s_mma_kernel<1024, true, 2, 1>,
                         cudaFuncAttributeMaxDynamicSharedMemorySize, GEMM_SMEM1);
    cudaFuncSetAttribute(gemm_bf16s_mma_kernel<1024, false, 1, 1>,
                         cudaFuncAttributeMaxDynamicSharedMemorySize, GEMM_SMEM1);
    cudaFuncSetAttribute(gemm_bf16s_mma_kernel<1024, false, 0, 3>,
                         cudaFuncAttributeMaxDynamicSharedMemorySize, GEMM_SMEM3);

    // ---- Edge normalization + CSR build ----
    detect_idx_kernel<<<1, 256>>>(ei);
    convert_idx_kernel<<<(2 * N_EDGES + 255) / 256, 256>>>(ei);
    zero_csr_kernel<<<(N_NODES + 255) / 256, 256>>>();
    count_deg_kernel<<<(N_EDGES + 255) / 256, 256>>>();
    const int NB = (N_NODES + 1023) / 1024;   // 98
    scan_block_kernel<<<NB, 1024>>>();
    scan_sums_kernel<<<1, 32>>>(NB);
    finalize_ptr_kernel<<<(N_NODES + 255) / 256, 256>>>();
    fill_csr_kernel<<<(N_EDGES + 255) / 256, 256>>>();

    dim3 gridGemm(HID / 128, (N_NODES + 127) / 128);   // (8, 782)
    dim3 gridFC(1, (N_NODES + 127) / 128);

    // ---- Layer 1: Ah = bf16(x + gather(x)) ----
    gather_x_kernel<<<N_NODES, 128>>>((const float2*)x, (__nv_bfloat162*)Ah);
    // GEMM1a: Ch = bf16(relu(Ah @ W1a + b1a))   [1-term]
    split_weightT_kernel<<<(D_IN * HID + 255) / 256, 256>>>(
        W1a, Wh, nullptr, D_IN, HID, HID);
    gemm_bf16s_mma_kernel<256, true, 2, 1><<<gridGemm, 256, GEMM_SMEM1>>>(
        Ah, nullptr, Wh, nullptr, b1a, nullptr,
        (__nv_bfloat162*)Ch, nullptr, N_NODES, HID, HID);
    // GEMM1b: Ah = bf16(relu(Ch @ W1b + b1b)) = h1   [1-term]
    split_weightT_kernel<<<(HID * HID + 255) / 256, 256>>>(
        W1b, Wh, nullptr, HID, HID, HID);
    gemm_bf16s_mma_kernel<1024, true, 2, 1><<<gridGemm, 256, GEMM_SMEM1>>>(
        Ch, nullptr, Wh, nullptr, b1b, nullptr,
        (__nv_bfloat162*)Ah, nullptr, N_NODES, HID, HID);

    // ---- Layer 2: Ch = bf16(h1 + gather(h1)) ----
    gather_h_kernel<<<N_NODES, 128>>>((const uint4*)Ah, (uint4*)Ch);
    // GEMM2a: Ah = bf16(relu(Ch @ W2a + b2a))   [1-term]
    split_weightT_kernel<<<(HID * HID + 255) / 256, 256>>>(
        W2a, Wh, nullptr, HID, HID, HID);
    gemm_bf16s_mma_kernel<1024, true, 2, 1><<<gridGemm, 256, GEMM_SMEM1>>>(
        Ch, nullptr, Wh, nullptr, b2a, nullptr,
        (__nv_bfloat162*)Ah, nullptr, N_NODES, HID, HID);
    // GEMM2b: (Ch, Al) = split(Ah @ W2b + b2b) = h2 hi/lo   [1-term, split out]
    split_weightT_kernel<<<(HID * HID + 255) / 256, 256>>>(
        W2b, Wh, nullptr, HID, HID, HID);
    gemm_bf16s_mma_kernel<1024, false, 1, 1><<<gridGemm, 256, GEMM_SMEM1>>>(
        Ah, nullptr, Wh, nullptr, b2b, nullptr,
        (__nv_bfloat162*)Ch, (__nv_bfloat162*)Al, N_NODES, HID, HID);

    // ---- Classifier (3-term, N padded 64->128) + log_softmax ----
    pad_bias_kernel<<<1, 128>>>(bfc, N_CLS);
    split_weightT_kernel<<<(HID * 128 + 255) / 256, 256>>>(
        Wfc, Wh, Wl, HID, N_CLS, 128);
    gemm_bf16s_mma_kernel<1024, false, 0, 3><<<gridFC, 256, GEMM_SMEM3>>>(
        Ch, Al, Wh, Wl, bfcPad, out, nullptr, nullptr, N_NODES, N_CLS, N_CLS);
    log_softmax64_kernel<<<(N_NODES * 32 + 255) / 256, 256>>>(out, N_NODES);
}

// round 14
// speedup vs baseline: 9.6296x; 1.2565x over previous
#include <cuda_runtime.h>
#include <cuda_bf16.h>
#include <math.h>
#include <stdint.h>

// Problem constants (fixed by the reference)
#define N_NODES  100000
#define N_EDGES  300000
#define D_IN     256
#define HID      1024
#define N_CLS    64

// ---------------------------------------------------------------------------
// Scratch (device globals: allocation-free)
// ---------------------------------------------------------------------------
__device__ __nv_bfloat16 g_Ah[(size_t)N_NODES * HID];       // act bf16 ping
__device__ __nv_bfloat16 g_Ch[(size_t)N_NODES * HID];       // act bf16 pong
__device__ __nv_bfloat16 g_Wh[(size_t)HID * HID];           // weight^T hi
__device__ __nv_bfloat16 g_WcTh[128 * HID];                 // composed cls W^T hi
__device__ __nv_bfloat16 g_WcTl[128 * HID];                 // composed cls W^T lo
__device__ float g_bfcPad[128];                             // composed cls bias
__device__ int   g_edges[2 * N_EDGES];
__device__ int   g_idx64;
// CSR scratch
__device__ int g_deg[N_NODES];
__device__ int g_incl[N_NODES];
__device__ int g_ptr[N_NODES];
__device__ int g_cursor[N_NODES];
__device__ int g_blockSums[128];
__device__ int g_csr_idx[N_EDGES];

// ---------------------------------------------------------------------------
// PTX helpers (all sm_80-era: valid under compute_103, no 'a' features)
// ---------------------------------------------------------------------------
__device__ __forceinline__ uint32_t s2u(const void* p) {
    uint32_t a;
    asm("{ .reg .u64 t; cvta.to.shared.u64 t, %1; cvt.u32.u64 %0, t; }"
        : "=r"(a) : "l"(p));
    return a;
}

__device__ __forceinline__ void cp_async16(uint32_t s, const void* g, unsigned sz) {
    asm volatile("cp.async.cg.shared.global [%0], [%1], 16, %2;"
                 :: "r"(s), "l"(g), "r"(sz));
}

__device__ __forceinline__ void ldsm4(uint32_t* r, uint32_t addr) {
    asm volatile("ldmatrix.sync.aligned.m8n8.x4.shared.b16 {%0,%1,%2,%3}, [%4];"
                 : "=r"(r[0]), "=r"(r[1]), "=r"(r[2]), "=r"(r[3]) : "r"(addr));
}

__device__ __forceinline__ void mma_bf16(float* d, const uint32_t* a,
                                         const uint32_t* b) {
    asm volatile(
        "mma.sync.aligned.m16n8k16.row.col.f32.bf16.bf16.f32 "
        "{%0,%1,%2,%3},{%4,%5,%6,%7},{%8,%9},{%0,%1,%2,%3};"
        : "+f"(d[0]), "+f"(d[1]), "+f"(d[2]), "+f"(d[3])
        : "r"(a[0]), "r"(a[1]), "r"(a[2]), "r"(a[3]), "r"(b[0]), "r"(b[1]));
}

// ---------------------------------------------------------------------------
// Edge-index dtype detection + normalization
// ---------------------------------------------------------------------------
__global__ void detect_idx_kernel(const unsigned int* __restrict__ ei) {
    unsigned v = ei[2 * threadIdx.x + 1];
    int any = __syncthreads_or(v != 0u);
    if (threadIdx.x == 0) g_idx64 = any ? 0 : 1;
}

__global__ void convert_idx_kernel(const unsigned int* __restrict__ ei) {
    int i = blockIdx.x * blockDim.x + threadIdx.x;
    if (i < 2 * N_EDGES) g_edges[i] = g_idx64 ? (int)ei[2 * i] : (int)ei[i];
}

// ---------------------------------------------------------------------------
// CSR build: degree count -> block scan -> ptr -> atomic-slot fill
// ---------------------------------------------------------------------------
__global__ void zero_csr_kernel() {
    int i = blockIdx.x * blockDim.x + threadIdx.x;
    if (i < N_NODES) { g_deg[i] = 0; g_cursor[i] = 0; }
}

__global__ void count_deg_kernel() {
    int e = blockIdx.x * blockDim.x + threadIdx.x;
    if (e < N_EDGES) atomicAdd(&g_deg[g_edges[N_EDGES + e]], 1);
}

__global__ void scan_block_kernel() {
    __shared__ int s[1024];
    int g = blockIdx.x * 1024 + threadIdx.x;
    int v = (g < N_NODES) ? g_deg[g] : 0;
    s[threadIdx.x] = v;
    __syncthreads();
#pragma unroll
    for (int off = 1; off < 1024; off <<= 1) {
        int t = (threadIdx.x >= off) ? s[threadIdx.x - off] : 0;
        __syncthreads();
        s[threadIdx.x] += t;
        __syncthreads();
    }
    if (g < N_NODES) g_incl[g] = s[threadIdx.x];
    if (threadIdx.x == 1023) g_blockSums[blockIdx.x] = s[1023];
}

__global__ void scan_sums_kernel(int nb) {
    if (threadIdx.x == 0) {
        int run = 0;
        for (int i = 0; i < nb; i++) { int t = g_blockSums[i]; g_blockSums[i] = run; run += t; }
    }
}

__global__ void finalize_ptr_kernel() {
    int g = blockIdx.x * blockDim.x + threadIdx.x;
    if (g < N_NODES) g_ptr[g] = g_incl[g] - g_deg[g] + g_blockSums[g >> 10];
}

__global__ void fill_csr_kernel() {
    int e = blockIdx.x * blockDim.x + threadIdx.x;
    if (e < N_EDGES) {
        int s = g_edges[e];
        int d = g_edges[N_EDGES + e];
        int slot = atomicAdd(&g_cursor[d], 1);
        g_csr_idx[g_ptr[d] + slot] = s;
    }
}

// ---------------------------------------------------------------------------
// Gather aggregation, layer 1: O[i] = bf16(x[i] + sum_j x[j]), D=256 fp32 in
// ---------------------------------------------------------------------------
__global__ void __launch_bounds__(128)
gather_x_kernel(const float2* __restrict__ X, __nv_bfloat162* __restrict__ O) {
    int node = blockIdx.x;
    int t = threadIdx.x;
    float2 a = X[(size_t)node * 128 + t];
    int st = g_ptr[node];
    int de = g_deg[node];
    for (int q = 0; q < de; q++) {
        int j = g_csr_idx[st + q];
        float2 v = X[(size_t)j * 128 + t];
        a.x += v.x;
        a.y += v.y;
    }
    O[(size_t)node * 128 + t] = __nv_bfloat162(__float2bfloat16(a.x),
                                               __float2bfloat16(a.y));
}

// ---------------------------------------------------------------------------
// Gather aggregation, layer 2: O[i] = bf16(H[i] + sum_j H[j]), D=1024 bf16 in
// ---------------------------------------------------------------------------
__global__ void __launch_bounds__(128)
gather_h_kernel(const uint4* __restrict__ H, uint4* __restrict__ O) {
    int node = blockIdx.x;
    int t = threadIdx.x;
    uint4 sv = H[(size_t)node * 128 + t];
    float acc[8];
    {
        float2 p0 = __bfloat1622float2(*(__nv_bfloat162*)&sv.x);
        float2 p1 = __bfloat1622float2(*(__nv_bfloat162*)&sv.y);
        float2 p2 = __bfloat1622float2(*(__nv_bfloat162*)&sv.z);
        float2 p3 = __bfloat1622float2(*(__nv_bfloat162*)&sv.w);
        acc[0] = p0.x; acc[1] = p0.y; acc[2] = p1.x; acc[3] = p1.y;
        acc[4] = p2.x; acc[5] = p2.y; acc[6] = p3.x; acc[7] = p3.y;
    }
    int st = g_ptr[node];
    int de = g_deg[node];
    for (int q = 0; q < de; q++) {
        int j = g_csr_idx[st + q];
        uint4 v = H[(size_t)j * 128 + t];
        float2 p0 = __bfloat1622float2(*(__nv_bfloat162*)&v.x);
        float2 p1 = __bfloat1622float2(*(__nv_bfloat162*)&v.y);
        float2 p2 = __bfloat1622float2(*(__nv_bfloat162*)&v.z);
        float2 p3 = __bfloat1622float2(*(__nv_bfloat162*)&v.w);
        acc[0] += p0.x; acc[1] += p0.y; acc[2] += p1.x; acc[3] += p1.y;
        acc[4] += p2.x; acc[5] += p2.y; acc[6] += p3.x; acc[7] += p3.y;
    }
    uint4 o;
    *(__nv_bfloat162*)&o.x = __nv_bfloat162(__float2bfloat16(acc[0]), __float2bfloat16(acc[1]));
    *(__nv_bfloat162*)&o.y = __nv_bfloat162(__float2bfloat16(acc[2]), __float2bfloat16(acc[3]));
    *(__nv_bfloat162*)&o.z = __nv_bfloat162(__float2bfloat16(acc[4]), __float2bfloat16(acc[5]));
    *(__nv_bfloat162*)&o.w = __nv_bfloat162(__float2bfloat16(acc[6]), __float2bfloat16(acc[7]));
    O[(size_t)node * 128 + t] = o;
}

// ---------------------------------------------------------------------------
// Coalesced weight transpose: W[Kd,Nd] fp32 -> Wt[Nd,Kd] bf16 (32x32 SMEM tile)
// Kd, Nd are multiples of 32 for all uses.
// ---------------------------------------------------------------------------
__global__ void __launch_bounds__(1024)
weightT_kernel(const float* __restrict__ W, __nv_bfloat16* __restrict__ Th,
               int Kd, int Nd) {
    __shared__ float tile[32][33];
    int n = blockIdx.x * 32 + threadIdx.x;
    int k = blockIdx.y * 32 + threadIdx.y;
    tile[threadIdx.y][threadIdx.x] = W[(size_t)k * Nd + n];
    __syncthreads();
    int ko = blockIdx.y * 32 + threadIdx.x;
    int no = blockIdx.x * 32 + threadIdx.y;
    Th[(size_t)no * Kd + ko] = __float2bfloat16(tile[threadIdx.x][threadIdx.y]);
}

// ---------------------------------------------------------------------------
// Classifier composition: Wcomb = W2b @ Wfc (fp32), written transposed + split
//   WcT[j][k] = sum_n W2b[k][n] * Wfc[n][j],  j<64 (rows 64..127 zero-padded)
// ---------------------------------------------------------------------------
__global__ void __launch_bounds__(256)
compose_cls_kernel(const float* __restrict__ W2b, const float* __restrict__ Wfc,
                   __nv_bfloat16* __restrict__ Th, __nv_bfloat16* __restrict__ Tl) {
    int j = threadIdx.x;                       // 0..63
    int k = blockIdx.x * 4 + threadIdx.y;      // 0..1023
    const float* wrow = W2b + (size_t)k * HID;
    float acc = 0.0f;
#pragma unroll 4
    for (int n = 0; n < HID; ++n)
        acc = fmaf(wrow[n], Wfc[(size_t)n * N_CLS + j], acc);
    __nv_bfloat16 h = __float2bfloat16(acc);
    Th[(size_t)j * HID + k] = h;
    Tl[(size_t)j * HID + k] = __float2bfloat16(acc - __bfloat162float(h));
}

__global__ void zero_pad_cls_kernel(__nv_bfloat16* __restrict__ Th,
                                    __nv_bfloat16* __restrict__ Tl) {
    int i = blockIdx.x * 256 + threadIdx.x;    // 64*1024 pad elements
    if (i < 64 * HID) {
        Th[64 * HID + i] = __float2bfloat16(0.0f);
        Tl[64 * HID + i] = __float2bfloat16(0.0f);
    }
}

__global__ void compose_bias_kernel(const float* __restrict__ b2b,
                                    const float* __restrict__ Wfc,
                                    const float* __restrict__ bfc) {
    int j = threadIdx.x;                       // 0..127
    float acc = 0.0f;
    if (j < N_CLS) {
#pragma unroll 4
        for (int n = 0; n < HID; ++n)
            acc = fmaf(b2b[n], Wfc[(size_t)n * N_CLS + j], acc);
        acc += bfc[j];
    }
    g_bfcPad[j] = acc;
}

// ---------------------------------------------------------------------------
// bf16 split-compensated mma.sync GEMM:
//   C[M, ncols] = act(A[M,K] @ W[K,ncols] + bias)
// TERMS=1: pure bf16 (AhBh only), compact 32KB stages -> 2 CTAs/SM.
// TERMS=2: W split; AhBh + AhBl (classifier), 48KB stages.
// BM=128, BN=128, BK=64. 256 threads = 2x4 warps (64x32 per warp).
// 3-stage cp.async pipeline; SW128-swizzled SMEM.
// OUT: 0 = fp32 to C (stride ostride, col guard); 2 = bf16 hi.
// ---------------------------------------------------------------------------
template <int TERMS> struct SmemLayout {
    static constexpr uint32_t OFF_BH = 16384u;
    static constexpr uint32_t OFF_BL = 32768u;
    static constexpr uint32_t STAGE  = (TERMS == 2) ? 49152u : 32768u;
};

template <int K, int TERMS>
__device__ __forceinline__ void load_stage(uint32_t tbase, int stage,
    const __nv_bfloat16* __restrict__ Ah,
    const __nv_bfloat16* __restrict__ Bh, const __nv_bfloat16* __restrict__ Bl,
    int chunk, int rowBase, int colBase, int M) {
    using L = SmemLayout<TERMS>;
    const int tid = threadIdx.x;
    const uint32_t sBase = tbase + (uint32_t)stage * L::STAGE;
    const long kOff = (long)chunk * 64;
#pragma unroll
    for (int i = 0; i < 4; ++i) {
        int t = i * 256 + tid;            // 0..1023 16B chunks per 16KB tile
        int r = t >> 3;
        int cc = t & 7;
        uint32_t sw = (uint32_t)(r * 128 + ((cc ^ (r & 7)) << 4));
        int gr = rowBase + r;
        unsigned sz = (gr < M) ? 16u : 0u;
        int ga = gr < M ? gr : (M - 1);
        size_t aoff = ((size_t)ga * K + kOff + cc * 8) * 2;  // bytes
        cp_async16(sBase + sw, (const char*)Ah + aoff, sz);
        int gn = colBase + r;
        size_t boff = ((size_t)gn * K + kOff + cc * 8) * 2;
        cp_async16(sBase + L::OFF_BH + sw, (const char*)Bh + boff, 16u);
        if (TERMS >= 2)
            cp_async16(sBase + L::OFF_BL + sw, (const char*)Bl + boff, 16u);
    }
}

struct Frags {
    uint32_t ah[4][4];
    uint32_t bh[2][4];
    uint32_t bl[2][4];
};

template <int TERMS>
__device__ __forceinline__ void load_frags(uint32_t st, int k,
                                           const int* arow, const int* brow,
                                           int a_ck, int b_ck, Frags& f) {
    using L = SmemLayout<TERMS>;
    const uint32_t aHi = st;
    const uint32_t bHi = st + L::OFF_BH, bLo = st + L::OFF_BL;
#pragma unroll
    for (int fm = 0; fm < 4; ++fm) {
        int row = arow[fm];
        int ck = k * 2 + a_ck;
        uint32_t off = (uint32_t)(row * 128 + ((ck ^ (row & 7)) << 4));
        ldsm4(f.ah[fm], aHi + off);
    }
#pragma unroll
    for (int f2 = 0; f2 < 2; ++f2) {
        int row = brow[f2];
        int ck = k * 2 + b_ck;
        uint32_t off = (uint32_t)(row * 128 + ((ck ^ (row & 7)) << 4));
        ldsm4(f.bh[f2], bHi + off);
        if (TERMS >= 2) ldsm4(f.bl[f2], bLo + off);
    }
}

template <int TERMS>
__device__ __forceinline__ void mma_frags(const Frags& f, float acc[4][4][4]) {
#pragma unroll
    for (int fm = 0; fm < 4; ++fm)
#pragma unroll
        for (int fn = 0; fn < 4; ++fn) {
            const uint32_t* pbh = &f.bh[fn >> 1][(fn & 1) * 2];
            const uint32_t* pbl = &f.bl[fn >> 1][(fn & 1) * 2];
            mma_bf16(acc[fm][fn], f.ah[fm], pbh);                  // Ah*Bh
            if (TERMS >= 2) mma_bf16(acc[fm][fn], f.ah[fm], pbl);  // Ah*Bl
        }
}

template <int K, bool RELU, int OUT, int TERMS>
__global__ void __launch_bounds__(256, TERMS == 1 ? 2 : 1)
gemm_bf16s_mma_kernel(const __nv_bfloat16* __restrict__ Ah,
                      const __nv_bfloat16* __restrict__ Bh,
                      const __nv_bfloat16* __restrict__ Bl,
                      const float* __restrict__ bias,
                      float* __restrict__ C,
                      __nv_bfloat162* __restrict__ Oh,
                      int M, int ostride, int ncols) {
    constexpr int NC = K / 64;
    using L = SmemLayout<TERMS>;
    extern __shared__ char smem[];
    const uint32_t tile_base = (s2u(smem) + 1023u) & ~1023u;

    const int tid = threadIdx.x;
    const int wid = tid >> 5;
    const int lane = tid & 31;
    const int wm = wid >> 2;          // 0..1
    const int wn = wid & 3;           // 0..3
    const int rowBase = blockIdx.y * 128;
    const int colBase = blockIdx.x * 128;

    const int midx = lane >> 3;
    const int l7 = lane & 7;
    const int a_ck = (midx >> 1);
    const int b_ck = (midx & 1);
    int arow[4], brow[2];
#pragma unroll
    for (int fm = 0; fm < 4; ++fm)
        arow[fm] = wm * 64 + fm * 16 + ((midx & 1) << 3) + l7;
#pragma unroll
    for (int f2 = 0; f2 < 2; ++f2)
        brow[f2] = wn * 32 + f2 * 16 + ((midx >> 1) << 3) + l7;

    float acc[4][4][4];
#pragma unroll
    for (int i = 0; i < 4; i++)
#pragma unroll
        for (int j = 0; j < 4; j++)
#pragma unroll
            for (int q = 0; q < 4; q++) acc[i][j][q] = 0.0f;

    // Prologue: prefetch chunks 0, 1
    load_stage<K, TERMS>(tile_base, 0, Ah, Bh, Bl, 0, rowBase, colBase, M);
    asm volatile("cp.async.commit_group;" ::: "memory");
    load_stage<K, TERMS>(tile_base, 1, Ah, Bh, Bl, 1, rowBase, colBase, M);
    asm volatile("cp.async.commit_group;" ::: "memory");

    Frags fr;
    for (int c = 0; c < NC; ++c) {
        if (c + 1 < NC) asm volatile("cp.async.wait_group 1;" ::: "memory");
        else            asm volatile("cp.async.wait_group 0;" ::: "memory");
        __syncthreads();
        const uint32_t st = tile_base + (uint32_t)(c % 3) * L::STAGE;
        if (c + 2 < NC) {
            load_stage<K, TERMS>(tile_base, (c + 2) % 3, Ah, Bh, Bl,
                                 c + 2, rowBase, colBase, M);
            asm volatile("cp.async.commit_group;" ::: "memory");
        }
#pragma unroll
        for (int k = 0; k < 4; ++k) {
            load_frags<TERMS>(st, k, arow, brow, a_ck, b_ck, fr);
            mma_frags<TERMS>(fr, acc);
        }
    }

    // Epilogue: bias (+relu); fp32 strided (col guard) or bf16 hi
    const int rowb = rowBase + wm * 64 + (lane >> 2);
    const int colb = colBase + wn * 32;
#pragma unroll
    for (int fm = 0; fm < 4; ++fm) {
        int r0 = rowb + fm * 16;
        int r1 = r0 + 8;
#pragma unroll
        for (int fn = 0; fn < 4; ++fn) {
            int col = colb + fn * 8 + (lane & 3) * 2;
            float2 bp = *reinterpret_cast<const float2*>(&bias[col]);
            float v0 = acc[fm][fn][0] + bp.x;
            float v1 = acc[fm][fn][1] + bp.y;
            float v2 = acc[fm][fn][2] + bp.x;
            float v3 = acc[fm][fn][3] + bp.y;
            if (RELU) {
                v0 = fmaxf(v0, 0.f); v1 = fmaxf(v1, 0.f);
                v2 = fmaxf(v2, 0.f); v3 = fmaxf(v3, 0.f);
            }
            if (OUT == 0) {
                if (col < ncols) {
                    if (r0 < M)
                        *reinterpret_cast<float2*>(&C[(size_t)r0 * ostride + col]) =
                            make_float2(v0, v1);
                    if (r1 < M)
                        *reinterpret_cast<float2*>(&C[(size_t)r1 * ostride + col]) =
                            make_float2(v2, v3);
                }
            } else {
                if (r0 < M) {
                    size_t h = ((size_t)r0 * ostride + col) >> 1;
                    Oh[h] = __nv_bfloat162(__float2bfloat16(v0),
                                           __float2bfloat16(v1));
                }
                if (r1 < M) {
                    size_t h = ((size_t)r1 * ostride + col) >> 1;
                    Oh[h] = __nv_bfloat162(__float2bfloat16(v2),
                                           __float2bfloat16(v3));
                }
            }
        }
    }
}

// ---------------------------------------------------------------------------
// In-place log_softmax over 64 classes, one warp per row
// ---------------------------------------------------------------------------
__global__ void log_softmax64_kernel(float* __restrict__ out, int M) {
    int warp = (blockIdx.x * blockDim.x + threadIdx.x) >> 5;
    int lane = threadIdx.x & 31;
    if (warp >= M) return;
    float* row = out + (size_t)warp * N_CLS;
    float a = row[lane];
    float b = row[lane + 32];
    float m = fmaxf(a, b);
#pragma unroll
    for (int o = 16; o > 0; o >>= 1)
        m = fmaxf(m, __shfl_xor_sync(0xFFFFFFFFu, m, o));
    float s = expf(a - m) + expf(b - m);
#pragma unroll
    for (int o = 16; o > 0; o >>= 1)
        s += __shfl_xor_sync(0xFFFFFFFFu, s, o);
    float lse = m + logf(s);
    row[lane]      = a - lse;
    row[lane + 32] = b - lse;
}

// ---------------------------------------------------------------------------
// Launch
// ---------------------------------------------------------------------------
extern "C" void kernel_launch(void* const* d_in, const int* in_sizes, int n_in,
                              void* d_out, int out_size) {
    const float*        x   = (const float*)d_in[0];
    const unsigned int* ei  = (const unsigned int*)d_in[1];
    const float* W1a = (const float*)d_in[2];
    const float* b1a = (const float*)d_in[3];
    const float* W1b = (const float*)d_in[4];
    const float* b1b = (const float*)d_in[5];
    const float* W2a = (const float*)d_in[6];
    const float* b2a = (const float*)d_in[7];
    const float* W2b = (const float*)d_in[8];
    const float* b2b = (const float*)d_in[9];
    const float* Wfc = (const float*)d_in[10];
    const float* bfc = (const float*)d_in[11];
    float* out = (float*)d_out;

    float *bfcPad;
    __nv_bfloat16 *Ah, *Ch, *Wh, *WcTh, *WcTl;
    cudaGetSymbolAddress((void**)&Ah, g_Ah);
    cudaGetSymbolAddress((void**)&Ch, g_Ch);
    cudaGetSymbolAddress((void**)&Wh, g_Wh);
    cudaGetSymbolAddress((void**)&WcTh, g_WcTh);
    cudaGetSymbolAddress((void**)&WcTl, g_WcTl);
    cudaGetSymbolAddress((void**)&bfcPad, g_bfcPad);

    // TERMS=1: 3 x 32KB stages -> 2 CTAs/SM.  TERMS=2: 3 x 48KB stages.
    const int GEMM_SMEM1 = 3 * 32768 + 1024;   // 99328 B
    const int GEMM_SMEM2 = 3 * 49152 + 1024;   // 148480 B
    cudaFuncSetAttribute(gemm_bf16s_mma_kernel<256, true, 2, 1>,
                         cudaFuncAttributeMaxDynamicSharedMemorySize, GEMM_SMEM1);
    cudaFuncSetAttribute(gemm_bf16s_mma_kernel<1024, true, 2, 1>,
                         cudaFuncAttributeMaxDynamicSharedMemorySize, GEMM_SMEM1);
    cudaFuncSetAttribute(gemm_bf16s_mma_kernel<1024, false, 0, 2>,
                         cudaFuncAttributeMaxDynamicSharedMemorySize, GEMM_SMEM2);

    // ---- Edge normalization + CSR build ----
    detect_idx_kernel<<<1, 256>>>(ei);
    convert_idx_kernel<<<(2 * N_EDGES + 255) / 256, 256>>>(ei);
    zero_csr_kernel<<<(N_NODES + 255) / 256, 256>>>();
    count_deg_kernel<<<(N_EDGES + 255) / 256, 256>>>();
    const int NB = (N_NODES + 1023) / 1024;   // 98
    scan_block_kernel<<<NB, 1024>>>();
    scan_sums_kernel<<<1, 32>>>(NB);
    finalize_ptr_kernel<<<(N_NODES + 255) / 256, 256>>>();
    fill_csr_kernel<<<(N_EDGES + 255) / 256, 256>>>();

    // ---- Classifier composition (independent of activations) ----
    compose_cls_kernel<<<HID / 4, dim3(64, 4)>>>(W2b, Wfc, WcTh, WcTl);
    zero_pad_cls_kernel<<<(64 * HID + 255) / 256, 256>>>(WcTh, WcTl);
    compose_bias_kernel<<<1, 128>>>(b2b, Wfc, bfc);

    dim3 gridGemm(HID / 128, (N_NODES + 127) / 128);   // (8, 782)
    dim3 gridFC(1, (N_NODES + 127) / 128);

    // ---- Layer 1: Ah = bf16(x + gather(x)) ----
    gather_x_kernel<<<N_NODES, 128>>>((const float2*)x, (__nv_bfloat162*)Ah);
    // GEMM1a: Ch = bf16(relu(Ah @ W1a + b1a))   [1-term]
    weightT_kernel<<<dim3(HID / 32, D_IN / 32), dim3(32, 32)>>>(W1a, Wh, D_IN, HID);
    gemm_bf16s_mma_kernel<256, true, 2, 1><<<gridGemm, 256, GEMM_SMEM1>>>(
        Ah, Wh, nullptr, b1a, nullptr, (__nv_bfloat162*)Ch, N_NODES, HID, HID);
    // GEMM1b: Ah = bf16(relu(Ch @ W1b + b1b)) = h1   [1-term]
    weightT_kernel<<<dim3(HID / 32, HID / 32), dim3(32, 32)>>>(W1b, Wh, HID, HID);
    gemm_bf16s_mma_kernel<1024, true, 2, 1><<<gridGemm, 256, GEMM_SMEM1>>>(
        Ch, Wh, nullptr, b1b, nullptr, (__nv_bfloat162*)Ah, N_NODES, HID, HID);

    // ---- Layer 2: Ch = bf16(h1 + gather(h1)) ----
    gather_h_kernel<<<N_NODES, 128>>>((const uint4*)Ah, (uint4*)Ch);
    // GEMM2a: Ah = bf16(relu(Ch @ W2a + b2a)) = h_act   [1-term]
    weightT_kernel<<<dim3(HID / 32, HID / 32), dim3(32, 32)>>>(W2a, Wh, HID, HID);
    gemm_bf16s_mma_kernel<1024, true, 2, 1><<<gridGemm, 256, GEMM_SMEM1>>>(
        Ch, Wh, nullptr, b2a, nullptr, (__nv_bfloat162*)Ah, N_NODES, HID, HID);

    // ---- Fused classifier: out = h_act @ Wcomb + bcomb   [2-term] ----
    gemm_bf16s_mma_kernel<1024, false, 0, 2><<<gridFC, 256, GEMM_SMEM2>>>(
        Ah, WcTh, WcTl, bfcPad, out, nullptr, N_NODES, N_CLS, N_CLS);
    log_softmax64_kernel<<<(N_NODES * 32 + 255) / 256, 256>>>(out, N_NODES);
}

// round 16
// speedup vs baseline: 10.0357x; 1.0422x over previous
#include <cuda_runtime.h>
#include <cuda_bf16.h>
#include <math.h>
#include <stdint.h>

// Problem constants (fixed by the reference)
#define N_NODES  100000
#define N_EDGES  300000
#define D_IN     256
#define HID      1024
#define N_CLS    64

// ---------------------------------------------------------------------------
// Scratch (device globals: allocation-free)
// ---------------------------------------------------------------------------
__device__ __nv_bfloat16 g_Ah[(size_t)N_NODES * HID];       // act bf16 ping
__device__ __nv_bfloat16 g_Ch[(size_t)N_NODES * HID];       // act bf16 pong
__device__ __nv_bfloat16 g_Wh[(size_t)HID * HID];           // weight^T hi
__device__ __nv_bfloat16 g_WcTh[128 * HID];                 // composed cls W^T (rows 64+ zero)
__device__ float g_bfcPad[128];                             // composed cls bias
__device__ int   g_edges[2 * N_EDGES];
__device__ int   g_idx64;
// CSR scratch
__device__ int g_deg[N_NODES];
__device__ int g_incl[N_NODES];
__device__ int g_ptr[N_NODES];
__device__ int g_cursor[N_NODES];
__device__ int g_blockSums[128];
__device__ int g_csr_idx[N_EDGES];

// ---------------------------------------------------------------------------
// PTX helpers (all sm_80-era: valid under compute_103, no 'a' features)
// ---------------------------------------------------------------------------
__device__ __forceinline__ uint32_t s2u(const void* p) {
    uint32_t a;
    asm("{ .reg .u64 t; cvta.to.shared.u64 t, %1; cvt.u32.u64 %0, t; }"
        : "=r"(a) : "l"(p));
    return a;
}

__device__ __forceinline__ void cp_async16(uint32_t s, const void* g, unsigned sz) {
    asm volatile("cp.async.cg.shared.global [%0], [%1], 16, %2;"
                 :: "r"(s), "l"(g), "r"(sz));
}

__device__ __forceinline__ void ldsm4(uint32_t* r, uint32_t addr) {
    asm volatile("ldmatrix.sync.aligned.m8n8.x4.shared.b16 {%0,%1,%2,%3}, [%4];"
                 : "=r"(r[0]), "=r"(r[1]), "=r"(r[2]), "=r"(r[3]) : "r"(addr));
}

__device__ __forceinline__ void mma_bf16(float* d, const uint32_t* a,
                                         const uint32_t* b) {
    asm volatile(
        "mma.sync.aligned.m16n8k16.row.col.f32.bf16.bf16.f32 "
        "{%0,%1,%2,%3},{%4,%5,%6,%7},{%8,%9},{%0,%1,%2,%3};"
        : "+f"(d[0]), "+f"(d[1]), "+f"(d[2]), "+f"(d[3])
        : "r"(a[0]), "r"(a[1]), "r"(a[2]), "r"(a[3]), "r"(b[0]), "r"(b[1]));
}

// ---------------------------------------------------------------------------
// Edge-index dtype detection + normalization
// ---------------------------------------------------------------------------
__global__ void detect_idx_kernel(const unsigned int* __restrict__ ei) {
    unsigned v = ei[2 * threadIdx.x + 1];
    int any = __syncthreads_or(v != 0u);
    if (threadIdx.x == 0) g_idx64 = any ? 0 : 1;
}

__global__ void convert_idx_kernel(const unsigned int* __restrict__ ei) {
    int i = blockIdx.x * blockDim.x + threadIdx.x;
    if (i < 2 * N_EDGES) g_edges[i] = g_idx64 ? (int)ei[2 * i] : (int)ei[i];
}

// ---------------------------------------------------------------------------
// CSR build: degree count -> block scan -> ptr -> atomic-slot fill
// ---------------------------------------------------------------------------
__global__ void zero_csr_kernel() {
    int i = blockIdx.x * blockDim.x + threadIdx.x;
    if (i < N_NODES) { g_deg[i] = 0; g_cursor[i] = 0; }
}

__global__ void count_deg_kernel() {
    int e = blockIdx.x * blockDim.x + threadIdx.x;
    if (e < N_EDGES) atomicAdd(&g_deg[g_edges[N_EDGES + e]], 1);
}

__global__ void scan_block_kernel() {
    __shared__ int s[1024];
    int g = blockIdx.x * 1024 + threadIdx.x;
    int v = (g < N_NODES) ? g_deg[g] : 0;
    s[threadIdx.x] = v;
    __syncthreads();
#pragma unroll
    for (int off = 1; off < 1024; off <<= 1) {
        int t = (threadIdx.x >= off) ? s[threadIdx.x - off] : 0;
        __syncthreads();
        s[threadIdx.x] += t;
        __syncthreads();
    }
    if (g < N_NODES) g_incl[g] = s[threadIdx.x];
    if (threadIdx.x == 1023) g_blockSums[blockIdx.x] = s[1023];
}

__global__ void scan_sums_kernel(int nb) {
    if (threadIdx.x == 0) {
        int run = 0;
        for (int i = 0; i < nb; i++) { int t = g_blockSums[i]; g_blockSums[i] = run; run += t; }
    }
}

__global__ void finalize_ptr_kernel() {
    int g = blockIdx.x * blockDim.x + threadIdx.x;
    if (g < N_NODES) g_ptr[g] = g_incl[g] - g_deg[g] + g_blockSums[g >> 10];
}

__global__ void fill_csr_kernel() {
    int e = blockIdx.x * blockDim.x + threadIdx.x;
    if (e < N_EDGES) {
        int s = g_edges[e];
        int d = g_edges[N_EDGES + e];
        int slot = atomicAdd(&g_cursor[d], 1);
        g_csr_idx[g_ptr[d] + slot] = s;
    }
}

// ---------------------------------------------------------------------------
// Gather aggregation, layer 1: O[i] = bf16(x[i] + sum_j x[j]), D=256 fp32 in
// SMEM-staged indices + 2-way unrolled row loads (MLP >= 2).
// ---------------------------------------------------------------------------
__global__ void __launch_bounds__(128)
gather_x_kernel(const float2* __restrict__ X, __nv_bfloat162* __restrict__ O) {
    __shared__ int sidx[64];
    int node = blockIdx.x;
    int t = threadIdx.x;
    float2 a = X[(size_t)node * 128 + t];
    int st = g_ptr[node];
    int de = g_deg[node];
    for (int base = 0; base < de; base += 64) {
        int cnt = min(64, de - base);
        if (t < cnt) sidx[t] = g_csr_idx[st + base + t];
        __syncthreads();
        int q = 0;
        if (cnt & 1) {
            float2 v = X[(size_t)sidx[0] * 128 + t];
            a.x += v.x; a.y += v.y;
            q = 1;
        }
        for (; q < cnt; q += 2) {
            float2 v0 = X[(size_t)sidx[q] * 128 + t];
            float2 v1 = X[(size_t)sidx[q + 1] * 128 + t];
            a.x += v0.x; a.y += v0.y;
            a.x += v1.x; a.y += v1.y;
        }
        __syncthreads();
    }
    O[(size_t)node * 128 + t] = __nv_bfloat162(__float2bfloat16(a.x),
                                               __float2bfloat16(a.y));
}

// ---------------------------------------------------------------------------
// Gather aggregation, layer 2: O[i] = bf16(H[i] + sum_j H[j]), D=1024 bf16 in
// SMEM-staged indices + 2-way unrolled row loads.
// ---------------------------------------------------------------------------
__device__ __forceinline__ void acc_u4(float* acc, uint4 v) {
    float2 p0 = __bfloat1622float2(*(__nv_bfloat162*)&v.x);
    float2 p1 = __bfloat1622float2(*(__nv_bfloat162*)&v.y);
    float2 p2 = __bfloat1622float2(*(__nv_bfloat162*)&v.z);
    float2 p3 = __bfloat1622float2(*(__nv_bfloat162*)&v.w);
    acc[0] += p0.x; acc[1] += p0.y; acc[2] += p1.x; acc[3] += p1.y;
    acc[4] += p2.x; acc[5] += p2.y; acc[6] += p3.x; acc[7] += p3.y;
}

__global__ void __launch_bounds__(128)
gather_h_kernel(const uint4* __restrict__ H, uint4* __restrict__ O) {
    __shared__ int sidx[64];
    int node = blockIdx.x;
    int t = threadIdx.x;
    float acc[8];
    {
        uint4 sv = H[(size_t)node * 128 + t];
        float2 p0 = __bfloat1622float2(*(__nv_bfloat162*)&sv.x);
        float2 p1 = __bfloat1622float2(*(__nv_bfloat162*)&sv.y);
        float2 p2 = __bfloat1622float2(*(__nv_bfloat162*)&sv.z);
        float2 p3 = __bfloat1622float2(*(__nv_bfloat162*)&sv.w);
        acc[0] = p0.x; acc[1] = p0.y; acc[2] = p1.x; acc[3] = p1.y;
        acc[4] = p2.x; acc[5] = p2.y; acc[6] = p3.x; acc[7] = p3.y;
    }
    int st = g_ptr[node];
    int de = g_deg[node];
    for (int base = 0; base < de; base += 64) {
        int cnt = min(64, de - base);
        if (t < cnt) sidx[t] = g_csr_idx[st + base + t];
        __syncthreads();
        int q = 0;
        if (cnt & 1) {
            uint4 v = H[(size_t)sidx[0] * 128 + t];
            acc_u4(acc, v);
            q = 1;
        }
        for (; q < cnt; q += 2) {
            uint4 v0 = H[(size_t)sidx[q] * 128 + t];
            uint4 v1 = H[(size_t)sidx[q + 1] * 128 + t];
            acc_u4(acc, v0);
            acc_u4(acc, v1);
        }
        __syncthreads();
    }
    uint4 o;
    *(__nv_bfloat162*)&o.x = __nv_bfloat162(__float2bfloat16(acc[0]), __float2bfloat16(acc[1]));
    *(__nv_bfloat162*)&o.y = __nv_bfloat162(__float2bfloat16(acc[2]), __float2bfloat16(acc[3]));
    *(__nv_bfloat162*)&o.z = __nv_bfloat162(__float2bfloat16(acc[4]), __float2bfloat16(acc[5]));
    *(__nv_bfloat162*)&o.w = __nv_bfloat162(__float2bfloat16(acc[6]), __float2bfloat16(acc[7]));
    O[(size_t)node * 128 + t] = o;
}

// ---------------------------------------------------------------------------
// Coalesced weight transpose: W[Kd,Nd] fp32 -> Wt[Nd,Kd] bf16 (32x32 SMEM tile)
// ---------------------------------------------------------------------------
__global__ void __launch_bounds__(1024)
weightT_kernel(const float* __restrict__ W, __nv_bfloat16* __restrict__ Th,
               int Kd, int Nd) {
    __shared__ float tile[32][33];
    int n = blockIdx.x * 32 + threadIdx.x;
    int k = blockIdx.y * 32 + threadIdx.y;
    tile[threadIdx.y][threadIdx.x] = W[(size_t)k * Nd + n];
    __syncthreads();
    int ko = blockIdx.y * 32 + threadIdx.x;
    int no = blockIdx.x * 32 + threadIdx.y;
    Th[(size_t)no * Kd + ko] = __float2bfloat16(tile[threadIdx.x][threadIdx.y]);
}

// ---------------------------------------------------------------------------
// Classifier composition: Wcomb = W2b @ Wfc (fp32), written transposed bf16
// ---------------------------------------------------------------------------
__global__ void __launch_bounds__(256)
compose_cls_kernel(const float* __restrict__ W2b, const float* __restrict__ Wfc,
                   __nv_bfloat16* __restrict__ Th) {
    int j = threadIdx.x;                       // 0..63
    int k = blockIdx.x * 4 + threadIdx.y;      // 0..1023
    const float* wrow = W2b + (size_t)k * HID;
    float acc = 0.0f;
#pragma unroll 4
    for (int n = 0; n < HID; ++n)
        acc = fmaf(wrow[n], Wfc[(size_t)n * N_CLS + j], acc);
    Th[(size_t)j * HID + k] = __float2bfloat16(acc);
}

__global__ void zero_pad_cls_kernel(__nv_bfloat16* __restrict__ Th) {
    int i = blockIdx.x * 256 + threadIdx.x;    // 64*1024 pad elements
    if (i < 64 * HID) Th[64 * HID + i] = __float2bfloat16(0.0f);
}

__global__ void compose_bias_kernel(const float* __restrict__ b2b,
                                    const float* __restrict__ Wfc,
                                    const float* __restrict__ bfc) {
    int j = threadIdx.x;                       // 0..127
    float acc = 0.0f;
    if (j < N_CLS) {
#pragma unroll 4
        for (int n = 0; n < HID; ++n)
            acc = fmaf(b2b[n], Wfc[(size_t)n * N_CLS + j], acc);
        acc += bfc[j];
    }
    g_bfcPad[j] = acc;
}

// ---------------------------------------------------------------------------
// Pure-bf16 mma.sync GEMM:  C[M, ncols] = act(A[M,K] @ W[K,ncols] + bias)
// BM=128, BN=128, BK=64. 256 threads = 2x4 warps (64x32 per warp).
// 3-stage cp.async pipeline (32KB/stage -> 2 CTAs/SM); SW128-swizzled SMEM.
// OUT: 0 = fp32 to C (stride ostride, col guard); 2 = bf16 hi.
// ---------------------------------------------------------------------------
static constexpr uint32_t STAGE_SZ = 32768u;
static constexpr uint32_t OFF_BH   = 16384u;

template <int K>
__device__ __forceinline__ void load_stage(uint32_t tbase, int stage,
    const __nv_bfloat16* __restrict__ Ah, const __nv_bfloat16* __restrict__ Bh,
    int chunk, int rowBase, int colBase, int M) {
    const int tid = threadIdx.x;
    const uint32_t sBase = tbase + (uint32_t)stage * STAGE_SZ;
    const long kOff = (long)chunk * 64;
#pragma unroll
    for (int i = 0; i < 4; ++i) {
        int t = i * 256 + tid;            // 0..1023 16B chunks per 16KB tile
        int r = t >> 3;
        int cc = t & 7;
        uint32_t sw = (uint32_t)(r * 128 + ((cc ^ (r & 7)) << 4));
        int gr = rowBase + r;
        unsigned sz = (gr < M) ? 16u : 0u;
        int ga = gr < M ? gr : (M - 1);
        size_t aoff = ((size_t)ga * K + kOff + cc * 8) * 2;  // bytes
        cp_async16(sBase + sw, (const char*)Ah + aoff, sz);
        int gn = colBase + r;
        size_t boff = ((size_t)gn * K + kOff + cc * 8) * 2;
        cp_async16(sBase + OFF_BH + sw, (const char*)Bh + boff, 16u);
    }
}

struct Frags {
    uint32_t ah[4][4];
    uint32_t bh[2][4];
};

__device__ __forceinline__ void load_frags(uint32_t st, int k,
                                           const int* arow, const int* brow,
                                           int a_ck, int b_ck, Frags& f) {
#pragma unroll
    for (int fm = 0; fm < 4; ++fm) {
        int row = arow[fm];
        int ck = k * 2 + a_ck;
        uint32_t off = (uint32_t)(row * 128 + ((ck ^ (row & 7)) << 4));
        ldsm4(f.ah[fm], st + off);
    }
#pragma unroll
    for (int f2 = 0; f2 < 2; ++f2) {
        int row = brow[f2];
        int ck = k * 2 + b_ck;
        uint32_t off = (uint32_t)(row * 128 + ((ck ^ (row & 7)) << 4));
        ldsm4(f.bh[f2], st + OFF_BH + off);
    }
}

__device__ __forceinline__ void mma_frags(const Frags& f, float acc[4][4][4]) {
#pragma unroll
    for (int fm = 0; fm < 4; ++fm)
#pragma unroll
        for (int fn = 0; fn < 4; ++fn)
            mma_bf16(acc[fm][fn], f.ah[fm], &f.bh[fn >> 1][(fn & 1) * 2]);
}

template <int K, bool RELU, int OUT>
__global__ void __launch_bounds__(256, 2)
gemm_bf16_mma_kernel(const __nv_bfloat16* __restrict__ Ah,
                     const __nv_bfloat16* __restrict__ Bh,
                     const float* __restrict__ bias,
                     float* __restrict__ C,
                     __nv_bfloat162* __restrict__ Oh,
                     int M, int ostride, int ncols) {
    constexpr int NC = K / 64;
    extern __shared__ char smem[];
    const uint32_t tile_base = (s2u(smem) + 1023u) & ~1023u;

    const int tid = threadIdx.x;
    const int wid = tid >> 5;
    const int lane = tid & 31;
    const int wm = wid >> 2;          // 0..1
    const int wn = wid & 3;           // 0..3
    const int rowBase = blockIdx.y * 128;
    const int colBase = blockIdx.x * 128;

    const int midx = lane >> 3;
    const int l7 = lane & 7;
    const int a_ck = (midx >> 1);
    const int b_ck = (midx & 1);
    int arow[4], brow[2];
#pragma unroll
    for (int fm = 0; fm < 4; ++fm)
        arow[fm] = wm * 64 + fm * 16 + ((midx & 1) << 3) + l7;
#pragma unroll
    for (int f2 = 0; f2 < 2; ++f2)
        brow[f2] = wn * 32 + f2 * 16 + ((midx >> 1) << 3) + l7;

    float acc[4][4][4];
#pragma unroll
    for (int i = 0; i < 4; i++)
#pragma unroll
        for (int j = 0; j < 4; j++)
#pragma unroll
            for (int q = 0; q < 4; q++) acc[i][j][q] = 0.0f;

    // Prologue: prefetch chunks 0, 1
    load_stage<K>(tile_base, 0, Ah, Bh, 0, rowBase, colBase, M);
    asm volatile("cp.async.commit_group;" ::: "memory");
    load_stage<K>(tile_base, 1, Ah, Bh, 1, rowBase, colBase, M);
    asm volatile("cp.async.commit_group;" ::: "memory");

    Frags fr;
    for (int c = 0; c < NC; ++c) {
        if (c + 1 < NC) asm volatile("cp.async.wait_group 1;" ::: "memory");
        else            asm volatile("cp.async.wait_group 0;" ::: "memory");
        __syncthreads();
        const uint32_t st = tile_base + (uint32_t)(c % 3) * STAGE_SZ;
        if (c + 2 < NC) {
            load_stage<K>(tile_base, (c + 2) % 3, Ah, Bh, c + 2,
                          rowBase, colBase, M);
            asm volatile("cp.async.commit_group;" ::: "memory");
        }
#pragma unroll
        for (int k = 0; k < 4; ++k) {
            load_frags(st, k, arow, brow, a_ck, b_ck, fr);
            mma_frags(fr, acc);
        }
    }

    // Epilogue: bias (+relu); fp32 strided (col guard) or bf16 hi
    const int rowb = rowBase + wm * 64 + (lane >> 2);
    const int colb = colBase + wn * 32;
#pragma unroll
    for (int fm = 0; fm < 4; ++fm) {
        int r0 = rowb + fm * 16;
        int r1 = r0 + 8;
#pragma unroll
        for (int fn = 0; fn < 4; ++fn) {
            int col = colb + fn * 8 + (lane & 3) * 2;
            float2 bp = *reinterpret_cast<const float2*>(&bias[col]);
            float v0 = acc[fm][fn][0] + bp.x;
            float v1 = acc[fm][fn][1] + bp.y;
            float v2 = acc[fm][fn][2] + bp.x;
            float v3 = acc[fm][fn][3] + bp.y;
            if (RELU) {
                v0 = fmaxf(v0, 0.f); v1 = fmaxf(v1, 0.f);
                v2 = fmaxf(v2, 0.f); v3 = fmaxf(v3, 0.f);
            }
            if (OUT == 0) {
                if (col < ncols) {
                    if (r0 < M)
                        *reinterpret_cast<float2*>(&C[(size_t)r0 * ostride + col]) =
                            make_float2(v0, v1);
                    if (r1 < M)
                        *reinterpret_cast<float2*>(&C[(size_t)r1 * ostride + col]) =
                            make_float2(v2, v3);
                }
            } else {
                if (r0 < M) {
                    size_t h = ((size_t)r0 * ostride + col) >> 1;
                    Oh[h] = __nv_bfloat162(__float2bfloat16(v0),
                                           __float2bfloat16(v1));
                }
                if (r1 < M) {
                    size_t h = ((size_t)r1 * ostride + col) >> 1;
                    Oh[h] = __nv_bfloat162(__float2bfloat16(v2),
                                           __float2bfloat16(v3));
                }
            }
        }
    }
}

// ---------------------------------------------------------------------------
// In-place log_softmax over 64 classes, one warp per row
// ---------------------------------------------------------------------------
__global__ void log_softmax64_kernel(float* __restrict__ out, int M) {
    int warp = (blockIdx.x * blockDim.x + threadIdx.x) >> 5;
    int lane = threadIdx.x & 31;
    if (warp >= M) return;
    float* row = out + (size_t)warp * N_CLS;
    float a = row[lane];
    float b = row[lane + 32];
    float m = fmaxf(a, b);
#pragma unroll
    for (int o = 16; o > 0; o >>= 1)
        m = fmaxf(m, __shfl_xor_sync(0xFFFFFFFFu, m, o));
    float s = expf(a - m) + expf(b - m);
#pragma unroll
    for (int o = 16; o > 0; o >>= 1)
        s += __shfl_xor_sync(0xFFFFFFFFu, s, o);
    float lse = m + logf(s);
    row[lane]      = a - lse;
    row[lane + 32] = b - lse;
}

// ---------------------------------------------------------------------------
// Launch
// ---------------------------------------------------------------------------
extern "C" void kernel_launch(void* const* d_in, const int* in_sizes, int n_in,
                              void* d_out, int out_size) {
    const float*        x   = (const float*)d_in[0];
    const unsigned int* ei  = (const unsigned int*)d_in[1];
    const float* W1a = (const float*)d_in[2];
    const float* b1a = (const float*)d_in[3];
    const float* W1b = (const float*)d_in[4];
    const float* b1b = (const float*)d_in[5];
    const float* W2a = (const float*)d_in[6];
    const float* b2a = (const float*)d_in[7];
    const float* W2b = (const float*)d_in[8];
    const float* b2b = (const float*)d_in[9];
    const float* Wfc = (const float*)d_in[10];
    const float* bfc = (const float*)d_in[11];
    float* out = (float*)d_out;

    float *bfcPad;
    __nv_bfloat16 *Ah, *Ch, *Wh, *WcTh;
    cudaGetSymbolAddress((void**)&Ah, g_Ah);
    cudaGetSymbolAddress((void**)&Ch, g_Ch);
    cudaGetSymbolAddress((void**)&Wh, g_Wh);
    cudaGetSymbolAddress((void**)&WcTh, g_WcTh);
    cudaGetSymbolAddress((void**)&bfcPad, g_bfcPad);

    // 3 x 32KB stages + align slack -> 2 CTAs/SM
    const int GEMM_SMEM = 3 * 32768 + 1024;   // 99328 B
    cudaFuncSetAttribute(gemm_bf16_mma_kernel<256, true, 2>,
                         cudaFuncAttributeMaxDynamicSharedMemorySize, GEMM_SMEM);
    cudaFuncSetAttribute(gemm_bf16_mma_kernel<1024, true, 2>,
                         cudaFuncAttributeMaxDynamicSharedMemorySize, GEMM_SMEM);
    cudaFuncSetAttribute(gemm_bf16_mma_kernel<1024, false, 0>,
                         cudaFuncAttributeMaxDynamicSharedMemorySize, GEMM_SMEM);

    // ---- Edge normalization + CSR build ----
    detect_idx_kernel<<<1, 256>>>(ei);
    convert_idx_kernel<<<(2 * N_EDGES + 255) / 256, 256>>>(ei);
    zero_csr_kernel<<<(N_NODES + 255) / 256, 256>>>();
    count_deg_kernel<<<(N_EDGES + 255) / 256, 256>>>();
    const int NB = (N_NODES + 1023) / 1024;   // 98
    scan_block_kernel<<<NB, 1024>>>();
    scan_sums_kernel<<<1, 32>>>(NB);
    finalize_ptr_kernel<<<(N_NODES + 255) / 256, 256>>>();
    fill_csr_kernel<<<(N_EDGES + 255) / 256, 256>>>();

    // ---- Classifier composition (independent of activations) ----
    compose_cls_kernel<<<HID / 4, dim3(64, 4)>>>(W2b, Wfc, WcTh);
    zero_pad_cls_kernel<<<(64 * HID + 255) / 256, 256>>>(WcTh);
    compose_bias_kernel<<<1, 128>>>(b2b, Wfc, bfc);

    dim3 gridGemm(HID / 128, (N_NODES + 127) / 128);   // (8, 782)
    dim3 gridFC(1, (N_NODES + 127) / 128);

    // ---- Layer 1: Ah = bf16(x + gather(x)) ----
    gather_x_kernel<<<N_NODES, 128>>>((const float2*)x, (__nv_bfloat162*)Ah);
    // GEMM1a: Ch = bf16(relu(Ah @ W1a + b1a))
    weightT_kernel<<<dim3(HID / 32, D_IN / 32), dim3(32, 32)>>>(W1a, Wh, D_IN, HID);
    gemm_bf16_mma_kernel<256, true, 2><<<gridGemm, 256, GEMM_SMEM>>>(
        Ah, Wh, b1a, nullptr, (__nv_bfloat162*)Ch, N_NODES, HID, HID);
    // GEMM1b: Ah = bf16(relu(Ch @ W1b + b1b)) = h1
    weightT_kernel<<<dim3(HID / 32, HID / 32), dim3(32, 32)>>>(W1b, Wh, HID, HID);
    gemm_bf16_mma_kernel<1024, true, 2><<<gridGemm, 256, GEMM_SMEM>>>(
        Ch, Wh, b1b, nullptr, (__nv_bfloat162*)Ah, N_NODES, HID, HID);

    // ---- Layer 2: Ch = bf16(h1 + gather(h1)) ----
    gather_h_kernel<<<N_NODES, 128>>>((const uint4*)Ah, (uint4*)Ch);
    // GEMM2a: Ah = bf16(relu(Ch @ W2a + b2a)) = h_act
    weightT_kernel<<<dim3(HID / 32, HID / 32), dim3(32, 32)>>>(W2a, Wh, HID, HID);
    gemm_bf16_mma_kernel<1024, true, 2><<<gridGemm, 256, GEMM_SMEM>>>(
        Ch, Wh, b2a, nullptr, (__nv_bfloat162*)Ah, N_NODES, HID, HID);

    // ---- Fused classifier: out = h_act @ Wcomb + bcomb ----
    gemm_bf16_mma_kernel<1024, false, 0><<<gridFC, 256, GEMM_SMEM>>>(
        Ah, WcTh, bfcPad, out, nullptr, N_NODES, N_CLS, N_CLS);
    log_softmax64_kernel<<<(N_NODES * 32 + 255) / 256, 256>>>(out, N_NODES);
}